// round 7
// baseline (speedup 1.0000x reference)
#include <cuda_runtime.h>
#include <cuda_bf16.h>
#include <math.h>
#include <stdint.h>

#define L 2048
#define C 256
#define NB 4
#define H 8
#define D 32
#define SD 16.0f

// ---------------- scratch (device globals; no allocation allowed) ----------------
__device__ float g_h [L*C];
__device__ float g_q [L*C];
__device__ float g_k [L*C];
__device__ float g_v [L*C];
__device__ float g_ao[L*C];
__device__ float g_mid[L*4*C];
__device__ __nv_bfloat16 g_bias[(size_t)NB*H*L*L];   // 256 MB
__device__ float g_ss1[NB][2*C];
__device__ float g_ss2[NB][2*C];
__device__ float g_scal[4];   // c_skip, c_out, c_in
// fused-LN precomputes
__device__ float g_G1[NB][C], g_B1[NB][C], g_G2[NB][C], g_B2[NB][C];
__device__ float g_wqkv[(size_t)NB*3*C*C];   // G1-scaled qkv weights
__device__ float g_wf1 [(size_t)NB*4*C*C];   // G2-scaled ffn1 weights
__device__ float g_gwA [NB][3*C + 4*C];      // GW vectors (qkv | ffn1)
__device__ float g_b2A [NB][3*C + 4*C];      // b2 vectors (qkv | ffn1, ffn_b1 folded)
__device__ float g_rs[L], g_m2[L];           // per-row rstd, -mu*rstd

__device__ __forceinline__ float gelu_exact(float x) {
    return 0.5f * x * (1.0f + erff(x * 0.70710678118654752f));
}

__device__ __forceinline__ void mma_tf32(float c[4],
    uint32_t a0, uint32_t a1, uint32_t a2, uint32_t a3,
    uint32_t b0, uint32_t b1)
{
    asm volatile(
        "mma.sync.aligned.m16n8k8.row.col.f32.tf32.tf32.f32 "
        "{%0,%1,%2,%3}, {%4,%5,%6,%7}, {%8,%9}, {%0,%1,%2,%3};"
        : "+f"(c[0]), "+f"(c[1]), "+f"(c[2]), "+f"(c[3])
        : "r"(a0), "r"(a1), "r"(a2), "r"(a3), "r"(b0), "r"(b1));
}

__device__ __forceinline__ void mma_bf16(float c[4],
    uint32_t a0, uint32_t a1, uint32_t a2, uint32_t a3,
    uint32_t b0, uint32_t b1)
{
    asm volatile(
        "mma.sync.aligned.m16n8k16.row.col.f32.bf16.bf16.f32 "
        "{%0,%1,%2,%3}, {%4,%5,%6,%7}, {%8,%9}, {%0,%1,%2,%3};"
        : "+f"(c[0]), "+f"(c[1]), "+f"(c[2]), "+f"(c[3])
        : "r"(a0), "r"(a1), "r"(a2), "r"(a3), "r"(b0), "r"(b1));
}

__device__ __forceinline__ void cp16(float* smem_dst, const float* gsrc) {
    uint32_t s = (uint32_t)__cvta_generic_to_shared(smem_dst);
    asm volatile("cp.async.cg.shared.global [%0], [%1], 16;" :: "r"(s), "l"(gsrc));
}
#define CP_COMMIT() asm volatile("cp.async.commit_group;")
#define CP_WAIT(n)  asm volatile("cp.async.wait_group %0;" :: "n"(n))

// ---------------- K0: time embedding, time MLP, adaLN cond projections ----------------
__global__ void __launch_bounds__(256) k_prep(
    const float* __restrict__ sigma,
    const float* __restrict__ tW1, const float* __restrict__ tb1,
    const float* __restrict__ tW2, const float* __restrict__ tb2,
    const float* __restrict__ a1pW, const float* __restrict__ a1pb,
    const float* __restrict__ a2pW, const float* __restrict__ a2pb)
{
    __shared__ float temb[C];
    __shared__ float hid[4*C];
    __shared__ float tcs[C];
    const int t = threadIdx.x;
    const float sg = sigma[0];
    if (t == 0) {
        float s2 = sg*sg + SD*SD;
        g_scal[0] = SD*SD / s2;
        g_scal[1] = sg*SD*rsqrtf(s2);
        g_scal[2] = rsqrtf(s2);
    }
    const float c_noise = 0.25f * logf(sg + 1e-8f);
    if (t < 128) {
        float fr = expf(-logf(10000.0f) * (float)t / 128.0f);
        float a = c_noise * fr;
        temb[t]       = cosf(a);
        temb[t + 128] = sinf(a);
    }
    __syncthreads();
    for (int r = t; r < 4*C; r += 256) {
        float acc = tb1[r];
        const float* w = tW1 + (size_t)r * C;
        for (int k2 = 0; k2 < C; k2++) acc += temb[k2] * w[k2];
        hid[r] = gelu_exact(acc);
    }
    __syncthreads();
    for (int r = t; r < C; r += 256) {
        float acc = tb2[r];
        const float* w = tW2 + (size_t)r * 4*C;
        for (int k2 = 0; k2 < 4*C; k2++) acc += hid[k2] * w[k2];
        tcs[r] = acc;
    }
    __syncthreads();
    for (int idx = t; idx < NB*2*C; idx += 256) {
        int b = idx / (2*C), r = idx % (2*C);
        float acc1 = a1pb[b*2*C + r];
        const float* w1 = a1pW + ((size_t)b*2*C + r) * C;
        float acc2 = a2pb[b*2*C + r];
        const float* w2 = a2pW + ((size_t)b*2*C + r) * C;
        for (int k2 = 0; k2 < C; k2++) { acc1 += tcs[k2]*w1[k2]; acc2 += tcs[k2]*w2[k2]; }
        g_ss1[b][r] = acc1;
        g_ss2[b][r] = acc2;
    }
}

// ---------------- fold1: G = g*(1+scale), Bc = b*(1+scale)+shift ----------------
__global__ void __launch_bounds__(256) k_fold1(
    const float* __restrict__ a1g, const float* __restrict__ a1b,
    const float* __restrict__ a2g, const float* __restrict__ a2b)
{
    int b = blockIdx.x, c = threadIdx.x;
    float s1 = 1.0f + g_ss1[b][c];
    g_G1[b][c] = a1g[b*C + c] * s1;
    g_B1[b][c] = a1b[b*C + c] * s1 + g_ss1[b][C + c];
    float s2 = 1.0f + g_ss2[b][c];
    g_G2[b][c] = a2g[b*C + c] * s2;
    g_B2[b][c] = a2b[b*C + c] * s2 + g_ss2[b][C + c];
}

// ---------------- foldW: W' = G (.) W, GW = sum G.W, b2 = sum Bc.W ----------------
__global__ void __launch_bounds__(256) k_foldW(
    const float* __restrict__ qW, const float* __restrict__ kW,
    const float* __restrict__ vW, const float* __restrict__ f1W,
    const float* __restrict__ f1b)
{
    const int lane = threadIdx.x & 31, warp = threadIdx.x >> 5;
    int gidx = blockIdx.x * 8 + warp;           // 0 .. NB*1792-1
    int b = gidx / 1792, n = gidx % 1792;
    const float *src, *G, *Bc;
    float* dst;
    float extra = 0.f;
    if (n < 768) {
        int w = n >> 8, nn = n & 255;
        src = (w == 0 ? qW : w == 1 ? kW : vW) + ((size_t)b*C + nn)*C;
        dst = g_wqkv + ((size_t)b*768 + n)*C;
        G = g_G1[b]; Bc = g_B1[b];
    } else {
        int nn = n - 768;
        src = f1W + ((size_t)b*4*C + nn)*C;
        dst = g_wf1 + ((size_t)b*1024 + nn)*C;
        G = g_G2[b]; Bc = g_B2[b];
        extra = f1b[b*4*C + nn];
    }
    float gw = 0.f, b2 = 0.f;
    for (int c = lane; c < C; c += 32) {
        float w = src[c];
        float wg = w * G[c];
        dst[c] = wg;
        gw += wg;
        b2 += w * Bc[c];
    }
    #pragma unroll
    for (int off = 16; off; off >>= 1) {
        gw += __shfl_xor_sync(0xffffffffu, gw, off);
        b2 += __shfl_xor_sync(0xffffffffu, b2, off);
    }
    if (lane == 0) { g_gwA[b][n] = gw; g_b2A[b][n] = b2 + extra; }
}

// ---------------- row stats: rs = rstd, m2 = -mu*rstd ----------------
__global__ void __launch_bounds__(256) k_rowstat(const float* __restrict__ X)
{
    const int lane = threadIdx.x & 31, warp = threadIdx.x >> 5;
    const int row = blockIdx.x * 8 + warp;
    const float* xr = X + (size_t)row * C;
    float s = 0.f, sq = 0.f;
    #pragma unroll
    for (int i = 0; i < 8; i++) {
        float v = xr[lane + 32*i];
        s += v; sq += v*v;
    }
    #pragma unroll
    for (int off = 16; off; off >>= 1) {
        s  += __shfl_xor_sync(0xffffffffu, s,  off);
        sq += __shfl_xor_sync(0xffffffffu, sq, off);
    }
    if (lane == 0) {
        float mu = s * (1.0f/256.0f);
        float var = sq * (1.0f/256.0f) - mu*mu;
        float rs = rsqrtf(var + 1e-5f);
        g_rs[row] = rs;
        g_m2[row] = -mu * rs;
    }
}

// ---------------- pair bias via tf32 mma ----------------
__global__ void __launch_bounds__(256) k_bias_tc(const float* __restrict__ pair,
                                                 const float* __restrict__ pW)
{
    __shared__ float As[128][68];
    __shared__ float Ws[32][68];
    const int tid = threadIdx.x, lane = tid & 31, warp = tid >> 5;
    const int lr = lane >> 2, lc = lane & 3;
    const size_t row0 = (size_t)blockIdx.x * 128;

    #pragma unroll
    for (int it = 0; it < 8; it++) {
        int idx = tid + 256*it;
        int r = idx >> 4, q = idx & 15;
        *(float4*)&As[r][4*q] = *(const float4*)&pair[(row0 + r) * 64 + 4*q];
    }
    #pragma unroll
    for (int it = 0; it < 2; it++) {
        int idx = tid + 256*it;
        int r = idx >> 4, q = idx & 15;
        *(float4*)&Ws[r][4*q] = *(const float4*)&pW[r * 64 + 4*q];
    }
    __syncthreads();

    float c[4][4] = {};
    const int arow = 16*warp + lr;
    #pragma unroll
    for (int kk = 0; kk < 64; kk += 8) {
        uint32_t a0 = __float_as_uint(As[arow  ][kk+lc]);
        uint32_t a1 = __float_as_uint(As[arow+8][kk+lc]);
        uint32_t a2 = __float_as_uint(As[arow  ][kk+4+lc]);
        uint32_t a3 = __float_as_uint(As[arow+8][kk+4+lc]);
        #pragma unroll
        for (int nt = 0; nt < 4; nt++) {
            uint32_t b0 = __float_as_uint(Ws[8*nt+lr][kk+lc]);
            uint32_t b1 = __float_as_uint(Ws[8*nt+lr][kk+4+lc]);
            mma_tf32(c[nt], a0, a1, a2, a3, b0, b1);
        }
    }
    __syncthreads();

    __nv_bfloat16* stage = (__nv_bfloat16*)&As[0][0];
    const int SP = 132;
    #pragma unroll
    for (int nt = 0; nt < 4; nt++) {
        #pragma unroll
        for (int half = 0; half < 2; half++) {
            int rloc = 16*warp + lr + 8*half;
            int col = 8*nt + 2*lc;
            stage[(col  )*SP + rloc] = __float2bfloat16(c[nt][2*half+0]);
            stage[(col+1)*SP + rloc] = __float2bfloat16(c[nt][2*half+1]);
        }
    }
    __syncthreads();
    for (int idx = tid; idx < 32*64; idx += 256) {
        int o = idx >> 6, r2 = (idx & 63) * 2;
        __nv_bfloat162 v = *(const __nv_bfloat162*)&stage[o*SP + r2];
        *(__nv_bfloat162*)&g_bias[(size_t)o * (size_t)L * (size_t)L + row0 + r2] = v;
    }
}

// ---------------- tf32 GEMM, 128x128 tile, cp.async double-buffered ----------------
#define GSTAGE (128*36)
#define GEMM_SMEM (4*GSTAGE*4)

template<bool HAS_BIAS, bool DO_GELU, bool HAS_RES, bool LN_EPI, bool COORD>
__device__ __forceinline__ void gemm_body128(
    const float* __restrict__ A, const float* __restrict__ Bw,
    const float* __restrict__ bias, const float* __restrict__ Rsrc,
    const float* __restrict__ GW, const float* __restrict__ b2v,
    const float* __restrict__ xn, const float* __restrict__ cW,
    const float* __restrict__ cb,
    float* __restrict__ Cout, int M, int N, int K)
{
    extern __shared__ float sm[];
    float* AsB = sm;
    float* BsB = sm + 2*GSTAGE;
    const int tid = threadIdx.x, lane = tid & 31, warp = tid >> 5;
    const int wm = warp >> 1, wn = warp & 1;
    const int m0 = blockIdx.y * 128, n0 = blockIdx.x * 128;
    const int lr = lane >> 2, lc = lane & 3;
    const int pr = tid >> 3, pq = tid & 7;

    float c[2][8][4];
    #pragma unroll
    for (int mt = 0; mt < 2; mt++)
        #pragma unroll
        for (int nt = 0; nt < 8; nt++)
            #pragma unroll
            for (int r = 0; r < 4; r++) c[mt][nt][r] = 0.f;

    const int NK = K >> 5;
    {
        float* as = AsB; float* bs = BsB;
        #pragma unroll
        for (int it = 0; it < 4; it++) {
            int r = pr + 32*it;
            cp16(&as[r*36 + 4*pq], &A [(size_t)(m0 + r)*K + 4*pq]);
            cp16(&bs[r*36 + 4*pq], &Bw[(size_t)(n0 + r)*K + 4*pq]);
        }
        CP_COMMIT();
    }

    for (int ks = 0; ks < NK; ks++) {
        if (ks + 1 < NK) {
            float* as = AsB + ((ks+1)&1)*GSTAGE;
            float* bs = BsB + ((ks+1)&1)*GSTAGE;
            int k0 = (ks+1) << 5;
            #pragma unroll
            for (int it = 0; it < 4; it++) {
                int r = pr + 32*it;
                cp16(&as[r*36 + 4*pq], &A [(size_t)(m0 + r)*K + k0 + 4*pq]);
                cp16(&bs[r*36 + 4*pq], &Bw[(size_t)(n0 + r)*K + k0 + 4*pq]);
            }
            CP_COMMIT();
            CP_WAIT(1);
        } else {
            CP_WAIT(0);
        }
        __syncthreads();
        const float* as = AsB + (ks&1)*GSTAGE;
        const float* bs = BsB + (ks&1)*GSTAGE;
        #pragma unroll
        for (int kk = 0; kk < 32; kk += 8) {
            uint32_t a[2][4], b[8][2];
            #pragma unroll
            for (int mt = 0; mt < 2; mt++) {
                int row = 32*wm + 16*mt + lr;
                a[mt][0] = __float_as_uint(as[(row  )*36 + kk+lc]);
                a[mt][1] = __float_as_uint(as[(row+8)*36 + kk+lc]);
                a[mt][2] = __float_as_uint(as[(row  )*36 + kk+4+lc]);
                a[mt][3] = __float_as_uint(as[(row+8)*36 + kk+4+lc]);
            }
            #pragma unroll
            for (int nt = 0; nt < 8; nt++) {
                int col = 64*wn + 8*nt + lr;
                b[nt][0] = __float_as_uint(bs[col*36 + kk+lc]);
                b[nt][1] = __float_as_uint(bs[col*36 + kk+4+lc]);
            }
            #pragma unroll
            for (int mt = 0; mt < 2; mt++)
                #pragma unroll
                for (int nt = 0; nt < 8; nt++)
                    mma_tf32(c[mt][nt], a[mt][0], a[mt][1], a[mt][2], a[mt][3],
                             b[nt][0], b[nt][1]);
        }
        __syncthreads();
    }

    #pragma unroll
    for (int mt = 0; mt < 2; mt++) {
        #pragma unroll
        for (int half = 0; half < 2; half++) {
            int row = m0 + 32*wm + 16*mt + lr + 8*half;
            float rs = 0.f, m2 = 0.f, cx0 = 0.f, cx1 = 0.f, cx2 = 0.f, cin = 0.f;
            if (LN_EPI) { rs = g_rs[row]; m2 = g_m2[row]; }
            if (COORD) {
                cin = g_scal[2];
                cx0 = xn[row*3+0]*cin; cx1 = xn[row*3+1]*cin; cx2 = xn[row*3+2]*cin;
            }
            #pragma unroll
            for (int nt = 0; nt < 8; nt++) {
                int col = n0 + 64*wn + 8*nt + 2*lc;
                float v0 = c[mt][nt][2*half+0];
                float v1 = c[mt][nt][2*half+1];
                if (LN_EPI) {
                    v0 = rs*v0 + m2*GW[col]   + b2v[col];
                    v1 = rs*v1 + m2*GW[col+1] + b2v[col+1];
                }
                if (HAS_BIAS) { v0 += bias[col]; v1 += bias[col+1]; }
                if (COORD) {
                    v0 += cb[col]   + cx0*cW[col*3+0]     + cx1*cW[col*3+1]     + cx2*cW[col*3+2];
                    v1 += cb[col+1] + cx0*cW[(col+1)*3+0] + cx1*cW[(col+1)*3+1] + cx2*cW[(col+1)*3+2];
                }
                if (DO_GELU)  { v0 = gelu_exact(v0); v1 = gelu_exact(v1); }
                if (HAS_RES)  { v0 += Rsrc[(size_t)row*N + col]; v1 += Rsrc[(size_t)row*N + col + 1]; }
                *(float2*)&Cout[(size_t)row*N + col] = make_float2(v0, v1);
            }
        }
    }
}

// plain GEMM (+bias)(+gelu)(+res)
template<bool HB, bool HG, bool HR>
__global__ void __launch_bounds__(256, 2) k_gemm_tc(
    const float* __restrict__ A, const float* __restrict__ Bw,
    const float* __restrict__ bias, const float* __restrict__ Rsrc,
    float* __restrict__ Cout, int M, int N, int K)
{
    gemm_body128<HB,HG,HR,false,false>(A, Bw, bias, Rsrc,
        nullptr, nullptr, nullptr, nullptr, nullptr, Cout, M, N, K);
}

// single-proj with coord fusion
__global__ void __launch_bounds__(256, 2) k_single_tc(
    const float* __restrict__ A, const float* __restrict__ Bw,
    const float* __restrict__ bias,
    const float* __restrict__ xn, const float* __restrict__ cW,
    const float* __restrict__ cb, float* __restrict__ Cout)
{
    gemm_body128<true,false,false,false,true>(A, Bw, bias, nullptr,
        nullptr, nullptr, xn, cW, cb, Cout, L, C, C);
}

// fused-LN qkv (z selects q/k/v)
__global__ void __launch_bounds__(256, 2) k_qkv_f(
    int b, float* __restrict__ q, float* __restrict__ k, float* __restrict__ v)
{
    int z = blockIdx.z;
    const float* Bw = g_wqkv + ((size_t)b*768 + z*256)*C;
    const float* GW = &g_gwA[b][z*256];
    const float* b2 = &g_b2A[b][z*256];
    float* Cout = (z == 0) ? q : (z == 1) ? k : v;
    gemm_body128<false,false,false,true,false>(g_h, Bw, nullptr, nullptr,
        GW, b2, nullptr, nullptr, nullptr, Cout, L, C, C);
}

// fused-LN ffn1 + gelu
__global__ void __launch_bounds__(256, 2) k_ffn1_f(int b, float* __restrict__ mid)
{
    const float* Bw = g_wf1 + (size_t)b*1024*C;
    const float* GW = &g_gwA[b][768];
    const float* b2 = &g_b2A[b][768];
    gemm_body128<false,true,false,true,false>(g_h, Bw, nullptr, nullptr,
        GW, b2, nullptr, nullptr, nullptr, mid, L, 4*C, C);
}

// ---------------- tensor-core flash attention (tf32 QK^T, bf16 PV) ----------------
#define ATTN_SMEM (18432 + 18432 + 8704 + 34816)
__global__ void __launch_bounds__(256) k_attn_tc(int blk)
{
    extern __shared__ char smc[];
    float* Qs = (float*)smc;
    float* Ks = (float*)(smc + 18432);
    __nv_bfloat16* Vt = (__nv_bfloat16*)(smc + 36864);
    __nv_bfloat16* Ps = (__nv_bfloat16*)(smc + 45568);

    const int h  = blockIdx.y;
    const int i0 = blockIdx.x * 128;
    const int tid = threadIdx.x, lane = tid & 31, warp = tid >> 5;
    const int lr = lane >> 2, lc = lane & 3;
    const float scale = 0.17677669529663687f;

    #pragma unroll
    for (int it = 0; it < 4; it++) {
        int idx = tid + 256*it;
        int r = idx >> 3, q = idx & 7;
        float4 v = *(const float4*)&g_q[(size_t)(i0 + r)*C + h*32 + 4*q];
        float* dst = &Qs[r*36 + 4*q];
        dst[0]=v.x*scale; dst[1]=v.y*scale; dst[2]=v.z*scale; dst[3]=v.w*scale;
    }

    float m_run[2] = {-1e30f, -1e30f};
    float l_run[2] = {0.f, 0.f};
    float o[4][4];
    #pragma unroll
    for (int nt = 0; nt < 4; nt++)
        #pragma unroll
        for (int r = 0; r < 4; r++) o[nt][r] = 0.f;

    const __nv_bfloat16* bias_w = g_bias + ((size_t)blk*H + h)*(size_t)L*L
                                         + (size_t)(i0 + 16*warp)*L;
    const int arow = 16*warp + lr;

    for (int j0 = 0; j0 < L; j0 += 128) {
        #pragma unroll
        for (int it = 0; it < 4; it++) {
            int idx = tid + 256*it;
            int r = idx >> 3, q = idx & 7;
            float4 kv = *(const float4*)&g_k[(size_t)(j0 + r)*C + h*32 + 4*q];
            *(float4*)&Ks[r*36 + 4*q] = kv;
            float4 vv = *(const float4*)&g_v[(size_t)(j0 + r)*C + h*32 + 4*q];
            Vt[(4*q+0)*136 + r] = __float2bfloat16(vv.x);
            Vt[(4*q+1)*136 + r] = __float2bfloat16(vv.y);
            Vt[(4*q+2)*136 + r] = __float2bfloat16(vv.z);
            Vt[(4*q+3)*136 + r] = __float2bfloat16(vv.w);
        }
        __syncthreads();

        float s[16][4];
        #pragma unroll
        for (int nt = 0; nt < 16; nt++)
            #pragma unroll
            for (int r = 0; r < 4; r++) s[nt][r] = 0.f;
        #pragma unroll
        for (int kk = 0; kk < 32; kk += 8) {
            uint32_t a0 = __float_as_uint(Qs[(arow  )*36 + kk+lc]);
            uint32_t a1 = __float_as_uint(Qs[(arow+8)*36 + kk+lc]);
            uint32_t a2 = __float_as_uint(Qs[(arow  )*36 + kk+4+lc]);
            uint32_t a3 = __float_as_uint(Qs[(arow+8)*36 + kk+4+lc]);
            #pragma unroll
            for (int nt = 0; nt < 16; nt++) {
                uint32_t b0 = __float_as_uint(Ks[(8*nt+lr)*36 + kk+lc]);
                uint32_t b1 = __float_as_uint(Ks[(8*nt+lr)*36 + kk+4+lc]);
                mma_tf32(s[nt], a0, a1, a2, a3, b0, b1);
            }
        }
        #pragma unroll
        for (int nt = 0; nt < 16; nt++) {
            int j = j0 + 8*nt + 2*lc;
            __nv_bfloat162 blo = *(const __nv_bfloat162*)&bias_w[(size_t)lr*L + j];
            __nv_bfloat162 bhi = *(const __nv_bfloat162*)&bias_w[(size_t)(lr+8)*L + j];
            s[nt][0] += __bfloat162float(blo.x); s[nt][1] += __bfloat162float(blo.y);
            s[nt][2] += __bfloat162float(bhi.x); s[nt][3] += __bfloat162float(bhi.y);
        }

        float mx0 = -1e30f, mx1 = -1e30f;
        #pragma unroll
        for (int nt = 0; nt < 16; nt++) {
            mx0 = fmaxf(mx0, fmaxf(s[nt][0], s[nt][1]));
            mx1 = fmaxf(mx1, fmaxf(s[nt][2], s[nt][3]));
        }
        mx0 = fmaxf(mx0, __shfl_xor_sync(0xffffffffu, mx0, 1));
        mx0 = fmaxf(mx0, __shfl_xor_sync(0xffffffffu, mx0, 2));
        mx1 = fmaxf(mx1, __shfl_xor_sync(0xffffffffu, mx1, 1));
        mx1 = fmaxf(mx1, __shfl_xor_sync(0xffffffffu, mx1, 2));
        float mn0 = fmaxf(m_run[0], mx0), mn1 = fmaxf(m_run[1], mx1);
        float cf0 = __expf(m_run[0] - mn0), cf1 = __expf(m_run[1] - mn1);
        float rs0 = 0.f, rs1 = 0.f;
        #pragma unroll
        for (int nt = 0; nt < 16; nt++) {
            float p0 = __expf(s[nt][0] - mn0);
            float p1 = __expf(s[nt][1] - mn0);
            float p2 = __expf(s[nt][2] - mn1);
            float p3 = __expf(s[nt][3] - mn1);
            rs0 += p0 + p1; rs1 += p2 + p3;
            int colw = 8*nt + 2*lc;
            *(__nv_bfloat162*)&Ps[(arow  )*136 + colw] = __floats2bfloat162_rn(p0, p1);
            *(__nv_bfloat162*)&Ps[(arow+8)*136 + colw] = __floats2bfloat162_rn(p2, p3);
        }
        rs0 += __shfl_xor_sync(0xffffffffu, rs0, 1);
        rs0 += __shfl_xor_sync(0xffffffffu, rs0, 2);
        rs1 += __shfl_xor_sync(0xffffffffu, rs1, 1);
        rs1 += __shfl_xor_sync(0xffffffffu, rs1, 2);
        l_run[0] = l_run[0]*cf0 + rs0;  m_run[0] = mn0;
        l_run[1] = l_run[1]*cf1 + rs1;  m_run[1] = mn1;
        #pragma unroll
        for (int nt = 0; nt < 4; nt++) {
            o[nt][0] *= cf0; o[nt][1] *= cf0;
            o[nt][2] *= cf1; o[nt][3] *= cf1;
        }
        __syncwarp();

        #pragma unroll
        for (int k0 = 0; k0 < 128; k0 += 16) {
            uint32_t a0 = *(const uint32_t*)&Ps[(arow  )*136 + k0 + 2*lc];
            uint32_t a1 = *(const uint32_t*)&Ps[(arow+8)*136 + k0 + 2*lc];
            uint32_t a2 = *(const uint32_t*)&Ps[(arow  )*136 + k0 + 8 + 2*lc];
            uint32_t a3 = *(const uint32_t*)&Ps[(arow+8)*136 + k0 + 8 + 2*lc];
            #pragma unroll
            for (int nt = 0; nt < 4; nt++) {
                uint32_t b0 = *(const uint32_t*)&Vt[(8*nt+lr)*136 + k0 + 2*lc];
                uint32_t b1 = *(const uint32_t*)&Vt[(8*nt+lr)*136 + k0 + 8 + 2*lc];
                mma_bf16(o[nt], a0, a1, a2, a3, b0, b1);
            }
        }
        __syncthreads();
    }

    float inv0 = 1.0f / l_run[0], inv1 = 1.0f / l_run[1];
    #pragma unroll
    for (int nt = 0; nt < 4; nt++) {
        int d = h*32 + 8*nt + 2*lc;
        size_t r0 = (size_t)(i0 + arow) * C + d;
        size_t r1 = (size_t)(i0 + arow + 8) * C + d;
        *(float2*)&g_ao[r0] = make_float2(o[nt][0]*inv0, o[nt][1]*inv0);
        *(float2*)&g_ao[r1] = make_float2(o[nt][2]*inv1, o[nt][3]*inv1);
    }
}

// ---------------- final ----------------
__global__ void __launch_bounds__(256) k_final(const float* __restrict__ xn,
                                               const float* __restrict__ oW,
                                               const float* __restrict__ ob,
                                               float* __restrict__ out)
{
    const int warp = threadIdx.x >> 5, lane = threadIdx.x & 31;
    const int row = blockIdx.x * 8 + warp;
    const float* hr = g_h + (size_t)row * C;
    #pragma unroll
    for (int c = 0; c < 3; c++) {
        float s = 0.f;
        for (int k = lane; k < C; k += 32) s += hr[k] * oW[c*C + k];
        #pragma unroll
        for (int off = 16; off; off >>= 1) s += __shfl_xor_sync(0xffffffffu, s, off);
        if (lane == 0)
            out[row*3 + c] = g_scal[0] * xn[row*3 + c] + g_scal[1] * (s + ob[c]);
    }
}

// ---------------- launcher ----------------
extern "C" void kernel_launch(void* const* d_in, const int* in_sizes, int n_in,
                              void* d_out, int out_size)
{
    const float* x_noisy  = (const float*)d_in[0];
    const float* sigma    = (const float*)d_in[1];
    const float* single   = (const float*)d_in[2];
    const float* pair     = (const float*)d_in[3];
    const float* coord_W  = (const float*)d_in[4];
    const float* coord_b  = (const float*)d_in[5];
    const float* single_W = (const float*)d_in[6];
    const float* single_b = (const float*)d_in[7];
    const float* tmlp_W1  = (const float*)d_in[8];
    const float* tmlp_b1  = (const float*)d_in[9];
    const float* tmlp_W2  = (const float*)d_in[10];
    const float* tmlp_b2  = (const float*)d_in[11];
    const float* ada1_g   = (const float*)d_in[12];
    const float* ada1_b   = (const float*)d_in[13];
    const float* ada1_pW  = (const float*)d_in[14];
    const float* ada1_pb  = (const float*)d_in[15];
    const float* qW       = (const float*)d_in[16];
    const float* kW       = (const float*)d_in[17];
    const float* vW       = (const float*)d_in[18];
    const float* pairW    = (const float*)d_in[19];
    const float* outW     = (const float*)d_in[20];
    const float* outb     = (const float*)d_in[21];
    const float* ada2_g   = (const float*)d_in[22];
    const float* ada2_b   = (const float*)d_in[23];
    const float* ada2_pW  = (const float*)d_in[24];
    const float* ada2_pb  = (const float*)d_in[25];
    const float* ffn_W1   = (const float*)d_in[26];
    const float* ffn_b1   = (const float*)d_in[27];
    const float* ffn_W2   = (const float*)d_in[28];
    const float* ffn_b2   = (const float*)d_in[29];
    const float* out_W    = (const float*)d_in[30];
    const float* out_b    = (const float*)d_in[31];
    float* out = (float*)d_out;

    float *p_h, *p_q, *p_k, *p_v, *p_ao, *p_mid;
    cudaGetSymbolAddress((void**)&p_h,  g_h);
    cudaGetSymbolAddress((void**)&p_q,  g_q);
    cudaGetSymbolAddress((void**)&p_k,  g_k);
    cudaGetSymbolAddress((void**)&p_v,  g_v);
    cudaGetSymbolAddress((void**)&p_ao, g_ao);
    cudaGetSymbolAddress((void**)&p_mid, g_mid);

    static cudaStream_t s2;
    static cudaEvent_t ev_fork, ev_bias;
    static int attr_set = 0;
    if (!attr_set) {
        cudaFuncSetAttribute(k_attn_tc, cudaFuncAttributeMaxDynamicSharedMemorySize, ATTN_SMEM);
        cudaFuncSetAttribute(k_gemm_tc<true,false,true >, cudaFuncAttributeMaxDynamicSharedMemorySize, GEMM_SMEM);
        cudaFuncSetAttribute(k_single_tc, cudaFuncAttributeMaxDynamicSharedMemorySize, GEMM_SMEM);
        cudaFuncSetAttribute(k_qkv_f,  cudaFuncAttributeMaxDynamicSharedMemorySize, GEMM_SMEM);
        cudaFuncSetAttribute(k_ffn1_f, cudaFuncAttributeMaxDynamicSharedMemorySize, GEMM_SMEM);
        cudaStreamCreateWithFlags(&s2, cudaStreamNonBlocking);
        cudaEventCreateWithFlags(&ev_fork, cudaEventDisableTiming);
        cudaEventCreateWithFlags(&ev_bias, cudaEventDisableTiming);
        attr_set = 1;
    }

    // fork: bias runs on side stream, joins before first attention
    cudaEventRecord(ev_fork, 0);
    cudaStreamWaitEvent(s2, ev_fork, 0);
    k_bias_tc<<<(L*L)/128, 256, 0, s2>>>(pair, pairW);
    cudaEventRecord(ev_bias, s2);

    k_prep<<<1, 256>>>(sigma, tmlp_W1, tmlp_b1, tmlp_W2, tmlp_b2,
                       ada1_pW, ada1_pb, ada2_pW, ada2_pb);
    k_fold1<<<NB, 256>>>(ada1_g, ada1_b, ada2_g, ada2_b);
    k_foldW<<<NB*1792/8, 256>>>(qW, kW, vW, ffn_W1, ffn_b1);
    k_single_tc<<<dim3(C/128, L/128), 256, GEMM_SMEM>>>(single, single_W, single_b,
                                                        x_noisy, coord_W, coord_b, p_h);

    for (int b = 0; b < NB; b++) {
        k_rowstat<<<L/8, 256>>>(p_h);
        k_qkv_f<<<dim3(C/128, L/128, 3), 256, GEMM_SMEM>>>(b, p_q, p_k, p_v);
        if (b == 0) cudaStreamWaitEvent(0, ev_bias, 0);
        k_attn_tc<<<dim3(L/128, H), 256, ATTN_SMEM>>>(b);
        k_gemm_tc<true,false,true><<<dim3(C/128, L/128), 256, GEMM_SMEM>>>(
            p_ao, outW + (size_t)b*C*C, outb + b*C, p_h, p_h, L, C, C);
        k_rowstat<<<L/8, 256>>>(p_h);
        k_ffn1_f<<<dim3(4*C/128, L/128), 256, GEMM_SMEM>>>(b, p_mid);
        k_gemm_tc<true,false,true><<<dim3(C/128, L/128), 256, GEMM_SMEM>>>(
            p_mid, ffn_W2 + (size_t)b*4*C*C, ffn_b2 + b*C, p_h, p_h, L, C, 4*C);
    }
    k_final<<<L/8, 256>>>(x_noisy, out_W, out_b, out);
}

// round 9
// speedup vs baseline: 1.2430x; 1.2430x over previous
#include <cuda_runtime.h>
#include <cuda_bf16.h>
#include <math.h>
#include <stdint.h>

#define L 2048
#define C 256
#define NB 4
#define H 8
#define D 32
#define SD 16.0f

// ---------------- scratch (device globals; no allocation allowed) ----------------
__device__ float g_h [L*C];
__device__ float g_q [L*C];
__device__ float g_k [L*C];
__device__ float g_v [L*C];
__device__ float g_ao[L*C];
__device__ float g_mid[L*4*C];
__device__ __nv_bfloat16 g_bias[(size_t)NB*H*L*L];   // 256 MB
__device__ float g_scal[4];   // c_skip, c_out, c_in
// fused-LN precomputes
__device__ float g_G1[NB][C], g_B1[NB][C], g_G2[NB][C], g_B2[NB][C];
__device__ float g_wqkv[(size_t)NB*3*C*C];   // G1-scaled qkv weights
__device__ float g_wf1 [(size_t)NB*4*C*C];   // G2-scaled ffn1 weights
__device__ float g_gwA [NB][3*C + 4*C];      // GW vectors (qkv | ffn1)
__device__ float g_b2A [NB][3*C + 4*C];      // b2 vectors (qkv | ffn1, ffn_b1 folded)
__device__ float g_rs[L], g_m2[L];           // per-row rstd, -mu*rstd

__device__ __forceinline__ float gelu_exact(float x) {
    return 0.5f * x * (1.0f + erff(x * 0.70710678118654752f));
}

__device__ __forceinline__ void mma_tf32(float c[4],
    uint32_t a0, uint32_t a1, uint32_t a2, uint32_t a3,
    uint32_t b0, uint32_t b1)
{
    asm volatile(
        "mma.sync.aligned.m16n8k8.row.col.f32.tf32.tf32.f32 "
        "{%0,%1,%2,%3}, {%4,%5,%6,%7}, {%8,%9}, {%0,%1,%2,%3};"
        : "+f"(c[0]), "+f"(c[1]), "+f"(c[2]), "+f"(c[3])
        : "r"(a0), "r"(a1), "r"(a2), "r"(a3), "r"(b0), "r"(b1));
}

__device__ __forceinline__ void mma_bf16(float c[4],
    uint32_t a0, uint32_t a1, uint32_t a2, uint32_t a3,
    uint32_t b0, uint32_t b1)
{
    asm volatile(
        "mma.sync.aligned.m16n8k16.row.col.f32.bf16.bf16.f32 "
        "{%0,%1,%2,%3}, {%4,%5,%6,%7}, {%8,%9}, {%0,%1,%2,%3};"
        : "+f"(c[0]), "+f"(c[1]), "+f"(c[2]), "+f"(c[3])
        : "r"(a0), "r"(a1), "r"(a2), "r"(a3), "r"(b0), "r"(b1));
}

__device__ __forceinline__ void cp16(float* smem_dst, const float* gsrc) {
    uint32_t s = (uint32_t)__cvta_generic_to_shared(smem_dst);
    asm volatile("cp.async.cg.shared.global [%0], [%1], 16;" :: "r"(s), "l"(gsrc));
}
#define CP_COMMIT() asm volatile("cp.async.commit_group;")
#define CP_WAIT(n)  asm volatile("cp.async.wait_group %0;" :: "n"(n))

// ---------------- K0: time embedding, time MLP, adaLN cond proj, fold1 ----------------
__global__ void __launch_bounds__(256) k_prep(
    const float* __restrict__ sigma,
    const float* __restrict__ tW1, const float* __restrict__ tb1,
    const float* __restrict__ tW2, const float* __restrict__ tb2,
    const float* __restrict__ a1pW, const float* __restrict__ a1pb,
    const float* __restrict__ a2pW, const float* __restrict__ a2pb,
    const float* __restrict__ a1g, const float* __restrict__ a1b,
    const float* __restrict__ a2g, const float* __restrict__ a2b)
{
    __shared__ float temb[C];
    __shared__ float hid[4*C];
    __shared__ float tcs[C];
    __shared__ float ss1[NB][2*C];
    __shared__ float ss2[NB][2*C];
    const int t = threadIdx.x;
    const float sg = sigma[0];
    if (t == 0) {
        float s2 = sg*sg + SD*SD;
        g_scal[0] = SD*SD / s2;
        g_scal[1] = sg*SD*rsqrtf(s2);
        g_scal[2] = rsqrtf(s2);
    }
    const float c_noise = 0.25f * logf(sg + 1e-8f);
    if (t < 128) {
        float fr = expf(-logf(10000.0f) * (float)t / 128.0f);
        float a = c_noise * fr;
        temb[t]       = cosf(a);
        temb[t + 128] = sinf(a);
    }
    __syncthreads();
    for (int r = t; r < 4*C; r += 256) {
        float acc = tb1[r];
        const float* w = tW1 + (size_t)r * C;
        for (int k2 = 0; k2 < C; k2++) acc += temb[k2] * w[k2];
        hid[r] = gelu_exact(acc);
    }
    __syncthreads();
    for (int r = t; r < C; r += 256) {
        float acc = tb2[r];
        const float* w = tW2 + (size_t)r * 4*C;
        for (int k2 = 0; k2 < 4*C; k2++) acc += hid[k2] * w[k2];
        tcs[r] = acc;
    }
    __syncthreads();
    for (int idx = t; idx < NB*2*C; idx += 256) {
        int b = idx / (2*C), r = idx % (2*C);
        float acc1 = a1pb[b*2*C + r];
        const float* w1 = a1pW + ((size_t)b*2*C + r) * C;
        float acc2 = a2pb[b*2*C + r];
        const float* w2 = a2pW + ((size_t)b*2*C + r) * C;
        for (int k2 = 0; k2 < C; k2++) { acc1 += tcs[k2]*w1[k2]; acc2 += tcs[k2]*w2[k2]; }
        ss1[b][r] = acc1;
        ss2[b][r] = acc2;
    }
    __syncthreads();
    for (int idx = t; idx < NB*C; idx += 256) {
        int b = idx >> 8, c = idx & 255;
        float s1 = 1.0f + ss1[b][c];
        g_G1[b][c] = a1g[b*C + c] * s1;
        g_B1[b][c] = a1b[b*C + c] * s1 + ss1[b][C + c];
        float s2 = 1.0f + ss2[b][c];
        g_G2[b][c] = a2g[b*C + c] * s2;
        g_B2[b][c] = a2b[b*C + c] * s2 + ss2[b][C + c];
    }
}

// ---------------- foldW: W' = G (.) W, GW = sum G.W, b2 = sum Bc.W ----------------
__global__ void __launch_bounds__(256) k_foldW(
    const float* __restrict__ qW, const float* __restrict__ kW,
    const float* __restrict__ vW, const float* __restrict__ f1W,
    const float* __restrict__ f1b)
{
    const int lane = threadIdx.x & 31, warp = threadIdx.x >> 5;
    int gidx = blockIdx.x * 8 + warp;
    int b = gidx / 1792, n = gidx % 1792;
    const float *src, *G, *Bc;
    float* dst;
    float extra = 0.f;
    if (n < 768) {
        int w = n >> 8, nn = n & 255;
        src = (w == 0 ? qW : w == 1 ? kW : vW) + ((size_t)b*C + nn)*C;
        dst = g_wqkv + ((size_t)b*768 + n)*C;
        G = g_G1[b]; Bc = g_B1[b];
    } else {
        int nn = n - 768;
        src = f1W + ((size_t)b*4*C + nn)*C;
        dst = g_wf1 + ((size_t)b*1024 + nn)*C;
        G = g_G2[b]; Bc = g_B2[b];
        extra = f1b[b*4*C + nn];
    }
    float gw = 0.f, b2 = 0.f;
    for (int c = lane; c < C; c += 32) {
        float w = src[c];
        float wg = w * G[c];
        dst[c] = wg;
        gw += wg;
        b2 += w * Bc[c];
    }
    #pragma unroll
    for (int off = 16; off; off >>= 1) {
        gw += __shfl_xor_sync(0xffffffffu, gw, off);
        b2 += __shfl_xor_sync(0xffffffffu, b2, off);
    }
    if (lane == 0) { g_gwA[b][n] = gw; g_b2A[b][n] = b2 + extra; }
}

// ---------------- row stats: rs = rstd, m2 = -mu*rstd ----------------
__global__ void __launch_bounds__(256) k_rowstat(const float* __restrict__ X)
{
    const int lane = threadIdx.x & 31, warp = threadIdx.x >> 5;
    const int row = blockIdx.x * 8 + warp;
    const float* xr = X + (size_t)row * C;
    float s = 0.f, sq = 0.f;
    #pragma unroll
    for (int i = 0; i < 8; i++) {
        float v = xr[lane + 32*i];
        s += v; sq += v*v;
    }
    #pragma unroll
    for (int off = 16; off; off >>= 1) {
        s  += __shfl_xor_sync(0xffffffffu, s,  off);
        sq += __shfl_xor_sync(0xffffffffu, sq, off);
    }
    if (lane == 0) {
        float mu = s * (1.0f/256.0f);
        float var = sq * (1.0f/256.0f) - mu*mu;
        float rs = rsqrtf(var + 1e-5f);
        g_rs[row] = rs;
        g_m2[row] = -mu * rs;
    }
}

// ---------------- pair bias via tf32 mma ----------------
__global__ void __launch_bounds__(256) k_bias_tc(const float* __restrict__ pair,
                                                 const float* __restrict__ pW)
{
    __shared__ float As[128][68];
    __shared__ float Ws[32][68];
    const int tid = threadIdx.x, lane = tid & 31, warp = tid >> 5;
    const int lr = lane >> 2, lc = lane & 3;
    const size_t row0 = (size_t)blockIdx.x * 128;

    #pragma unroll
    for (int it = 0; it < 8; it++) {
        int idx = tid + 256*it;
        int r = idx >> 4, q = idx & 15;
        *(float4*)&As[r][4*q] = *(const float4*)&pair[(row0 + r) * 64 + 4*q];
    }
    #pragma unroll
    for (int it = 0; it < 2; it++) {
        int idx = tid + 256*it;
        int r = idx >> 4, q = idx & 15;
        *(float4*)&Ws[r][4*q] = *(const float4*)&pW[r * 64 + 4*q];
    }
    __syncthreads();

    float c[4][4] = {};
    const int arow = 16*warp + lr;
    #pragma unroll
    for (int kk = 0; kk < 64; kk += 8) {
        uint32_t a0 = __float_as_uint(As[arow  ][kk+lc]);
        uint32_t a1 = __float_as_uint(As[arow+8][kk+lc]);
        uint32_t a2 = __float_as_uint(As[arow  ][kk+4+lc]);
        uint32_t a3 = __float_as_uint(As[arow+8][kk+4+lc]);
        #pragma unroll
        for (int nt = 0; nt < 4; nt++) {
            uint32_t b0 = __float_as_uint(Ws[8*nt+lr][kk+lc]);
            uint32_t b1 = __float_as_uint(Ws[8*nt+lr][kk+4+lc]);
            mma_tf32(c[nt], a0, a1, a2, a3, b0, b1);
        }
    }
    __syncthreads();

    __nv_bfloat16* stage = (__nv_bfloat16*)&As[0][0];
    const int SP = 132;
    #pragma unroll
    for (int nt = 0; nt < 4; nt++) {
        #pragma unroll
        for (int half = 0; half < 2; half++) {
            int rloc = 16*warp + lr + 8*half;
            int col = 8*nt + 2*lc;
            stage[(col  )*SP + rloc] = __float2bfloat16(c[nt][2*half+0]);
            stage[(col+1)*SP + rloc] = __float2bfloat16(c[nt][2*half+1]);
        }
    }
    __syncthreads();
    for (int idx = tid; idx < 32*64; idx += 256) {
        int o = idx >> 6, r2 = (idx & 63) * 2;
        __nv_bfloat162 v = *(const __nv_bfloat162*)&stage[o*SP + r2];
        *(__nv_bfloat162*)&g_bias[(size_t)o * (size_t)L * (size_t)L + row0 + r2] = v;
    }
}

// ---------------- tf32 GEMM, 128x128 tile, cp.async double-buffered ----------------
#define GSTAGE (128*36)
#define GEMM_SMEM (4*GSTAGE*4)

template<bool HAS_BIAS, bool DO_GELU, bool HAS_RES, bool LN_EPI, bool COORD>
__device__ __forceinline__ void gemm_body128(
    const float* __restrict__ A, const float* __restrict__ Bw,
    const float* __restrict__ bias, const float* __restrict__ Rsrc,
    const float* __restrict__ GW, const float* __restrict__ b2v,
    const float* __restrict__ xn, const float* __restrict__ cW,
    const float* __restrict__ cb,
    float* __restrict__ Cout, int M, int N, int K)
{
    extern __shared__ float sm[];
    float* AsB = sm;
    float* BsB = sm + 2*GSTAGE;
    const int tid = threadIdx.x, lane = tid & 31, warp = tid >> 5;
    const int wm = warp >> 1, wn = warp & 1;
    const int m0 = blockIdx.y * 128, n0 = blockIdx.x * 128;
    const int lr = lane >> 2, lc = lane & 3;
    const int pr = tid >> 3, pq = tid & 7;

    float c[2][8][4];
    #pragma unroll
    for (int mt = 0; mt < 2; mt++)
        #pragma unroll
        for (int nt = 0; nt < 8; nt++)
            #pragma unroll
            for (int r = 0; r < 4; r++) c[mt][nt][r] = 0.f;

    const int NK = K >> 5;
    {
        float* as = AsB; float* bs = BsB;
        #pragma unroll
        for (int it = 0; it < 4; it++) {
            int r = pr + 32*it;
            cp16(&as[r*36 + 4*pq], &A [(size_t)(m0 + r)*K + 4*pq]);
            cp16(&bs[r*36 + 4*pq], &Bw[(size_t)(n0 + r)*K + 4*pq]);
        }
        CP_COMMIT();
    }

    for (int ks = 0; ks < NK; ks++) {
        if (ks + 1 < NK) {
            float* as = AsB + ((ks+1)&1)*GSTAGE;
            float* bs = BsB + ((ks+1)&1)*GSTAGE;
            int k0 = (ks+1) << 5;
            #pragma unroll
            for (int it = 0; it < 4; it++) {
                int r = pr + 32*it;
                cp16(&as[r*36 + 4*pq], &A [(size_t)(m0 + r)*K + k0 + 4*pq]);
                cp16(&bs[r*36 + 4*pq], &Bw[(size_t)(n0 + r)*K + k0 + 4*pq]);
            }
            CP_COMMIT();
            CP_WAIT(1);
        } else {
            CP_WAIT(0);
        }
        __syncthreads();
        const float* as = AsB + (ks&1)*GSTAGE;
        const float* bs = BsB + (ks&1)*GSTAGE;
        #pragma unroll
        for (int kk = 0; kk < 32; kk += 8) {
            uint32_t a[2][4], b[8][2];
            #pragma unroll
            for (int mt = 0; mt < 2; mt++) {
                int row = 32*wm + 16*mt + lr;
                a[mt][0] = __float_as_uint(as[(row  )*36 + kk+lc]);
                a[mt][1] = __float_as_uint(as[(row+8)*36 + kk+lc]);
                a[mt][2] = __float_as_uint(as[(row  )*36 + kk+4+lc]);
                a[mt][3] = __float_as_uint(as[(row+8)*36 + kk+4+lc]);
            }
            #pragma unroll
            for (int nt = 0; nt < 8; nt++) {
                int col = 64*wn + 8*nt + lr;
                b[nt][0] = __float_as_uint(bs[col*36 + kk+lc]);
                b[nt][1] = __float_as_uint(bs[col*36 + kk+4+lc]);
            }
            #pragma unroll
            for (int mt = 0; mt < 2; mt++)
                #pragma unroll
                for (int nt = 0; nt < 8; nt++)
                    mma_tf32(c[mt][nt], a[mt][0], a[mt][1], a[mt][2], a[mt][3],
                             b[nt][0], b[nt][1]);
        }
        __syncthreads();
    }

    #pragma unroll
    for (int mt = 0; mt < 2; mt++) {
        #pragma unroll
        for (int half = 0; half < 2; half++) {
            int row = m0 + 32*wm + 16*mt + lr + 8*half;
            float rs = 0.f, m2 = 0.f, cx0 = 0.f, cx1 = 0.f, cx2 = 0.f;
            if (LN_EPI) { rs = g_rs[row]; m2 = g_m2[row]; }
            if (COORD) {
                float cin = g_scal[2];
                cx0 = xn[row*3+0]*cin; cx1 = xn[row*3+1]*cin; cx2 = xn[row*3+2]*cin;
            }
            #pragma unroll
            for (int nt = 0; nt < 8; nt++) {
                int col = n0 + 64*wn + 8*nt + 2*lc;
                float v0 = c[mt][nt][2*half+0];
                float v1 = c[mt][nt][2*half+1];
                if (LN_EPI) {
                    v0 = rs*v0 + m2*GW[col]   + b2v[col];
                    v1 = rs*v1 + m2*GW[col+1] + b2v[col+1];
                }
                if (HAS_BIAS) { v0 += bias[col]; v1 += bias[col+1]; }
                if (COORD) {
                    v0 += cb[col]   + cx0*cW[col*3+0]     + cx1*cW[col*3+1]     + cx2*cW[col*3+2];
                    v1 += cb[col+1] + cx0*cW[(col+1)*3+0] + cx1*cW[(col+1)*3+1] + cx2*cW[(col+1)*3+2];
                }
                if (DO_GELU)  { v0 = gelu_exact(v0); v1 = gelu_exact(v1); }
                if (HAS_RES)  { v0 += Rsrc[(size_t)row*N + col]; v1 += Rsrc[(size_t)row*N + col + 1]; }
                *(float2*)&Cout[(size_t)row*N + col] = make_float2(v0, v1);
            }
        }
    }
}

template<bool HB, bool HG, bool HR>
__global__ void __launch_bounds__(256, 2) k_gemm_tc(
    const float* __restrict__ A, const float* __restrict__ Bw,
    const float* __restrict__ bias, const float* __restrict__ Rsrc,
    float* __restrict__ Cout, int M, int N, int K)
{
    gemm_body128<HB,HG,HR,false,false>(A, Bw, bias, Rsrc,
        nullptr, nullptr, nullptr, nullptr, nullptr, Cout, M, N, K);
}

__global__ void __launch_bounds__(256, 2) k_single_tc(
    const float* __restrict__ A, const float* __restrict__ Bw,
    const float* __restrict__ bias,
    const float* __restrict__ xn, const float* __restrict__ cW,
    const float* __restrict__ cb, float* __restrict__ Cout)
{
    gemm_body128<true,false,false,false,true>(A, Bw, bias, nullptr,
        nullptr, nullptr, xn, cW, cb, Cout, L, C, C);
}

__global__ void __launch_bounds__(256, 2) k_qkv_f(
    int b, float* __restrict__ q, float* __restrict__ k, float* __restrict__ v)
{
    int z = blockIdx.z;
    const float* Bw = g_wqkv + ((size_t)b*768 + z*256)*C;
    const float* GW = &g_gwA[b][z*256];
    const float* b2 = &g_b2A[b][z*256];
    float* Cout = (z == 0) ? q : (z == 1) ? k : v;
    gemm_body128<false,false,false,true,false>(g_h, Bw, nullptr, nullptr,
        GW, b2, nullptr, nullptr, nullptr, Cout, L, C, C);
}

__global__ void __launch_bounds__(256, 2) k_ffn1_f(int b, float* __restrict__ mid)
{
    const float* Bw = g_wf1 + (size_t)b*1024*C;
    const float* GW = &g_gwA[b][768];
    const float* b2 = &g_b2A[b][768];
    gemm_body128<false,true,false,true,false>(g_h, Bw, nullptr, nullptr,
        GW, b2, nullptr, nullptr, nullptr, mid, L, 4*C, C);
}

// ---------------- tensor-core flash attention (tf32 QK^T, bf16 PV) ----------------
#define ATTN_SMEM (18432 + 18432 + 8704 + 34816)
__global__ void __launch_bounds__(256) k_attn_tc(int blk)
{
    extern __shared__ char smc[];
    float* Qs = (float*)smc;
    float* Ks = (float*)(smc + 18432);
    __nv_bfloat16* Vt = (__nv_bfloat16*)(smc + 36864);
    __nv_bfloat16* Ps = (__nv_bfloat16*)(smc + 45568);

    const int h  = blockIdx.y;
    const int i0 = blockIdx.x * 128;
    const int tid = threadIdx.x, lane = tid & 31, warp = tid >> 5;
    const int lr = lane >> 2, lc = lane & 3;
    const float scale = 0.17677669529663687f;

    #pragma unroll
    for (int it = 0; it < 4; it++) {
        int idx = tid + 256*it;
        int r = idx >> 3, q = idx & 7;
        float4 v = *(const float4*)&g_q[(size_t)(i0 + r)*C + h*32 + 4*q];
        float* dst = &Qs[r*36 + 4*q];
        dst[0]=v.x*scale; dst[1]=v.y*scale; dst[2]=v.z*scale; dst[3]=v.w*scale;
    }

    float m_run[2] = {-1e30f, -1e30f};
    float l_run[2] = {0.f, 0.f};
    float o[4][4];
    #pragma unroll
    for (int nt = 0; nt < 4; nt++)
        #pragma unroll
        for (int r = 0; r < 4; r++) o[nt][r] = 0.f;

    const __nv_bfloat16* bias_w = g_bias + ((size_t)blk*H + h)*(size_t)L*L
                                         + (size_t)(i0 + 16*warp)*L;
    const int arow = 16*warp + lr;

    for (int j0 = 0; j0 < L; j0 += 128) {
        #pragma unroll
        for (int it = 0; it < 4; it++) {
            int idx = tid + 256*it;
            int r = idx >> 3, q = idx & 7;
            float4 kv = *(const float4*)&g_k[(size_t)(j0 + r)*C + h*32 + 4*q];
            *(float4*)&Ks[r*36 + 4*q] = kv;
            float4 vv = *(const float4*)&g_v[(size_t)(j0 + r)*C + h*32 + 4*q];
            Vt[(4*q+0)*136 + r] = __float2bfloat16(vv.x);
            Vt[(4*q+1)*136 + r] = __float2bfloat16(vv.y);
            Vt[(4*q+2)*136 + r] = __float2bfloat16(vv.z);
            Vt[(4*q+3)*136 + r] = __float2bfloat16(vv.w);
        }
        __syncthreads();

        float s[16][4];
        #pragma unroll
        for (int nt = 0; nt < 16; nt++)
            #pragma unroll
            for (int r = 0; r < 4; r++) s[nt][r] = 0.f;
        #pragma unroll
        for (int kk = 0; kk < 32; kk += 8) {
            uint32_t a0 = __float_as_uint(Qs[(arow  )*36 + kk+lc]);
            uint32_t a1 = __float_as_uint(Qs[(arow+8)*36 + kk+lc]);
            uint32_t a2 = __float_as_uint(Qs[(arow  )*36 + kk+4+lc]);
            uint32_t a3 = __float_as_uint(Qs[(arow+8)*36 + kk+4+lc]);
            #pragma unroll
            for (int nt = 0; nt < 16; nt++) {
                uint32_t b0 = __float_as_uint(Ks[(8*nt+lr)*36 + kk+lc]);
                uint32_t b1 = __float_as_uint(Ks[(8*nt+lr)*36 + kk+4+lc]);
                mma_tf32(s[nt], a0, a1, a2, a3, b0, b1);
            }
        }
        #pragma unroll
        for (int nt = 0; nt < 16; nt++) {
            int j = j0 + 8*nt + 2*lc;
            __nv_bfloat162 blo = *(const __nv_bfloat162*)&bias_w[(size_t)lr*L + j];
            __nv_bfloat162 bhi = *(const __nv_bfloat162*)&bias_w[(size_t)(lr+8)*L + j];
            s[nt][0] += __bfloat162float(blo.x); s[nt][1] += __bfloat162float(blo.y);
            s[nt][2] += __bfloat162float(bhi.x); s[nt][3] += __bfloat162float(bhi.y);
        }

        float mx0 = -1e30f, mx1 = -1e30f;
        #pragma unroll
        for (int nt = 0; nt < 16; nt++) {
            mx0 = fmaxf(mx0, fmaxf(s[nt][0], s[nt][1]));
            mx1 = fmaxf(mx1, fmaxf(s[nt][2], s[nt][3]));
        }
        mx0 = fmaxf(mx0, __shfl_xor_sync(0xffffffffu, mx0, 1));
        mx0 = fmaxf(mx0, __shfl_xor_sync(0xffffffffu, mx0, 2));
        mx1 = fmaxf(mx1, __shfl_xor_sync(0xffffffffu, mx1, 1));
        mx1 = fmaxf(mx1, __shfl_xor_sync(0xffffffffu, mx1, 2));
        float mn0 = fmaxf(m_run[0], mx0), mn1 = fmaxf(m_run[1], mx1);
        float cf0 = __expf(m_run[0] - mn0), cf1 = __expf(m_run[1] - mn1);
        float rs0 = 0.f, rs1 = 0.f;
        #pragma unroll
        for (int nt = 0; nt < 16; nt++) {
            float p0 = __expf(s[nt][0] - mn0);
            float p1 = __expf(s[nt][1] - mn0);
            float p2 = __expf(s[nt][2] - mn1);
            float p3 = __expf(s[nt][3] - mn1);
            rs0 += p0 + p1; rs1 += p2 + p3;
            int colw = 8*nt + 2*lc;
            *(__nv_bfloat162*)&Ps[(arow  )*136 + colw] = __floats2bfloat162_rn(p0, p1);
            *(__nv_bfloat162*)&Ps[(arow+8)*136 + colw] = __floats2bfloat162_rn(p2, p3);
        }
        rs0 += __shfl_xor_sync(0xffffffffu, rs0, 1);
        rs0 += __shfl_xor_sync(0xffffffffu, rs0, 2);
        rs1 += __shfl_xor_sync(0xffffffffu, rs1, 1);
        rs1 += __shfl_xor_sync(0xffffffffu, rs1, 2);
        l_run[0] = l_run[0]*cf0 + rs0;  m_run[0] = mn0;
        l_run[1] = l_run[1]*cf1 + rs1;  m_run[1] = mn1;
        #pragma unroll
        for (int nt = 0; nt < 4; nt++) {
            o[nt][0] *= cf0; o[nt][1] *= cf0;
            o[nt][2] *= cf1; o[nt][3] *= cf1;
        }
        __syncwarp();

        #pragma unroll
        for (int k0 = 0; k0 < 128; k0 += 16) {
            uint32_t a0 = *(const uint32_t*)&Ps[(arow  )*136 + k0 + 2*lc];
            uint32_t a1 = *(const uint32_t*)&Ps[(arow+8)*136 + k0 + 2*lc];
            uint32_t a2 = *(const uint32_t*)&Ps[(arow  )*136 + k0 + 8 + 2*lc];
            uint32_t a3 = *(const uint32_t*)&Ps[(arow+8)*136 + k0 + 8 + 2*lc];
            #pragma unroll
            for (int nt = 0; nt < 4; nt++) {
                uint32_t b0 = *(const uint32_t*)&Vt[(8*nt+lr)*136 + k0 + 2*lc];
                uint32_t b1 = *(const uint32_t*)&Vt[(8*nt+lr)*136 + k0 + 8 + 2*lc];
                mma_bf16(o[nt], a0, a1, a2, a3, b0, b1);
            }
        }
        __syncthreads();
    }

    float inv0 = 1.0f / l_run[0], inv1 = 1.0f / l_run[1];
    #pragma unroll
    for (int nt = 0; nt < 4; nt++) {
        int d = h*32 + 8*nt + 2*lc;
        size_t r0 = (size_t)(i0 + arow) * C + d;
        size_t r1 = (size_t)(i0 + arow + 8) * C + d;
        *(float2*)&g_ao[r0] = make_float2(o[nt][0]*inv0, o[nt][1]*inv0);
        *(float2*)&g_ao[r1] = make_float2(o[nt][2]*inv1, o[nt][3]*inv1);
    }
}

// ---------------- final ----------------
__global__ void __launch_bounds__(256) k_final(const float* __restrict__ xn,
                                               const float* __restrict__ oW,
                                               const float* __restrict__ ob,
                                               float* __restrict__ out)
{
    const int warp = threadIdx.x >> 5, lane = threadIdx.x & 31;
    const int row = blockIdx.x * 8 + warp;
    const float* hr = g_h + (size_t)row * C;
    #pragma unroll
    for (int c = 0; c < 3; c++) {
        float s = 0.f;
        for (int k = lane; k < C; k += 32) s += hr[k] * oW[c*C + k];
        #pragma unroll
        for (int off = 16; off; off >>= 1) s += __shfl_xor_sync(0xffffffffu, s, off);
        if (lane == 0)
            out[row*3 + c] = g_scal[0] * xn[row*3 + c] + g_scal[1] * (s + ob[c]);
    }
}

// ---------------- launcher ----------------
extern "C" void kernel_launch(void* const* d_in, const int* in_sizes, int n_in,
                              void* d_out, int out_size)
{
    const float* x_noisy  = (const float*)d_in[0];
    const float* sigma    = (const float*)d_in[1];
    const float* single   = (const float*)d_in[2];
    const float* pair     = (const float*)d_in[3];
    const float* coord_W  = (const float*)d_in[4];
    const float* coord_b  = (const float*)d_in[5];
    const float* single_W = (const float*)d_in[6];
    const float* single_b = (const float*)d_in[7];
    const float* tmlp_W1  = (const float*)d_in[8];
    const float* tmlp_b1  = (const float*)d_in[9];
    const float* tmlp_W2  = (const float*)d_in[10];
    const float* tmlp_b2  = (const float*)d_in[11];
    const float* ada1_g   = (const float*)d_in[12];
    const float* ada1_b   = (const float*)d_in[13];
    const float* ada1_pW  = (const float*)d_in[14];
    const float* ada1_pb  = (const float*)d_in[15];
    const float* qW       = (const float*)d_in[16];
    const float* kW       = (const float*)d_in[17];
    const float* vW       = (const float*)d_in[18];
    const float* pairW    = (const float*)d_in[19];
    const float* outW     = (const float*)d_in[20];
    const float* outb     = (const float*)d_in[21];
    const float* ada2_g   = (const float*)d_in[22];
    const float* ada2_b   = (const float*)d_in[23];
    const float* ada2_pW  = (const float*)d_in[24];
    const float* ada2_pb  = (const float*)d_in[25];
    const float* ffn_W1   = (const float*)d_in[26];
    const float* ffn_b1   = (const float*)d_in[27];
    const float* ffn_W2   = (const float*)d_in[28];
    const float* ffn_b2   = (const float*)d_in[29];
    const float* out_W    = (const float*)d_in[30];
    const float* out_b    = (const float*)d_in[31];
    float* out = (float*)d_out;

    float *p_h, *p_q, *p_k, *p_v, *p_ao, *p_mid;
    cudaGetSymbolAddress((void**)&p_h,  g_h);
    cudaGetSymbolAddress((void**)&p_q,  g_q);
    cudaGetSymbolAddress((void**)&p_k,  g_k);
    cudaGetSymbolAddress((void**)&p_v,  g_v);
    cudaGetSymbolAddress((void**)&p_ao, g_ao);
    cudaGetSymbolAddress((void**)&p_mid, g_mid);

    static int attr_set = 0;
    if (!attr_set) {
        cudaFuncSetAttribute(k_attn_tc, cudaFuncAttributeMaxDynamicSharedMemorySize, ATTN_SMEM);
        cudaFuncSetAttribute(k_gemm_tc<true,false,true >, cudaFuncAttributeMaxDynamicSharedMemorySize, GEMM_SMEM);
        cudaFuncSetAttribute(k_single_tc, cudaFuncAttributeMaxDynamicSharedMemorySize, GEMM_SMEM);
        cudaFuncSetAttribute(k_qkv_f,  cudaFuncAttributeMaxDynamicSharedMemorySize, GEMM_SMEM);
        cudaFuncSetAttribute(k_ffn1_f, cudaFuncAttributeMaxDynamicSharedMemorySize, GEMM_SMEM);
        attr_set = 1;
    }

    k_bias_tc<<<(L*L)/128, 256>>>(pair, pairW);
    k_prep<<<1, 256>>>(sigma, tmlp_W1, tmlp_b1, tmlp_W2, tmlp_b2,
                       ada1_pW, ada1_pb, ada2_pW, ada2_pb,
                       ada1_g, ada1_b, ada2_g, ada2_b);
    k_foldW<<<NB*1792/8, 256>>>(qW, kW, vW, ffn_W1, ffn_b1);
    k_single_tc<<<dim3(C/128, L/128), 256, GEMM_SMEM>>>(single, single_W, single_b,
                                                        x_noisy, coord_W, coord_b, p_h);

    for (int b = 0; b < NB; b++) {
        k_rowstat<<<L/8, 256>>>(p_h);
        k_qkv_f<<<dim3(C/128, L/128, 3), 256, GEMM_SMEM>>>(b, p_q, p_k, p_v);
        k_attn_tc<<<dim3(L/128, H), 256, ATTN_SMEM>>>(b);
        k_gemm_tc<true,false,true><<<dim3(C/128, L/128), 256, GEMM_SMEM>>>(
            p_ao, outW + (size_t)b*C*C, outb + b*C, p_h, p_h, L, C, C);
        k_rowstat<<<L/8, 256>>>(p_h);
        k_ffn1_f<<<dim3(4*C/128, L/128), 256, GEMM_SMEM>>>(b, p_mid);
        k_gemm_tc<true,false,true><<<dim3(C/128, L/128), 256, GEMM_SMEM>>>(
            p_mid, ffn_W2 + (size_t)b*4*C*C, ffn_b2 + b*C, p_h, p_h, L, C, 4*C);
    }
    k_final<<<L/8, 256>>>(x_noisy, out_W, out_b, out);
}

// round 10
// speedup vs baseline: 1.3126x; 1.0561x over previous
#include <cuda_runtime.h>
#include <cuda_bf16.h>
#include <math.h>
#include <stdint.h>

#define L 2048
#define C 256
#define NB 4
#define H 8
#define D 32
#define SD 16.0f

// ---------------- scratch (device globals; no allocation allowed) ----------------
__device__ float g_h [L*C];
__device__ float g_q [L*C];
__device__ float g_k [L*C];
__device__ float g_v [L*C];
__device__ float g_ao[L*C];
__device__ float g_mid[L*4*C];
__device__ __nv_bfloat16 g_bias[(size_t)NB*H*L*L];   // 256 MB
__device__ float g_scal[4];   // c_skip, c_out, c_in
// fused-LN precomputes
__device__ float g_G1[NB][C], g_B1[NB][C], g_G2[NB][C], g_B2[NB][C];
__device__ float g_wqkv[(size_t)NB*3*C*C];   // G1-scaled qkv weights
__device__ float g_wf1 [(size_t)NB*4*C*C];   // G2-scaled ffn1 weights
__device__ float g_gwA [NB][3*C + 4*C];      // GW vectors (qkv | ffn1)
__device__ float g_b2A [NB][3*C + 4*C];      // b2 vectors (qkv | ffn1, ffn_b1 folded)
__device__ float g_rs[L], g_m2[L];           // per-row rstd, -mu*rstd

__device__ __forceinline__ float gelu_exact(float x) {
    return 0.5f * x * (1.0f + erff(x * 0.70710678118654752f));
}

__device__ __forceinline__ void mma_tf32(float c[4],
    uint32_t a0, uint32_t a1, uint32_t a2, uint32_t a3,
    uint32_t b0, uint32_t b1)
{
    asm volatile(
        "mma.sync.aligned.m16n8k8.row.col.f32.tf32.tf32.f32 "
        "{%0,%1,%2,%3}, {%4,%5,%6,%7}, {%8,%9}, {%0,%1,%2,%3};"
        : "+f"(c[0]), "+f"(c[1]), "+f"(c[2]), "+f"(c[3])
        : "r"(a0), "r"(a1), "r"(a2), "r"(a3), "r"(b0), "r"(b1));
}

__device__ __forceinline__ void mma_bf16(float c[4],
    uint32_t a0, uint32_t a1, uint32_t a2, uint32_t a3,
    uint32_t b0, uint32_t b1)
{
    asm volatile(
        "mma.sync.aligned.m16n8k16.row.col.f32.bf16.bf16.f32 "
        "{%0,%1,%2,%3}, {%4,%5,%6,%7}, {%8,%9}, {%0,%1,%2,%3};"
        : "+f"(c[0]), "+f"(c[1]), "+f"(c[2]), "+f"(c[3])
        : "r"(a0), "r"(a1), "r"(a2), "r"(a3), "r"(b0), "r"(b1));
}

__device__ __forceinline__ uint32_t pack_bf16x2(float lo, float hi) {
    __nv_bfloat162 t = __floats2bfloat162_rn(lo, hi);
    return *(uint32_t*)&t;
}

__device__ __forceinline__ void cp16(float* smem_dst, const float* gsrc) {
    uint32_t s = (uint32_t)__cvta_generic_to_shared(smem_dst);
    asm volatile("cp.async.cg.shared.global [%0], [%1], 16;" :: "r"(s), "l"(gsrc));
}
#define CP_COMMIT() asm volatile("cp.async.commit_group;")
#define CP_WAIT(n)  asm volatile("cp.async.wait_group %0;" :: "n"(n))

// ---------------- K0: time embedding, time MLP, adaLN cond proj, fold1 ----------------
__global__ void __launch_bounds__(256) k_prep(
    const float* __restrict__ sigma,
    const float* __restrict__ tW1, const float* __restrict__ tb1,
    const float* __restrict__ tW2, const float* __restrict__ tb2,
    const float* __restrict__ a1pW, const float* __restrict__ a1pb,
    const float* __restrict__ a2pW, const float* __restrict__ a2pb,
    const float* __restrict__ a1g, const float* __restrict__ a1b,
    const float* __restrict__ a2g, const float* __restrict__ a2b)
{
    __shared__ float temb[C];
    __shared__ float hid[4*C];
    __shared__ float tcs[C];
    __shared__ float ss1[NB][2*C];
    __shared__ float ss2[NB][2*C];
    const int t = threadIdx.x;
    const float sg = sigma[0];
    if (t == 0) {
        float s2 = sg*sg + SD*SD;
        g_scal[0] = SD*SD / s2;
        g_scal[1] = sg*SD*rsqrtf(s2);
        g_scal[2] = rsqrtf(s2);
    }
    const float c_noise = 0.25f * logf(sg + 1e-8f);
    if (t < 128) {
        float fr = expf(-logf(10000.0f) * (float)t / 128.0f);
        float a = c_noise * fr;
        temb[t]       = cosf(a);
        temb[t + 128] = sinf(a);
    }
    __syncthreads();
    for (int r = t; r < 4*C; r += 256) {
        float acc = tb1[r];
        const float* w = tW1 + (size_t)r * C;
        for (int k2 = 0; k2 < C; k2++) acc += temb[k2] * w[k2];
        hid[r] = gelu_exact(acc);
    }
    __syncthreads();
    for (int r = t; r < C; r += 256) {
        float acc = tb2[r];
        const float* w = tW2 + (size_t)r * 4*C;
        for (int k2 = 0; k2 < 4*C; k2++) acc += hid[k2] * w[k2];
        tcs[r] = acc;
    }
    __syncthreads();
    for (int idx = t; idx < NB*2*C; idx += 256) {
        int b = idx / (2*C), r = idx % (2*C);
        float acc1 = a1pb[b*2*C + r];
        const float* w1 = a1pW + ((size_t)b*2*C + r) * C;
        float acc2 = a2pb[b*2*C + r];
        const float* w2 = a2pW + ((size_t)b*2*C + r) * C;
        for (int k2 = 0; k2 < C; k2++) { acc1 += tcs[k2]*w1[k2]; acc2 += tcs[k2]*w2[k2]; }
        ss1[b][r] = acc1;
        ss2[b][r] = acc2;
    }
    __syncthreads();
    for (int idx = t; idx < NB*C; idx += 256) {
        int b = idx >> 8, c = idx & 255;
        float s1 = 1.0f + ss1[b][c];
        g_G1[b][c] = a1g[b*C + c] * s1;
        g_B1[b][c] = a1b[b*C + c] * s1 + ss1[b][C + c];
        float s2 = 1.0f + ss2[b][c];
        g_G2[b][c] = a2g[b*C + c] * s2;
        g_B2[b][c] = a2b[b*C + c] * s2 + ss2[b][C + c];
    }
}

// ---------------- foldW ----------------
__global__ void __launch_bounds__(256) k_foldW(
    const float* __restrict__ qW, const float* __restrict__ kW,
    const float* __restrict__ vW, const float* __restrict__ f1W,
    const float* __restrict__ f1b)
{
    const int lane = threadIdx.x & 31, warp = threadIdx.x >> 5;
    int gidx = blockIdx.x * 8 + warp;
    int b = gidx / 1792, n = gidx % 1792;
    const float *src, *G, *Bc;
    float* dst;
    float extra = 0.f;
    if (n < 768) {
        int w = n >> 8, nn = n & 255;
        src = (w == 0 ? qW : w == 1 ? kW : vW) + ((size_t)b*C + nn)*C;
        dst = g_wqkv + ((size_t)b*768 + n)*C;
        G = g_G1[b]; Bc = g_B1[b];
    } else {
        int nn = n - 768;
        src = f1W + ((size_t)b*4*C + nn)*C;
        dst = g_wf1 + ((size_t)b*1024 + nn)*C;
        G = g_G2[b]; Bc = g_B2[b];
        extra = f1b[b*4*C + nn];
    }
    float gw = 0.f, b2 = 0.f;
    for (int c = lane; c < C; c += 32) {
        float w = src[c];
        float wg = w * G[c];
        dst[c] = wg;
        gw += wg;
        b2 += w * Bc[c];
    }
    #pragma unroll
    for (int off = 16; off; off >>= 1) {
        gw += __shfl_xor_sync(0xffffffffu, gw, off);
        b2 += __shfl_xor_sync(0xffffffffu, b2, off);
    }
    if (lane == 0) { g_gwA[b][n] = gw; g_b2A[b][n] = b2 + extra; }
}

// ---------------- row stats ----------------
__global__ void __launch_bounds__(256) k_rowstat(const float* __restrict__ X)
{
    const int lane = threadIdx.x & 31, warp = threadIdx.x >> 5;
    const int row = blockIdx.x * 8 + warp;
    const float* xr = X + (size_t)row * C;
    float s = 0.f, sq = 0.f;
    #pragma unroll
    for (int i = 0; i < 8; i++) {
        float v = xr[lane + 32*i];
        s += v; sq += v*v;
    }
    #pragma unroll
    for (int off = 16; off; off >>= 1) {
        s  += __shfl_xor_sync(0xffffffffu, s,  off);
        sq += __shfl_xor_sync(0xffffffffu, sq, off);
    }
    if (lane == 0) {
        float mu = s * (1.0f/256.0f);
        float var = sq * (1.0f/256.0f) - mu*mu;
        float rs = rsqrtf(var + 1e-5f);
        g_rs[row] = rs;
        g_m2[row] = -mu * rs;
    }
}

// ---------------- pair bias via tf32 mma ----------------
__global__ void __launch_bounds__(256) k_bias_tc(const float* __restrict__ pair,
                                                 const float* __restrict__ pW)
{
    __shared__ float As[128][68];
    __shared__ float Ws[32][68];
    const int tid = threadIdx.x, lane = tid & 31, warp = tid >> 5;
    const int lr = lane >> 2, lc = lane & 3;
    const size_t row0 = (size_t)blockIdx.x * 128;

    #pragma unroll
    for (int it = 0; it < 8; it++) {
        int idx = tid + 256*it;
        int r = idx >> 4, q = idx & 15;
        *(float4*)&As[r][4*q] = *(const float4*)&pair[(row0 + r) * 64 + 4*q];
    }
    #pragma unroll
    for (int it = 0; it < 2; it++) {
        int idx = tid + 256*it;
        int r = idx >> 4, q = idx & 15;
        *(float4*)&Ws[r][4*q] = *(const float4*)&pW[r * 64 + 4*q];
    }
    __syncthreads();

    float c[4][4] = {};
    const int arow = 16*warp + lr;
    #pragma unroll
    for (int kk = 0; kk < 64; kk += 8) {
        uint32_t a0 = __float_as_uint(As[arow  ][kk+lc]);
        uint32_t a1 = __float_as_uint(As[arow+8][kk+lc]);
        uint32_t a2 = __float_as_uint(As[arow  ][kk+4+lc]);
        uint32_t a3 = __float_as_uint(As[arow+8][kk+4+lc]);
        #pragma unroll
        for (int nt = 0; nt < 4; nt++) {
            uint32_t b0 = __float_as_uint(Ws[8*nt+lr][kk+lc]);
            uint32_t b1 = __float_as_uint(Ws[8*nt+lr][kk+4+lc]);
            mma_tf32(c[nt], a0, a1, a2, a3, b0, b1);
        }
    }
    __syncthreads();

    __nv_bfloat16* stage = (__nv_bfloat16*)&As[0][0];
    const int SP = 132;
    #pragma unroll
    for (int nt = 0; nt < 4; nt++) {
        #pragma unroll
        for (int half = 0; half < 2; half++) {
            int rloc = 16*warp + lr + 8*half;
            int col = 8*nt + 2*lc;
            stage[(col  )*SP + rloc] = __float2bfloat16(c[nt][2*half+0]);
            stage[(col+1)*SP + rloc] = __float2bfloat16(c[nt][2*half+1]);
        }
    }
    __syncthreads();
    for (int idx = tid; idx < 32*64; idx += 256) {
        int o = idx >> 6, r2 = (idx & 63) * 2;
        __nv_bfloat162 v = *(const __nv_bfloat162*)&stage[o*SP + r2];
        *(__nv_bfloat162*)&g_bias[(size_t)o * (size_t)L * (size_t)L + row0 + r2] = v;
    }
}

// ---------------- tf32 GEMM, 64x128 tile, cp.async double-buffered ----------------
// 8 warps = 2(M) x 4(N); warp tile 32x32.
#define GA_STAGE (64*36)
#define GB_STAGE (128*36)
#define GEMM_SMEM ((2*GA_STAGE + 2*GB_STAGE)*4)

template<bool HAS_BIAS, bool DO_GELU, bool HAS_RES, bool LN_EPI, bool COORD>
__device__ __forceinline__ void gemm_body64(
    const float* __restrict__ A, const float* __restrict__ Bw,
    const float* __restrict__ bias, const float* __restrict__ Rsrc,
    const float* __restrict__ GW, const float* __restrict__ b2v,
    const float* __restrict__ xn, const float* __restrict__ cW,
    const float* __restrict__ cb,
    float* __restrict__ Cout, int M, int N, int K)
{
    extern __shared__ float sm[];
    float* AsB = sm;                    // [2][64][36]
    float* BsB = sm + 2*GA_STAGE;       // [2][128][36]
    const int tid = threadIdx.x, lane = tid & 31, warp = tid >> 5;
    const int wm = warp >> 2, wn = warp & 3;
    const int m0 = blockIdx.y * 64, n0 = blockIdx.x * 128;
    const int lr = lane >> 2, lc = lane & 3;
    const int pr = tid >> 3, pq = tid & 7;

    float c[2][4][4];
    #pragma unroll
    for (int mt = 0; mt < 2; mt++)
        #pragma unroll
        for (int nt = 0; nt < 4; nt++)
            #pragma unroll
            for (int r = 0; r < 4; r++) c[mt][nt][r] = 0.f;

    const int NK = K >> 5;
    {
        #pragma unroll
        for (int it = 0; it < 2; it++) {
            int r = pr + 32*it;
            cp16(&AsB[r*36 + 4*pq], &A[(size_t)(m0 + r)*K + 4*pq]);
        }
        #pragma unroll
        for (int it = 0; it < 4; it++) {
            int r = pr + 32*it;
            cp16(&BsB[r*36 + 4*pq], &Bw[(size_t)(n0 + r)*K + 4*pq]);
        }
        CP_COMMIT();
    }

    for (int ks = 0; ks < NK; ks++) {
        if (ks + 1 < NK) {
            float* as = AsB + ((ks+1)&1)*GA_STAGE;
            float* bs = BsB + ((ks+1)&1)*GB_STAGE;
            int k0 = (ks+1) << 5;
            #pragma unroll
            for (int it = 0; it < 2; it++) {
                int r = pr + 32*it;
                cp16(&as[r*36 + 4*pq], &A[(size_t)(m0 + r)*K + k0 + 4*pq]);
            }
            #pragma unroll
            for (int it = 0; it < 4; it++) {
                int r = pr + 32*it;
                cp16(&bs[r*36 + 4*pq], &Bw[(size_t)(n0 + r)*K + k0 + 4*pq]);
            }
            CP_COMMIT();
            CP_WAIT(1);
        } else {
            CP_WAIT(0);
        }
        __syncthreads();
        const float* as = AsB + (ks&1)*GA_STAGE;
        const float* bs = BsB + (ks&1)*GB_STAGE;
        #pragma unroll
        for (int kk = 0; kk < 32; kk += 8) {
            uint32_t a[2][4], b[4][2];
            #pragma unroll
            for (int mt = 0; mt < 2; mt++) {
                int row = 32*wm + 16*mt + lr;
                a[mt][0] = __float_as_uint(as[(row  )*36 + kk+lc]);
                a[mt][1] = __float_as_uint(as[(row+8)*36 + kk+lc]);
                a[mt][2] = __float_as_uint(as[(row  )*36 + kk+4+lc]);
                a[mt][3] = __float_as_uint(as[(row+8)*36 + kk+4+lc]);
            }
            #pragma unroll
            for (int nt = 0; nt < 4; nt++) {
                int col = 32*wn + 8*nt + lr;
                b[nt][0] = __float_as_uint(bs[col*36 + kk+lc]);
                b[nt][1] = __float_as_uint(bs[col*36 + kk+4+lc]);
            }
            #pragma unroll
            for (int mt = 0; mt < 2; mt++)
                #pragma unroll
                for (int nt = 0; nt < 4; nt++)
                    mma_tf32(c[mt][nt], a[mt][0], a[mt][1], a[mt][2], a[mt][3],
                             b[nt][0], b[nt][1]);
        }
        __syncthreads();
    }

    #pragma unroll
    for (int mt = 0; mt < 2; mt++) {
        #pragma unroll
        for (int half = 0; half < 2; half++) {
            int row = m0 + 32*wm + 16*mt + lr + 8*half;
            float rs = 0.f, m2 = 0.f, cx0 = 0.f, cx1 = 0.f, cx2 = 0.f;
            if (LN_EPI) { rs = g_rs[row]; m2 = g_m2[row]; }
            if (COORD) {
                float cin = g_scal[2];
                cx0 = xn[row*3+0]*cin; cx1 = xn[row*3+1]*cin; cx2 = xn[row*3+2]*cin;
            }
            #pragma unroll
            for (int nt = 0; nt < 4; nt++) {
                int col = n0 + 32*wn + 8*nt + 2*lc;
                float v0 = c[mt][nt][2*half+0];
                float v1 = c[mt][nt][2*half+1];
                if (LN_EPI) {
                    v0 = rs*v0 + m2*GW[col]   + b2v[col];
                    v1 = rs*v1 + m2*GW[col+1] + b2v[col+1];
                }
                if (HAS_BIAS) { v0 += bias[col]; v1 += bias[col+1]; }
                if (COORD) {
                    v0 += cb[col]   + cx0*cW[col*3+0]     + cx1*cW[col*3+1]     + cx2*cW[col*3+2];
                    v1 += cb[col+1] + cx0*cW[(col+1)*3+0] + cx1*cW[(col+1)*3+1] + cx2*cW[(col+1)*3+2];
                }
                if (DO_GELU)  { v0 = gelu_exact(v0); v1 = gelu_exact(v1); }
                if (HAS_RES)  { v0 += Rsrc[(size_t)row*N + col]; v1 += Rsrc[(size_t)row*N + col + 1]; }
                *(float2*)&Cout[(size_t)row*N + col] = make_float2(v0, v1);
            }
        }
    }
}

template<bool HB, bool HG, bool HR>
__global__ void __launch_bounds__(256, 2) k_gemm_tc(
    const float* __restrict__ A, const float* __restrict__ Bw,
    const float* __restrict__ bias, const float* __restrict__ Rsrc,
    float* __restrict__ Cout, int M, int N, int K)
{
    gemm_body64<HB,HG,HR,false,false>(A, Bw, bias, Rsrc,
        nullptr, nullptr, nullptr, nullptr, nullptr, Cout, M, N, K);
}

__global__ void __launch_bounds__(256, 2) k_single_tc(
    const float* __restrict__ A, const float* __restrict__ Bw,
    const float* __restrict__ bias,
    const float* __restrict__ xn, const float* __restrict__ cW,
    const float* __restrict__ cb, float* __restrict__ Cout)
{
    gemm_body64<true,false,false,false,true>(A, Bw, bias, nullptr,
        nullptr, nullptr, xn, cW, cb, Cout, L, C, C);
}

__global__ void __launch_bounds__(256, 2) k_qkv_f(
    int b, float* __restrict__ q, float* __restrict__ k, float* __restrict__ v)
{
    int z = blockIdx.z;
    const float* Bw = g_wqkv + ((size_t)b*768 + z*256)*C;
    const float* GW = &g_gwA[b][z*256];
    const float* b2 = &g_b2A[b][z*256];
    float* Cout = (z == 0) ? q : (z == 1) ? k : v;
    gemm_body64<false,false,false,true,false>(g_h, Bw, nullptr, nullptr,
        GW, b2, nullptr, nullptr, nullptr, Cout, L, C, C);
}

__global__ void __launch_bounds__(256, 2) k_ffn1_f(int b, float* __restrict__ mid)
{
    const float* Bw = g_wf1 + (size_t)b*1024*C;
    const float* GW = &g_gwA[b][768];
    const float* b2 = &g_b2A[b][768];
    gemm_body64<false,true,false,true,false>(g_h, Bw, nullptr, nullptr,
        GW, b2, nullptr, nullptr, nullptr, mid, L, 4*C, C);
}

// ---------------- tensor-core flash attention ----------------
// tf32 QK^T (cp.async double-buffered K), bf16 PV with P fed straight from
// softmax registers (m16n8k16 A-fragment layout matches), V register-prefetch.
#define KSTG (128*36)
#define VSTG (32*136)
#define ATTN_SMEM (18432 + 2*18432 + 2*8704)   // Qs + Ks[2] + Vt[2] = 72704
__global__ void __launch_bounds__(256) k_attn_tc(int blk)
{
    extern __shared__ char smc[];
    float* Qs = (float*)smc;                                  // [128][36]
    float* KsB = (float*)(smc + 18432);                       // [2][128][36]
    __nv_bfloat16* VtB = (__nv_bfloat16*)(smc + 18432 + 2*18432); // [2][32][136]

    const int h  = blockIdx.y;
    const int i0 = blockIdx.x * 128;
    const int tid = threadIdx.x, lane = tid & 31, warp = tid >> 5;
    const int lr = lane >> 2, lc = lane & 3;
    const float scale = 0.17677669529663687f;

    // Q load (scaled)
    #pragma unroll
    for (int it = 0; it < 4; it++) {
        int idx = tid + 256*it;
        int r = idx >> 3, q = idx & 7;
        float4 v = *(const float4*)&g_q[(size_t)(i0 + r)*C + h*32 + 4*q];
        float* dst = &Qs[r*36 + 4*q];
        dst[0]=v.x*scale; dst[1]=v.y*scale; dst[2]=v.z*scale; dst[3]=v.w*scale;
    }

    // prologue: V0 -> regs, cp.async K0
    float4 vv[4];
    {
        #pragma unroll
        for (int it = 0; it < 4; it++) {
            int idx = tid + 256*it;
            int r = idx >> 3, q = idx & 7;
            vv[it] = *(const float4*)&g_v[(size_t)(0 + r)*C + h*32 + 4*q];
            cp16(&KsB[r*36 + 4*q], &g_k[(size_t)(0 + r)*C + h*32 + 4*q]);
        }
        CP_COMMIT();
        #pragma unroll
        for (int it = 0; it < 4; it++) {
            int idx = tid + 256*it;
            int r = idx >> 3, q = idx & 7;
            VtB[(4*q+0)*136 + r] = __float2bfloat16(vv[it].x);
            VtB[(4*q+1)*136 + r] = __float2bfloat16(vv[it].y);
            VtB[(4*q+2)*136 + r] = __float2bfloat16(vv[it].z);
            VtB[(4*q+3)*136 + r] = __float2bfloat16(vv[it].w);
        }
        CP_WAIT(0);
        __syncthreads();
    }

    float m_run[2] = {-1e30f, -1e30f};
    float l_run[2] = {0.f, 0.f};
    float o[4][4];
    #pragma unroll
    for (int nt = 0; nt < 4; nt++)
        #pragma unroll
        for (int r = 0; r < 4; r++) o[nt][r] = 0.f;

    const __nv_bfloat16* bias_w = g_bias + ((size_t)blk*H + h)*(size_t)L*L
                                         + (size_t)(i0 + 16*warp)*L;
    const int arow = 16*warp + lr;

    for (int jt = 0; jt < 16; jt++) {
        const int cur = jt & 1, nxt = cur ^ 1;
        const float* Ks = KsB + cur*KSTG;
        const __nv_bfloat16* Vt = VtB + cur*VSTG;
        const bool more = (jt + 1 < 16);

        if (more) {
            int j0n = (jt + 1) * 128;
            float* ks = KsB + nxt*KSTG;
            #pragma unroll
            for (int it = 0; it < 4; it++) {
                int idx = tid + 256*it;
                int r = idx >> 3, q = idx & 7;
                vv[it] = *(const float4*)&g_v[(size_t)(j0n + r)*C + h*32 + 4*q];
                cp16(&ks[r*36 + 4*q], &g_k[(size_t)(j0n + r)*C + h*32 + 4*q]);
            }
            CP_COMMIT();
        }

        // S = Q K^T
        float s[16][4];
        #pragma unroll
        for (int nt = 0; nt < 16; nt++)
            #pragma unroll
            for (int r = 0; r < 4; r++) s[nt][r] = 0.f;
        #pragma unroll
        for (int kk = 0; kk < 32; kk += 8) {
            uint32_t a0 = __float_as_uint(Qs[(arow  )*36 + kk+lc]);
            uint32_t a1 = __float_as_uint(Qs[(arow+8)*36 + kk+lc]);
            uint32_t a2 = __float_as_uint(Qs[(arow  )*36 + kk+4+lc]);
            uint32_t a3 = __float_as_uint(Qs[(arow+8)*36 + kk+4+lc]);
            #pragma unroll
            for (int nt = 0; nt < 16; nt++) {
                uint32_t b0 = __float_as_uint(Ks[(8*nt+lr)*36 + kk+lc]);
                uint32_t b1 = __float_as_uint(Ks[(8*nt+lr)*36 + kk+4+lc]);
                mma_tf32(s[nt], a0, a1, a2, a3, b0, b1);
            }
        }
        // + pair bias
        const int j0 = jt * 128;
        #pragma unroll
        for (int nt = 0; nt < 16; nt++) {
            int j = j0 + 8*nt + 2*lc;
            __nv_bfloat162 blo = *(const __nv_bfloat162*)&bias_w[(size_t)lr*L + j];
            __nv_bfloat162 bhi = *(const __nv_bfloat162*)&bias_w[(size_t)(lr+8)*L + j];
            s[nt][0] += __bfloat162float(blo.x); s[nt][1] += __bfloat162float(blo.y);
            s[nt][2] += __bfloat162float(bhi.x); s[nt][3] += __bfloat162float(bhi.y);
        }

        // online softmax (rows lr / lr+8 within warp quad)
        float mx0 = -1e30f, mx1 = -1e30f;
        #pragma unroll
        for (int nt = 0; nt < 16; nt++) {
            mx0 = fmaxf(mx0, fmaxf(s[nt][0], s[nt][1]));
            mx1 = fmaxf(mx1, fmaxf(s[nt][2], s[nt][3]));
        }
        mx0 = fmaxf(mx0, __shfl_xor_sync(0xffffffffu, mx0, 1));
        mx0 = fmaxf(mx0, __shfl_xor_sync(0xffffffffu, mx0, 2));
        mx1 = fmaxf(mx1, __shfl_xor_sync(0xffffffffu, mx1, 1));
        mx1 = fmaxf(mx1, __shfl_xor_sync(0xffffffffu, mx1, 2));
        float mn0 = fmaxf(m_run[0], mx0), mn1 = fmaxf(m_run[1], mx1);
        float cf0 = __expf(m_run[0] - mn0), cf1 = __expf(m_run[1] - mn1);
        float rs0 = 0.f, rs1 = 0.f;
        #pragma unroll
        for (int nt = 0; nt < 16; nt++) {
            s[nt][0] = __expf(s[nt][0] - mn0);
            s[nt][1] = __expf(s[nt][1] - mn0);
            s[nt][2] = __expf(s[nt][2] - mn1);
            s[nt][3] = __expf(s[nt][3] - mn1);
            rs0 += s[nt][0] + s[nt][1];
            rs1 += s[nt][2] + s[nt][3];
        }
        rs0 += __shfl_xor_sync(0xffffffffu, rs0, 1);
        rs0 += __shfl_xor_sync(0xffffffffu, rs0, 2);
        rs1 += __shfl_xor_sync(0xffffffffu, rs1, 1);
        rs1 += __shfl_xor_sync(0xffffffffu, rs1, 2);
        l_run[0] = l_run[0]*cf0 + rs0;  m_run[0] = mn0;
        l_run[1] = l_run[1]*cf1 + rs1;  m_run[1] = mn1;
        #pragma unroll
        for (int nt = 0; nt < 4; nt++) {
            o[nt][0] *= cf0; o[nt][1] *= cf0;
            o[nt][2] *= cf1; o[nt][3] *= cf1;
        }

        // O += P V : P packed straight from registers (bf16 A-fragment layout)
        #pragma unroll
        for (int c2 = 0; c2 < 8; c2++) {
            uint32_t a0 = pack_bf16x2(s[2*c2  ][0], s[2*c2  ][1]);
            uint32_t a1 = pack_bf16x2(s[2*c2  ][2], s[2*c2  ][3]);
            uint32_t a2 = pack_bf16x2(s[2*c2+1][0], s[2*c2+1][1]);
            uint32_t a3 = pack_bf16x2(s[2*c2+1][2], s[2*c2+1][3]);
            #pragma unroll
            for (int nt = 0; nt < 4; nt++) {
                uint32_t b0 = *(const uint32_t*)&Vt[(8*nt+lr)*136 + 16*c2 + 2*lc];
                uint32_t b1 = *(const uint32_t*)&Vt[(8*nt+lr)*136 + 16*c2 + 8 + 2*lc];
                mma_bf16(o[nt], a0, a1, a2, a3, b0, b1);
            }
        }

        if (more) {
            __nv_bfloat16* vt = VtB + nxt*VSTG;
            #pragma unroll
            for (int it = 0; it < 4; it++) {
                int idx = tid + 256*it;
                int r = idx >> 3, q = idx & 7;
                vt[(4*q+0)*136 + r] = __float2bfloat16(vv[it].x);
                vt[(4*q+1)*136 + r] = __float2bfloat16(vv[it].y);
                vt[(4*q+2)*136 + r] = __float2bfloat16(vv[it].z);
                vt[(4*q+3)*136 + r] = __float2bfloat16(vv[it].w);
            }
            CP_WAIT(0);
        }
        __syncthreads();
    }

    float inv0 = 1.0f / l_run[0], inv1 = 1.0f / l_run[1];
    #pragma unroll
    for (int nt = 0; nt < 4; nt++) {
        int d = h*32 + 8*nt + 2*lc;
        size_t r0 = (size_t)(i0 + arow) * C + d;
        size_t r1 = (size_t)(i0 + arow + 8) * C + d;
        *(float2*)&g_ao[r0] = make_float2(o[nt][0]*inv0, o[nt][1]*inv0);
        *(float2*)&g_ao[r1] = make_float2(o[nt][2]*inv1, o[nt][3]*inv1);
    }
}

// ---------------- final ----------------
__global__ void __launch_bounds__(256) k_final(const float* __restrict__ xn,
                                               const float* __restrict__ oW,
                                               const float* __restrict__ ob,
                                               float* __restrict__ out)
{
    const int warp = threadIdx.x >> 5, lane = threadIdx.x & 31;
    const int row = blockIdx.x * 8 + warp;
    const float* hr = g_h + (size_t)row * C;
    #pragma unroll
    for (int c = 0; c < 3; c++) {
        float s = 0.f;
        for (int k = lane; k < C; k += 32) s += hr[k] * oW[c*C + k];
        #pragma unroll
        for (int off = 16; off; off >>= 1) s += __shfl_xor_sync(0xffffffffu, s, off);
        if (lane == 0)
            out[row*3 + c] = g_scal[0] * xn[row*3 + c] + g_scal[1] * (s + ob[c]);
    }
}

// ---------------- launcher ----------------
extern "C" void kernel_launch(void* const* d_in, const int* in_sizes, int n_in,
                              void* d_out, int out_size)
{
    const float* x_noisy  = (const float*)d_in[0];
    const float* sigma    = (const float*)d_in[1];
    const float* single   = (const float*)d_in[2];
    const float* pair     = (const float*)d_in[3];
    const float* coord_W  = (const float*)d_in[4];
    const float* coord_b  = (const float*)d_in[5];
    const float* single_W = (const float*)d_in[6];
    const float* single_b = (const float*)d_in[7];
    const float* tmlp_W1  = (const float*)d_in[8];
    const float* tmlp_b1  = (const float*)d_in[9];
    const float* tmlp_W2  = (const float*)d_in[10];
    const float* tmlp_b2  = (const float*)d_in[11];
    const float* ada1_g   = (const float*)d_in[12];
    const float* ada1_b   = (const float*)d_in[13];
    const float* ada1_pW  = (const float*)d_in[14];
    const float* ada1_pb  = (const float*)d_in[15];
    const float* qW       = (const float*)d_in[16];
    const float* kW       = (const float*)d_in[17];
    const float* vW       = (const float*)d_in[18];
    const float* pairW    = (const float*)d_in[19];
    const float* outW     = (const float*)d_in[20];
    const float* outb     = (const float*)d_in[21];
    const float* ada2_g   = (const float*)d_in[22];
    const float* ada2_b   = (const float*)d_in[23];
    const float* ada2_pW  = (const float*)d_in[24];
    const float* ada2_pb  = (const float*)d_in[25];
    const float* ffn_W1   = (const float*)d_in[26];
    const float* ffn_b1   = (const float*)d_in[27];
    const float* ffn_W2   = (const float*)d_in[28];
    const float* ffn_b2   = (const float*)d_in[29];
    const float* out_W    = (const float*)d_in[30];
    const float* out_b    = (const float*)d_in[31];
    float* out = (float*)d_out;

    float *p_h, *p_q, *p_k, *p_v, *p_ao, *p_mid;
    cudaGetSymbolAddress((void**)&p_h,  g_h);
    cudaGetSymbolAddress((void**)&p_q,  g_q);
    cudaGetSymbolAddress((void**)&p_k,  g_k);
    cudaGetSymbolAddress((void**)&p_v,  g_v);
    cudaGetSymbolAddress((void**)&p_ao, g_ao);
    cudaGetSymbolAddress((void**)&p_mid, g_mid);

    static int attr_set = 0;
    if (!attr_set) {
        cudaFuncSetAttribute(k_attn_tc, cudaFuncAttributeMaxDynamicSharedMemorySize, ATTN_SMEM);
        cudaFuncSetAttribute(k_gemm_tc<true,false,true >, cudaFuncAttributeMaxDynamicSharedMemorySize, GEMM_SMEM);
        cudaFuncSetAttribute(k_single_tc, cudaFuncAttributeMaxDynamicSharedMemorySize, GEMM_SMEM);
        cudaFuncSetAttribute(k_qkv_f,  cudaFuncAttributeMaxDynamicSharedMemorySize, GEMM_SMEM);
        cudaFuncSetAttribute(k_ffn1_f, cudaFuncAttributeMaxDynamicSharedMemorySize, GEMM_SMEM);
        attr_set = 1;
    }

    k_bias_tc<<<(L*L)/128, 256>>>(pair, pairW);
    k_prep<<<1, 256>>>(sigma, tmlp_W1, tmlp_b1, tmlp_W2, tmlp_b2,
                       ada1_pW, ada1_pb, ada2_pW, ada2_pb,
                       ada1_g, ada1_b, ada2_g, ada2_b);
    k_foldW<<<NB*1792/8, 256>>>(qW, kW, vW, ffn_W1, ffn_b1);
    k_single_tc<<<dim3(C/128, L/64), 256, GEMM_SMEM>>>(single, single_W, single_b,
                                                       x_noisy, coord_W, coord_b, p_h);

    for (int b = 0; b < NB; b++) {
        k_rowstat<<<L/8, 256>>>(p_h);
        k_qkv_f<<<dim3(C/128, L/64, 3), 256, GEMM_SMEM>>>(b, p_q, p_k, p_v);
        k_attn_tc<<<dim3(L/128, H), 256, ATTN_SMEM>>>(b);
        k_gemm_tc<true,false,true><<<dim3(C/128, L/64), 256, GEMM_SMEM>>>(
            p_ao, outW + (size_t)b*C*C, outb + b*C, p_h, p_h, L, C, C);
        k_rowstat<<<L/8, 256>>>(p_h);
        k_ffn1_f<<<dim3(4*C/128, L/64), 256, GEMM_SMEM>>>(b, p_mid);
        k_gemm_tc<true,false,true><<<dim3(C/128, L/64), 256, GEMM_SMEM>>>(
            p_mid, ffn_W2 + (size_t)b*4*C*C, ffn_b2 + b*C, p_h, p_h, L, C, 4*C);
    }
    k_final<<<L/8, 256>>>(x_noisy, out_W, out_b, out);
}

// round 11
// speedup vs baseline: 1.3281x; 1.0118x over previous
#include <cuda_runtime.h>
#include <cuda_bf16.h>
#include <math.h>
#include <stdint.h>

#define L 2048
#define C 256
#define NB 4
#define H 8
#define D 32
#define SD 16.0f

// ---------------- scratch (device globals; no allocation allowed) ----------------
__device__ float g_h [L*C];
__device__ float g_q [L*C];
__device__ float g_k [L*C];
__device__ float g_v [L*C];
__device__ float g_ao[L*C];
__device__ float g_mid[L*4*C];
__device__ __nv_bfloat16 g_bias[(size_t)NB*H*L*L];   // 256 MB
__device__ float g_scal[4];   // c_skip, c_out, c_in
// fused-LN precomputes
__device__ float g_G1[NB][C], g_B1[NB][C], g_G2[NB][C], g_B2[NB][C];
__device__ float g_wqkv[(size_t)NB*3*C*C];   // G1-scaled qkv weights
__device__ float g_wf1 [(size_t)NB*4*C*C];   // G2-scaled ffn1 weights
__device__ float g_gwA [NB][3*C + 4*C];      // GW vectors (qkv | ffn1)
__device__ float g_b2A [NB][3*C + 4*C];      // b2 vectors (qkv | ffn1, ffn_b1 folded)

__device__ __forceinline__ float gelu_exact(float x) {
    return 0.5f * x * (1.0f + erff(x * 0.70710678118654752f));
}

__device__ __forceinline__ void mma_tf32(float c[4],
    uint32_t a0, uint32_t a1, uint32_t a2, uint32_t a3,
    uint32_t b0, uint32_t b1)
{
    asm volatile(
        "mma.sync.aligned.m16n8k8.row.col.f32.tf32.tf32.f32 "
        "{%0,%1,%2,%3}, {%4,%5,%6,%7}, {%8,%9}, {%0,%1,%2,%3};"
        : "+f"(c[0]), "+f"(c[1]), "+f"(c[2]), "+f"(c[3])
        : "r"(a0), "r"(a1), "r"(a2), "r"(a3), "r"(b0), "r"(b1));
}

__device__ __forceinline__ void mma_bf16(float c[4],
    uint32_t a0, uint32_t a1, uint32_t a2, uint32_t a3,
    uint32_t b0, uint32_t b1)
{
    asm volatile(
        "mma.sync.aligned.m16n8k16.row.col.f32.bf16.bf16.f32 "
        "{%0,%1,%2,%3}, {%4,%5,%6,%7}, {%8,%9}, {%0,%1,%2,%3};"
        : "+f"(c[0]), "+f"(c[1]), "+f"(c[2]), "+f"(c[3])
        : "r"(a0), "r"(a1), "r"(a2), "r"(a3), "r"(b0), "r"(b1));
}

__device__ __forceinline__ uint32_t pack_bf16x2(float lo, float hi) {
    __nv_bfloat162 t = __floats2bfloat162_rn(lo, hi);
    return *(uint32_t*)&t;
}

__device__ __forceinline__ void cp16(float* smem_dst, const float* gsrc) {
    uint32_t s = (uint32_t)__cvta_generic_to_shared(smem_dst);
    asm volatile("cp.async.cg.shared.global [%0], [%1], 16;" :: "r"(s), "l"(gsrc));
}
#define CP_COMMIT() asm volatile("cp.async.commit_group;")
#define CP_WAIT(n)  asm volatile("cp.async.wait_group %0;" :: "n"(n))

// ---------------- K0: time embedding, time MLP, adaLN cond proj, fold1 ----------------
__global__ void __launch_bounds__(256) k_prep(
    const float* __restrict__ sigma,
    const float* __restrict__ tW1, const float* __restrict__ tb1,
    const float* __restrict__ tW2, const float* __restrict__ tb2,
    const float* __restrict__ a1pW, const float* __restrict__ a1pb,
    const float* __restrict__ a2pW, const float* __restrict__ a2pb,
    const float* __restrict__ a1g, const float* __restrict__ a1b,
    const float* __restrict__ a2g, const float* __restrict__ a2b)
{
    __shared__ float temb[C];
    __shared__ float hid[4*C];
    __shared__ float tcs[C];
    __shared__ float ss1[NB][2*C];
    __shared__ float ss2[NB][2*C];
    const int t = threadIdx.x;
    const float sg = sigma[0];
    if (t == 0) {
        float s2 = sg*sg + SD*SD;
        g_scal[0] = SD*SD / s2;
        g_scal[1] = sg*SD*rsqrtf(s2);
        g_scal[2] = rsqrtf(s2);
    }
    const float c_noise = 0.25f * logf(sg + 1e-8f);
    if (t < 128) {
        float fr = expf(-logf(10000.0f) * (float)t / 128.0f);
        float a = c_noise * fr;
        temb[t]       = cosf(a);
        temb[t + 128] = sinf(a);
    }
    __syncthreads();
    for (int r = t; r < 4*C; r += 256) {
        float acc = tb1[r];
        const float* w = tW1 + (size_t)r * C;
        for (int k2 = 0; k2 < C; k2++) acc += temb[k2] * w[k2];
        hid[r] = gelu_exact(acc);
    }
    __syncthreads();
    for (int r = t; r < C; r += 256) {
        float acc = tb2[r];
        const float* w = tW2 + (size_t)r * 4*C;
        for (int k2 = 0; k2 < 4*C; k2++) acc += hid[k2] * w[k2];
        tcs[r] = acc;
    }
    __syncthreads();
    for (int idx = t; idx < NB*2*C; idx += 256) {
        int b = idx / (2*C), r = idx % (2*C);
        float acc1 = a1pb[b*2*C + r];
        const float* w1 = a1pW + ((size_t)b*2*C + r) * C;
        float acc2 = a2pb[b*2*C + r];
        const float* w2 = a2pW + ((size_t)b*2*C + r) * C;
        for (int k2 = 0; k2 < C; k2++) { acc1 += tcs[k2]*w1[k2]; acc2 += tcs[k2]*w2[k2]; }
        ss1[b][r] = acc1;
        ss2[b][r] = acc2;
    }
    __syncthreads();
    for (int idx = t; idx < NB*C; idx += 256) {
        int b = idx >> 8, c = idx & 255;
        float s1 = 1.0f + ss1[b][c];
        g_G1[b][c] = a1g[b*C + c] * s1;
        g_B1[b][c] = a1b[b*C + c] * s1 + ss1[b][C + c];
        float s2 = 1.0f + ss2[b][c];
        g_G2[b][c] = a2g[b*C + c] * s2;
        g_B2[b][c] = a2b[b*C + c] * s2 + ss2[b][C + c];
    }
}

// ---------------- foldW ----------------
__global__ void __launch_bounds__(256) k_foldW(
    const float* __restrict__ qW, const float* __restrict__ kW,
    const float* __restrict__ vW, const float* __restrict__ f1W,
    const float* __restrict__ f1b)
{
    const int lane = threadIdx.x & 31, warp = threadIdx.x >> 5;
    int gidx = blockIdx.x * 8 + warp;
    int b = gidx / 1792, n = gidx % 1792;
    const float *src, *G, *Bc;
    float* dst;
    float extra = 0.f;
    if (n < 768) {
        int w = n >> 8, nn = n & 255;
        src = (w == 0 ? qW : w == 1 ? kW : vW) + ((size_t)b*C + nn)*C;
        dst = g_wqkv + ((size_t)b*768 + n)*C;
        G = g_G1[b]; Bc = g_B1[b];
    } else {
        int nn = n - 768;
        src = f1W + ((size_t)b*4*C + nn)*C;
        dst = g_wf1 + ((size_t)b*1024 + nn)*C;
        G = g_G2[b]; Bc = g_B2[b];
        extra = f1b[b*4*C + nn];
    }
    float gw = 0.f, b2 = 0.f;
    for (int c = lane; c < C; c += 32) {
        float w = src[c];
        float wg = w * G[c];
        dst[c] = wg;
        gw += wg;
        b2 += w * Bc[c];
    }
    #pragma unroll
    for (int off = 16; off; off >>= 1) {
        gw += __shfl_xor_sync(0xffffffffu, gw, off);
        b2 += __shfl_xor_sync(0xffffffffu, b2, off);
    }
    if (lane == 0) { g_gwA[b][n] = gw; g_b2A[b][n] = b2 + extra; }
}

// ---------------- pair bias via tf32 mma ----------------
__global__ void __launch_bounds__(256) k_bias_tc(const float* __restrict__ pair,
                                                 const float* __restrict__ pW)
{
    __shared__ float As[128][68];
    __shared__ float Ws[32][68];
    const int tid = threadIdx.x, lane = tid & 31, warp = tid >> 5;
    const int lr = lane >> 2, lc = lane & 3;
    const size_t row0 = (size_t)blockIdx.x * 128;

    #pragma unroll
    for (int it = 0; it < 8; it++) {
        int idx = tid + 256*it;
        int r = idx >> 4, q = idx & 15;
        *(float4*)&As[r][4*q] = *(const float4*)&pair[(row0 + r) * 64 + 4*q];
    }
    #pragma unroll
    for (int it = 0; it < 2; it++) {
        int idx = tid + 256*it;
        int r = idx >> 4, q = idx & 15;
        *(float4*)&Ws[r][4*q] = *(const float4*)&pW[r * 64 + 4*q];
    }
    __syncthreads();

    float c[4][4] = {};
    const int arow = 16*warp + lr;
    #pragma unroll
    for (int kk = 0; kk < 64; kk += 8) {
        uint32_t a0 = __float_as_uint(As[arow  ][kk+lc]);
        uint32_t a1 = __float_as_uint(As[arow+8][kk+lc]);
        uint32_t a2 = __float_as_uint(As[arow  ][kk+4+lc]);
        uint32_t a3 = __float_as_uint(As[arow+8][kk+4+lc]);
        #pragma unroll
        for (int nt = 0; nt < 4; nt++) {
            uint32_t b0 = __float_as_uint(Ws[8*nt+lr][kk+lc]);
            uint32_t b1 = __float_as_uint(Ws[8*nt+lr][kk+4+lc]);
            mma_tf32(c[nt], a0, a1, a2, a3, b0, b1);
        }
    }
    __syncthreads();

    __nv_bfloat16* stage = (__nv_bfloat16*)&As[0][0];
    const int SP = 132;
    #pragma unroll
    for (int nt = 0; nt < 4; nt++) {
        #pragma unroll
        for (int half = 0; half < 2; half++) {
            int rloc = 16*warp + lr + 8*half;
            int col = 8*nt + 2*lc;
            stage[(col  )*SP + rloc] = __float2bfloat16(c[nt][2*half+0]);
            stage[(col+1)*SP + rloc] = __float2bfloat16(c[nt][2*half+1]);
        }
    }
    __syncthreads();
    for (int idx = tid; idx < 32*64; idx += 256) {
        int o = idx >> 6, r2 = (idx & 63) * 2;
        __nv_bfloat162 v = *(const __nv_bfloat162*)&stage[o*SP + r2];
        *(__nv_bfloat162*)&g_bias[(size_t)o * (size_t)L * (size_t)L + row0 + r2] = v;
    }
}

// ---------------- tf32 GEMM, 64x64 tile, cp.async double-buffered ----------------
// 8 warps = 2(M) x 4(N); warp tile 32x16. Optional in-kernel row-LN stats.
#define G_STAGE (64*36)
#define GEMM_SMEM (4*G_STAGE*4)   // 36864

template<bool HAS_BIAS, bool DO_GELU, bool HAS_RES, bool LN_EPI, bool COORD>
__device__ __forceinline__ void gemm_body64(
    const float* __restrict__ A, const float* __restrict__ Bw,
    const float* __restrict__ bias, const float* __restrict__ Rsrc,
    const float* __restrict__ GW, const float* __restrict__ b2v,
    const float* __restrict__ xn, const float* __restrict__ cW,
    const float* __restrict__ cb,
    float* __restrict__ Cout, int M, int N, int K)
{
    extern __shared__ float sm[];
    float* AsB = sm;                    // [2][64][36]
    float* BsB = sm + 2*G_STAGE;        // [2][64][36]
    const int tid = threadIdx.x, lane = tid & 31, warp = tid >> 5;
    const int wm = warp >> 2, wn = warp & 3;
    const int m0 = blockIdx.y * 64, n0 = blockIdx.x * 64;
    const int lr = lane >> 2, lc = lane & 3;
    const int pr = tid >> 3, pq = tid & 7;

    float c[2][2][4];
    #pragma unroll
    for (int mt = 0; mt < 2; mt++)
        #pragma unroll
        for (int nt = 0; nt < 2; nt++)
            #pragma unroll
            for (int r = 0; r < 4; r++) c[mt][nt][r] = 0.f;

    // row-stat accumulators (4 threads per row: row = tid>>2, seg = tid&3)
    float stat_s = 0.f, stat_q = 0.f;
    const int srow = tid >> 2, sseg = tid & 3;

    const int NK = K >> 5;
    {
        #pragma unroll
        for (int it = 0; it < 2; it++) {
            int r = pr + 32*it;
            cp16(&AsB[r*36 + 4*pq], &A [(size_t)(m0 + r)*K + 4*pq]);
            cp16(&BsB[r*36 + 4*pq], &Bw[(size_t)(n0 + r)*K + 4*pq]);
        }
        CP_COMMIT();
    }

    for (int ks = 0; ks < NK; ks++) {
        if (ks + 1 < NK) {
            float* as = AsB + ((ks+1)&1)*G_STAGE;
            float* bs = BsB + ((ks+1)&1)*G_STAGE;
            int k0 = (ks+1) << 5;
            #pragma unroll
            for (int it = 0; it < 2; it++) {
                int r = pr + 32*it;
                cp16(&as[r*36 + 4*pq], &A [(size_t)(m0 + r)*K + k0 + 4*pq]);
                cp16(&bs[r*36 + 4*pq], &Bw[(size_t)(n0 + r)*K + k0 + 4*pq]);
            }
            CP_COMMIT();
            CP_WAIT(1);
        } else {
            CP_WAIT(0);
        }
        __syncthreads();
        const float* as = AsB + (ks&1)*G_STAGE;
        const float* bs = BsB + (ks&1)*G_STAGE;

        if (LN_EPI) {   // accumulate row sums on the idle FMA pipe
            const float* ap = as + srow*36 + sseg*8;
            #pragma unroll
            for (int u = 0; u < 8; u++) { float v = ap[u]; stat_s += v; stat_q += v*v; }
        }

        #pragma unroll
        for (int kk = 0; kk < 32; kk += 8) {
            uint32_t a[2][4], b[2][2];
            #pragma unroll
            for (int mt = 0; mt < 2; mt++) {
                int row = 32*wm + 16*mt + lr;
                a[mt][0] = __float_as_uint(as[(row  )*36 + kk+lc]);
                a[mt][1] = __float_as_uint(as[(row+8)*36 + kk+lc]);
                a[mt][2] = __float_as_uint(as[(row  )*36 + kk+4+lc]);
                a[mt][3] = __float_as_uint(as[(row+8)*36 + kk+4+lc]);
            }
            #pragma unroll
            for (int nt = 0; nt < 2; nt++) {
                int col = 16*wn + 8*nt + lr;
                b[nt][0] = __float_as_uint(bs[col*36 + kk+lc]);
                b[nt][1] = __float_as_uint(bs[col*36 + kk+4+lc]);
            }
            #pragma unroll
            for (int mt = 0; mt < 2; mt++)
                #pragma unroll
                for (int nt = 0; nt < 2; nt++)
                    mma_tf32(c[mt][nt], a[mt][0], a[mt][1], a[mt][2], a[mt][3],
                             b[nt][0], b[nt][1]);
        }
        __syncthreads();
    }

    float* rs_s = sm;        // alias A smem (free after mainloop)
    float* m2_s = sm + 64;
    if (LN_EPI) {
        stat_s += __shfl_xor_sync(0xffffffffu, stat_s, 1);
        stat_s += __shfl_xor_sync(0xffffffffu, stat_s, 2);
        stat_q += __shfl_xor_sync(0xffffffffu, stat_q, 1);
        stat_q += __shfl_xor_sync(0xffffffffu, stat_q, 2);
        if (sseg == 0) {
            float mu = stat_s * (1.0f/256.0f);
            float var = stat_q * (1.0f/256.0f) - mu*mu;
            float rsv = rsqrtf(var + 1e-5f);
            rs_s[srow] = rsv;
            m2_s[srow] = -mu * rsv;
        }
        __syncthreads();
    }

    #pragma unroll
    for (int mt = 0; mt < 2; mt++) {
        #pragma unroll
        for (int half = 0; half < 2; half++) {
            int rloc = 32*wm + 16*mt + lr + 8*half;
            int row = m0 + rloc;
            float rs = 0.f, m2 = 0.f, cx0 = 0.f, cx1 = 0.f, cx2 = 0.f;
            if (LN_EPI) { rs = rs_s[rloc]; m2 = m2_s[rloc]; }
            if (COORD) {
                float cin = g_scal[2];
                cx0 = xn[row*3+0]*cin; cx1 = xn[row*3+1]*cin; cx2 = xn[row*3+2]*cin;
            }
            #pragma unroll
            for (int nt = 0; nt < 2; nt++) {
                int col = n0 + 16*wn + 8*nt + 2*lc;
                float v0 = c[mt][nt][2*half+0];
                float v1 = c[mt][nt][2*half+1];
                if (LN_EPI) {
                    v0 = rs*v0 + m2*GW[col]   + b2v[col];
                    v1 = rs*v1 + m2*GW[col+1] + b2v[col+1];
                }
                if (HAS_BIAS) { v0 += bias[col]; v1 += bias[col+1]; }
                if (COORD) {
                    v0 += cb[col]   + cx0*cW[col*3+0]     + cx1*cW[col*3+1]     + cx2*cW[col*3+2];
                    v1 += cb[col+1] + cx0*cW[(col+1)*3+0] + cx1*cW[(col+1)*3+1] + cx2*cW[(col+1)*3+2];
                }
                if (DO_GELU)  { v0 = gelu_exact(v0); v1 = gelu_exact(v1); }
                if (HAS_RES)  { v0 += Rsrc[(size_t)row*N + col]; v1 += Rsrc[(size_t)row*N + col + 1]; }
                *(float2*)&Cout[(size_t)row*N + col] = make_float2(v0, v1);
            }
        }
    }
}

template<bool HB, bool HG, bool HR>
__global__ void __launch_bounds__(256, 2) k_gemm_tc(
    const float* __restrict__ A, const float* __restrict__ Bw,
    const float* __restrict__ bias, const float* __restrict__ Rsrc,
    float* __restrict__ Cout, int M, int N, int K)
{
    gemm_body64<HB,HG,HR,false,false>(A, Bw, bias, Rsrc,
        nullptr, nullptr, nullptr, nullptr, nullptr, Cout, M, N, K);
}

__global__ void __launch_bounds__(256, 2) k_single_tc(
    const float* __restrict__ A, const float* __restrict__ Bw,
    const float* __restrict__ bias,
    const float* __restrict__ xn, const float* __restrict__ cW,
    const float* __restrict__ cb, float* __restrict__ Cout)
{
    gemm_body64<true,false,false,false,true>(A, Bw, bias, nullptr,
        nullptr, nullptr, xn, cW, cb, Cout, L, C, C);
}

__global__ void __launch_bounds__(256, 2) k_qkv_f(
    int b, float* __restrict__ q, float* __restrict__ k, float* __restrict__ v)
{
    int z = blockIdx.z;
    const float* Bw = g_wqkv + ((size_t)b*768 + z*256)*C;
    const float* GW = &g_gwA[b][z*256];
    const float* b2 = &g_b2A[b][z*256];
    float* Cout = (z == 0) ? q : (z == 1) ? k : v;
    gemm_body64<false,false,false,true,false>(g_h, Bw, nullptr, nullptr,
        GW, b2, nullptr, nullptr, nullptr, Cout, L, C, C);
}

__global__ void __launch_bounds__(256, 2) k_ffn1_f(int b, float* __restrict__ mid)
{
    const float* Bw = g_wf1 + (size_t)b*1024*C;
    const float* GW = &g_gwA[b][768];
    const float* b2 = &g_b2A[b][768];
    gemm_body64<false,true,false,true,false>(g_h, Bw, nullptr, nullptr,
        GW, b2, nullptr, nullptr, nullptr, mid, L, 4*C, C);
}

// ---------------- tensor-core flash attention ----------------
// tf32 QK^T (cp.async double-buffered K), bf16 PV with P fed straight from
// softmax registers, V register-prefetch.
#define KSTG (128*36)
#define VSTG (32*136)
#define ATTN_SMEM (18432 + 2*18432 + 2*8704)   // Qs + Ks[2] + Vt[2] = 72704
__global__ void __launch_bounds__(256) k_attn_tc(int blk)
{
    extern __shared__ char smc[];
    float* Qs = (float*)smc;                                  // [128][36]
    float* KsB = (float*)(smc + 18432);                       // [2][128][36]
    __nv_bfloat16* VtB = (__nv_bfloat16*)(smc + 18432 + 2*18432); // [2][32][136]

    const int h  = blockIdx.y;
    const int i0 = blockIdx.x * 128;
    const int tid = threadIdx.x, lane = tid & 31, warp = tid >> 5;
    const int lr = lane >> 2, lc = lane & 3;
    const float scale = 0.17677669529663687f;

    #pragma unroll
    for (int it = 0; it < 4; it++) {
        int idx = tid + 256*it;
        int r = idx >> 3, q = idx & 7;
        float4 v = *(const float4*)&g_q[(size_t)(i0 + r)*C + h*32 + 4*q];
        float* dst = &Qs[r*36 + 4*q];
        dst[0]=v.x*scale; dst[1]=v.y*scale; dst[2]=v.z*scale; dst[3]=v.w*scale;
    }

    float4 vv[4];
    {
        #pragma unroll
        for (int it = 0; it < 4; it++) {
            int idx = tid + 256*it;
            int r = idx >> 3, q = idx & 7;
            vv[it] = *(const float4*)&g_v[(size_t)(0 + r)*C + h*32 + 4*q];
            cp16(&KsB[r*36 + 4*q], &g_k[(size_t)(0 + r)*C + h*32 + 4*q]);
        }
        CP_COMMIT();
        #pragma unroll
        for (int it = 0; it < 4; it++) {
            int idx = tid + 256*it;
            int r = idx >> 3, q = idx & 7;
            VtB[(4*q+0)*136 + r] = __float2bfloat16(vv[it].x);
            VtB[(4*q+1)*136 + r] = __float2bfloat16(vv[it].y);
            VtB[(4*q+2)*136 + r] = __float2bfloat16(vv[it].z);
            VtB[(4*q+3)*136 + r] = __float2bfloat16(vv[it].w);
        }
        CP_WAIT(0);
        __syncthreads();
    }

    float m_run[2] = {-1e30f, -1e30f};
    float l_run[2] = {0.f, 0.f};
    float o[4][4];
    #pragma unroll
    for (int nt = 0; nt < 4; nt++)
        #pragma unroll
        for (int r = 0; r < 4; r++) o[nt][r] = 0.f;

    const __nv_bfloat16* bias_w = g_bias + ((size_t)blk*H + h)*(size_t)L*L
                                         + (size_t)(i0 + 16*warp)*L;
    const int arow = 16*warp + lr;

    for (int jt = 0; jt < 16; jt++) {
        const int cur = jt & 1, nxt = cur ^ 1;
        const float* Ks = KsB + cur*KSTG;
        const __nv_bfloat16* Vt = VtB + cur*VSTG;
        const bool more = (jt + 1 < 16);

        if (more) {
            int j0n = (jt + 1) * 128;
            float* ks = KsB + nxt*KSTG;
            #pragma unroll
            for (int it = 0; it < 4; it++) {
                int idx = tid + 256*it;
                int r = idx >> 3, q = idx & 7;
                vv[it] = *(const float4*)&g_v[(size_t)(j0n + r)*C + h*32 + 4*q];
                cp16(&ks[r*36 + 4*q], &g_k[(size_t)(j0n + r)*C + h*32 + 4*q]);
            }
            CP_COMMIT();
        }

        float s[16][4];
        #pragma unroll
        for (int nt = 0; nt < 16; nt++)
            #pragma unroll
            for (int r = 0; r < 4; r++) s[nt][r] = 0.f;
        #pragma unroll
        for (int kk = 0; kk < 32; kk += 8) {
            uint32_t a0 = __float_as_uint(Qs[(arow  )*36 + kk+lc]);
            uint32_t a1 = __float_as_uint(Qs[(arow+8)*36 + kk+lc]);
            uint32_t a2 = __float_as_uint(Qs[(arow  )*36 + kk+4+lc]);
            uint32_t a3 = __float_as_uint(Qs[(arow+8)*36 + kk+4+lc]);
            #pragma unroll
            for (int nt = 0; nt < 16; nt++) {
                uint32_t b0 = __float_as_uint(Ks[(8*nt+lr)*36 + kk+lc]);
                uint32_t b1 = __float_as_uint(Ks[(8*nt+lr)*36 + kk+4+lc]);
                mma_tf32(s[nt], a0, a1, a2, a3, b0, b1);
            }
        }
        const int j0 = jt * 128;
        #pragma unroll
        for (int nt = 0; nt < 16; nt++) {
            int j = j0 + 8*nt + 2*lc;
            __nv_bfloat162 blo = *(const __nv_bfloat162*)&bias_w[(size_t)lr*L + j];
            __nv_bfloat162 bhi = *(const __nv_bfloat162*)&bias_w[(size_t)(lr+8)*L + j];
            s[nt][0] += __bfloat162float(blo.x); s[nt][1] += __bfloat162float(blo.y);
            s[nt][2] += __bfloat162float(bhi.x); s[nt][3] += __bfloat162float(bhi.y);
        }

        float mx0 = -1e30f, mx1 = -1e30f;
        #pragma unroll
        for (int nt = 0; nt < 16; nt++) {
            mx0 = fmaxf(mx0, fmaxf(s[nt][0], s[nt][1]));
            mx1 = fmaxf(mx1, fmaxf(s[nt][2], s[nt][3]));
        }
        mx0 = fmaxf(mx0, __shfl_xor_sync(0xffffffffu, mx0, 1));
        mx0 = fmaxf(mx0, __shfl_xor_sync(0xffffffffu, mx0, 2));
        mx1 = fmaxf(mx1, __shfl_xor_sync(0xffffffffu, mx1, 1));
        mx1 = fmaxf(mx1, __shfl_xor_sync(0xffffffffu, mx1, 2));
        float mn0 = fmaxf(m_run[0], mx0), mn1 = fmaxf(m_run[1], mx1);
        float cf0 = __expf(m_run[0] - mn0), cf1 = __expf(m_run[1] - mn1);
        float rs0 = 0.f, rs1 = 0.f;
        #pragma unroll
        for (int nt = 0; nt < 16; nt++) {
            s[nt][0] = __expf(s[nt][0] - mn0);
            s[nt][1] = __expf(s[nt][1] - mn0);
            s[nt][2] = __expf(s[nt][2] - mn1);
            s[nt][3] = __expf(s[nt][3] - mn1);
            rs0 += s[nt][0] + s[nt][1];
            rs1 += s[nt][2] + s[nt][3];
        }
        rs0 += __shfl_xor_sync(0xffffffffu, rs0, 1);
        rs0 += __shfl_xor_sync(0xffffffffu, rs0, 2);
        rs1 += __shfl_xor_sync(0xffffffffu, rs1, 1);
        rs1 += __shfl_xor_sync(0xffffffffu, rs1, 2);
        l_run[0] = l_run[0]*cf0 + rs0;  m_run[0] = mn0;
        l_run[1] = l_run[1]*cf1 + rs1;  m_run[1] = mn1;
        #pragma unroll
        for (int nt = 0; nt < 4; nt++) {
            o[nt][0] *= cf0; o[nt][1] *= cf0;
            o[nt][2] *= cf1; o[nt][3] *= cf1;
        }

        #pragma unroll
        for (int c2 = 0; c2 < 8; c2++) {
            uint32_t a0 = pack_bf16x2(s[2*c2  ][0], s[2*c2  ][1]);
            uint32_t a1 = pack_bf16x2(s[2*c2  ][2], s[2*c2  ][3]);
            uint32_t a2 = pack_bf16x2(s[2*c2+1][0], s[2*c2+1][1]);
            uint32_t a3 = pack_bf16x2(s[2*c2+1][2], s[2*c2+1][3]);
            #pragma unroll
            for (int nt = 0; nt < 4; nt++) {
                uint32_t b0 = *(const uint32_t*)&Vt[(8*nt+lr)*136 + 16*c2 + 2*lc];
                uint32_t b1 = *(const uint32_t*)&Vt[(8*nt+lr)*136 + 16*c2 + 8 + 2*lc];
                mma_bf16(o[nt], a0, a1, a2, a3, b0, b1);
            }
        }

        if (more) {
            __nv_bfloat16* vt = VtB + nxt*VSTG;
            #pragma unroll
            for (int it = 0; it < 4; it++) {
                int idx = tid + 256*it;
                int r = idx >> 3, q = idx & 7;
                vt[(4*q+0)*136 + r] = __float2bfloat16(vv[it].x);
                vt[(4*q+1)*136 + r] = __float2bfloat16(vv[it].y);
                vt[(4*q+2)*136 + r] = __float2bfloat16(vv[it].z);
                vt[(4*q+3)*136 + r] = __float2bfloat16(vv[it].w);
            }
            CP_WAIT(0);
        }
        __syncthreads();
    }

    float inv0 = 1.0f / l_run[0], inv1 = 1.0f / l_run[1];
    #pragma unroll
    for (int nt = 0; nt < 4; nt++) {
        int d = h*32 + 8*nt + 2*lc;
        size_t r0 = (size_t)(i0 + arow) * C + d;
        size_t r1 = (size_t)(i0 + arow + 8) * C + d;
        *(float2*)&g_ao[r0] = make_float2(o[nt][0]*inv0, o[nt][1]*inv0);
        *(float2*)&g_ao[r1] = make_float2(o[nt][2]*inv1, o[nt][3]*inv1);
    }
}

// ---------------- final ----------------
__global__ void __launch_bounds__(256) k_final(const float* __restrict__ xn,
                                               const float* __restrict__ oW,
                                               const float* __restrict__ ob,
                                               float* __restrict__ out)
{
    const int warp = threadIdx.x >> 5, lane = threadIdx.x & 31;
    const int row = blockIdx.x * 8 + warp;
    const float* hr = g_h + (size_t)row * C;
    #pragma unroll
    for (int c = 0; c < 3; c++) {
        float s = 0.f;
        for (int k = lane; k < C; k += 32) s += hr[k] * oW[c*C + k];
        #pragma unroll
        for (int off = 16; off; off >>= 1) s += __shfl_xor_sync(0xffffffffu, s, off);
        if (lane == 0)
            out[row*3 + c] = g_scal[0] * xn[row*3 + c] + g_scal[1] * (s + ob[c]);
    }
}

// ---------------- launcher ----------------
extern "C" void kernel_launch(void* const* d_in, const int* in_sizes, int n_in,
                              void* d_out, int out_size)
{
    const float* x_noisy  = (const float*)d_in[0];
    const float* sigma    = (const float*)d_in[1];
    const float* single   = (const float*)d_in[2];
    const float* pair     = (const float*)d_in[3];
    const float* coord_W  = (const float*)d_in[4];
    const float* coord_b  = (const float*)d_in[5];
    const float* single_W = (const float*)d_in[6];
    const float* single_b = (const float*)d_in[7];
    const float* tmlp_W1  = (const float*)d_in[8];
    const float* tmlp_b1  = (const float*)d_in[9];
    const float* tmlp_W2  = (const float*)d_in[10];
    const float* tmlp_b2  = (const float*)d_in[11];
    const float* ada1_g   = (const float*)d_in[12];
    const float* ada1_b   = (const float*)d_in[13];
    const float* ada1_pW  = (const float*)d_in[14];
    const float* ada1_pb  = (const float*)d_in[15];
    const float* qW       = (const float*)d_in[16];
    const float* kW       = (const float*)d_in[17];
    const float* vW       = (const float*)d_in[18];
    const float* pairW    = (const float*)d_in[19];
    const float* outW     = (const float*)d_in[20];
    const float* outb     = (const float*)d_in[21];
    const float* ada2_g   = (const float*)d_in[22];
    const float* ada2_b   = (const float*)d_in[23];
    const float* ada2_pW  = (const float*)d_in[24];
    const float* ada2_pb  = (const float*)d_in[25];
    const float* ffn_W1   = (const float*)d_in[26];
    const float* ffn_b1   = (const float*)d_in[27];
    const float* ffn_W2   = (const float*)d_in[28];
    const float* ffn_b2   = (const float*)d_in[29];
    const float* out_W    = (const float*)d_in[30];
    const float* out_b    = (const float*)d_in[31];
    float* out = (float*)d_out;

    float *p_h, *p_q, *p_k, *p_v, *p_ao, *p_mid;
    cudaGetSymbolAddress((void**)&p_h,  g_h);
    cudaGetSymbolAddress((void**)&p_q,  g_q);
    cudaGetSymbolAddress((void**)&p_k,  g_k);
    cudaGetSymbolAddress((void**)&p_v,  g_v);
    cudaGetSymbolAddress((void**)&p_ao, g_ao);
    cudaGetSymbolAddress((void**)&p_mid, g_mid);

    static int attr_set = 0;
    if (!attr_set) {
        cudaFuncSetAttribute(k_attn_tc, cudaFuncAttributeMaxDynamicSharedMemorySize, ATTN_SMEM);
        cudaFuncSetAttribute(k_gemm_tc<true,false,true >, cudaFuncAttributeMaxDynamicSharedMemorySize, GEMM_SMEM);
        cudaFuncSetAttribute(k_single_tc, cudaFuncAttributeMaxDynamicSharedMemorySize, GEMM_SMEM);
        cudaFuncSetAttribute(k_qkv_f,  cudaFuncAttributeMaxDynamicSharedMemorySize, GEMM_SMEM);
        cudaFuncSetAttribute(k_ffn1_f, cudaFuncAttributeMaxDynamicSharedMemorySize, GEMM_SMEM);
        attr_set = 1;
    }

    k_bias_tc<<<(L*L)/128, 256>>>(pair, pairW);
    k_prep<<<1, 256>>>(sigma, tmlp_W1, tmlp_b1, tmlp_W2, tmlp_b2,
                       ada1_pW, ada1_pb, ada2_pW, ada2_pb,
                       ada1_g, ada1_b, ada2_g, ada2_b);
    k_foldW<<<NB*1792/8, 256>>>(qW, kW, vW, ffn_W1, ffn_b1);
    k_single_tc<<<dim3(C/64, L/64), 256, GEMM_SMEM>>>(single, single_W, single_b,
                                                      x_noisy, coord_W, coord_b, p_h);

    for (int b = 0; b < NB; b++) {
        k_qkv_f<<<dim3(C/64, L/64, 3), 256, GEMM_SMEM>>>(b, p_q, p_k, p_v);
        k_attn_tc<<<dim3(L/128, H), 256, ATTN_SMEM>>>(b);
        k_gemm_tc<true,false,true><<<dim3(C/64, L/64), 256, GEMM_SMEM>>>(
            p_ao, outW + (size_t)b*C*C, outb + b*C, p_h, p_h, L, C, C);
        k_ffn1_f<<<dim3(4*C/64, L/64), 256, GEMM_SMEM>>>(b, p_mid);
        k_gemm_tc<true,false,true><<<dim3(C/64, L/64), 256, GEMM_SMEM>>>(
            p_mid, ffn_W2 + (size_t)b*4*C*C, ffn_b2 + b*C, p_h, p_h, L, C, 4*C);
    }
    k_final<<<L/8, 256>>>(x_noisy, out_W, out_b, out);
}

// round 12
// speedup vs baseline: 1.3345x; 1.0048x over previous
#include <cuda_runtime.h>
#include <cuda_bf16.h>
#include <math.h>
#include <stdint.h>

#define L 2048
#define C 256
#define NB 4
#define H 8
#define D 32
#define SD 16.0f

// ---------------- scratch (device globals; no allocation allowed) ----------------
__device__ float g_h [L*C];
__device__ float g_q [L*C];
__device__ float g_k [L*C];
__device__ float g_v [L*C];
__device__ float g_ao[L*C];
__device__ float g_mid[L*4*C];
__device__ __nv_bfloat16 g_bias[(size_t)NB*H*L*L];   // 256 MB
__device__ float g_scal[4];   // c_skip, c_out, c_in
// fused-LN precomputes
__device__ float g_G1[NB][C], g_B1[NB][C], g_G2[NB][C], g_B2[NB][C];
__device__ float g_wqkv[(size_t)NB*3*C*C];   // G1-scaled qkv weights
__device__ float g_wf1 [(size_t)NB*4*C*C];   // G2-scaled ffn1 weights
__device__ float g_gwA [NB][3*C + 4*C];      // GW vectors (qkv | ffn1)
__device__ float g_b2A [NB][3*C + 4*C];      // b2 vectors (qkv | ffn1, ffn_b1 folded)

__device__ __forceinline__ float gelu_exact(float x) {
    return 0.5f * x * (1.0f + erff(x * 0.70710678118654752f));
}

__device__ __forceinline__ void mma_tf32(float c[4],
    uint32_t a0, uint32_t a1, uint32_t a2, uint32_t a3,
    uint32_t b0, uint32_t b1)
{
    asm volatile(
        "mma.sync.aligned.m16n8k8.row.col.f32.tf32.tf32.f32 "
        "{%0,%1,%2,%3}, {%4,%5,%6,%7}, {%8,%9}, {%0,%1,%2,%3};"
        : "+f"(c[0]), "+f"(c[1]), "+f"(c[2]), "+f"(c[3])
        : "r"(a0), "r"(a1), "r"(a2), "r"(a3), "r"(b0), "r"(b1));
}

__device__ __forceinline__ void mma_bf16(float c[4],
    uint32_t a0, uint32_t a1, uint32_t a2, uint32_t a3,
    uint32_t b0, uint32_t b1)
{
    asm volatile(
        "mma.sync.aligned.m16n8k16.row.col.f32.bf16.bf16.f32 "
        "{%0,%1,%2,%3}, {%4,%5,%6,%7}, {%8,%9}, {%0,%1,%2,%3};"
        : "+f"(c[0]), "+f"(c[1]), "+f"(c[2]), "+f"(c[3])
        : "r"(a0), "r"(a1), "r"(a2), "r"(a3), "r"(b0), "r"(b1));
}

__device__ __forceinline__ uint32_t pack_bf16x2(float lo, float hi) {
    __nv_bfloat162 t = __floats2bfloat162_rn(lo, hi);
    return *(uint32_t*)&t;
}

__device__ __forceinline__ void cp16(float* smem_dst, const float* gsrc) {
    uint32_t s = (uint32_t)__cvta_generic_to_shared(smem_dst);
    asm volatile("cp.async.cg.shared.global [%0], [%1], 16;" :: "r"(s), "l"(gsrc));
}
#define CP_COMMIT() asm volatile("cp.async.commit_group;")
#define CP_WAIT(n)  asm volatile("cp.async.wait_group %0;" :: "n"(n))

// ---------------- K0: time embedding, time MLP, adaLN cond proj, fold1 ----------------
__global__ void __launch_bounds__(256) k_prep(
    const float* __restrict__ sigma,
    const float* __restrict__ tW1, const float* __restrict__ tb1,
    const float* __restrict__ tW2, const float* __restrict__ tb2,
    const float* __restrict__ a1pW, const float* __restrict__ a1pb,
    const float* __restrict__ a2pW, const float* __restrict__ a2pb,
    const float* __restrict__ a1g, const float* __restrict__ a1b,
    const float* __restrict__ a2g, const float* __restrict__ a2b)
{
    __shared__ float temb[C];
    __shared__ float hid[4*C];
    __shared__ float tcs[C];
    __shared__ float ss1[NB][2*C];
    __shared__ float ss2[NB][2*C];
    const int t = threadIdx.x;
    const float sg = sigma[0];
    if (t == 0) {
        float s2 = sg*sg + SD*SD;
        g_scal[0] = SD*SD / s2;
        g_scal[1] = sg*SD*rsqrtf(s2);
        g_scal[2] = rsqrtf(s2);
    }
    const float c_noise = 0.25f * logf(sg + 1e-8f);
    if (t < 128) {
        float fr = expf(-logf(10000.0f) * (float)t / 128.0f);
        float a = c_noise * fr;
        temb[t]       = cosf(a);
        temb[t + 128] = sinf(a);
    }
    __syncthreads();
    for (int r = t; r < 4*C; r += 256) {
        float acc = tb1[r];
        const float* w = tW1 + (size_t)r * C;
        for (int k2 = 0; k2 < C; k2++) acc += temb[k2] * w[k2];
        hid[r] = gelu_exact(acc);
    }
    __syncthreads();
    for (int r = t; r < C; r += 256) {
        float acc = tb2[r];
        const float* w = tW2 + (size_t)r * 4*C;
        for (int k2 = 0; k2 < 4*C; k2++) acc += hid[k2] * w[k2];
        tcs[r] = acc;
    }
    __syncthreads();
    for (int idx = t; idx < NB*2*C; idx += 256) {
        int b = idx / (2*C), r = idx % (2*C);
        float acc1 = a1pb[b*2*C + r];
        const float* w1 = a1pW + ((size_t)b*2*C + r) * C;
        float acc2 = a2pb[b*2*C + r];
        const float* w2 = a2pW + ((size_t)b*2*C + r) * C;
        for (int k2 = 0; k2 < C; k2++) { acc1 += tcs[k2]*w1[k2]; acc2 += tcs[k2]*w2[k2]; }
        ss1[b][r] = acc1;
        ss2[b][r] = acc2;
    }
    __syncthreads();
    for (int idx = t; idx < NB*C; idx += 256) {
        int b = idx >> 8, c = idx & 255;
        float s1 = 1.0f + ss1[b][c];
        g_G1[b][c] = a1g[b*C + c] * s1;
        g_B1[b][c] = a1b[b*C + c] * s1 + ss1[b][C + c];
        float s2 = 1.0f + ss2[b][c];
        g_G2[b][c] = a2g[b*C + c] * s2;
        g_B2[b][c] = a2b[b*C + c] * s2 + ss2[b][C + c];
    }
}

// ---------------- foldW ----------------
__global__ void __launch_bounds__(256) k_foldW(
    const float* __restrict__ qW, const float* __restrict__ kW,
    const float* __restrict__ vW, const float* __restrict__ f1W,
    const float* __restrict__ f1b)
{
    const int lane = threadIdx.x & 31, warp = threadIdx.x >> 5;
    int gidx = blockIdx.x * 8 + warp;
    int b = gidx / 1792, n = gidx % 1792;
    const float *src, *G, *Bc;
    float* dst;
    float extra = 0.f;
    if (n < 768) {
        int w = n >> 8, nn = n & 255;
        src = (w == 0 ? qW : w == 1 ? kW : vW) + ((size_t)b*C + nn)*C;
        dst = g_wqkv + ((size_t)b*768 + n)*C;
        G = g_G1[b]; Bc = g_B1[b];
    } else {
        int nn = n - 768;
        src = f1W + ((size_t)b*4*C + nn)*C;
        dst = g_wf1 + ((size_t)b*1024 + nn)*C;
        G = g_G2[b]; Bc = g_B2[b];
        extra = f1b[b*4*C + nn];
    }
    float gw = 0.f, b2 = 0.f;
    for (int c = lane; c < C; c += 32) {
        float w = src[c];
        float wg = w * G[c];
        dst[c] = wg;
        gw += wg;
        b2 += w * Bc[c];
    }
    #pragma unroll
    for (int off = 16; off; off >>= 1) {
        gw += __shfl_xor_sync(0xffffffffu, gw, off);
        b2 += __shfl_xor_sync(0xffffffffu, b2, off);
    }
    if (lane == 0) { g_gwA[b][n] = gw; g_b2A[b][n] = b2 + extra; }
}

// ---------------- pair bias via tf32 mma ----------------
__global__ void __launch_bounds__(256) k_bias_tc(const float* __restrict__ pair,
                                                 const float* __restrict__ pW)
{
    __shared__ float As[128][68];
    __shared__ float Ws[32][68];
    const int tid = threadIdx.x, lane = tid & 31, warp = tid >> 5;
    const int lr = lane >> 2, lc = lane & 3;
    const size_t row0 = (size_t)blockIdx.x * 128;

    #pragma unroll
    for (int it = 0; it < 8; it++) {
        int idx = tid + 256*it;
        int r = idx >> 4, q = idx & 15;
        *(float4*)&As[r][4*q] = *(const float4*)&pair[(row0 + r) * 64 + 4*q];
    }
    #pragma unroll
    for (int it = 0; it < 2; it++) {
        int idx = tid + 256*it;
        int r = idx >> 4, q = idx & 15;
        *(float4*)&Ws[r][4*q] = *(const float4*)&pW[r * 64 + 4*q];
    }
    __syncthreads();

    float c[4][4] = {};
    const int arow = 16*warp + lr;
    #pragma unroll
    for (int kk = 0; kk < 64; kk += 8) {
        uint32_t a0 = __float_as_uint(As[arow  ][kk+lc]);
        uint32_t a1 = __float_as_uint(As[arow+8][kk+lc]);
        uint32_t a2 = __float_as_uint(As[arow  ][kk+4+lc]);
        uint32_t a3 = __float_as_uint(As[arow+8][kk+4+lc]);
        #pragma unroll
        for (int nt = 0; nt < 4; nt++) {
            uint32_t b0 = __float_as_uint(Ws[8*nt+lr][kk+lc]);
            uint32_t b1 = __float_as_uint(Ws[8*nt+lr][kk+4+lc]);
            mma_tf32(c[nt], a0, a1, a2, a3, b0, b1);
        }
    }
    __syncthreads();

    __nv_bfloat16* stage = (__nv_bfloat16*)&As[0][0];
    const int SP = 132;
    #pragma unroll
    for (int nt = 0; nt < 4; nt++) {
        #pragma unroll
        for (int half = 0; half < 2; half++) {
            int rloc = 16*warp + lr + 8*half;
            int col = 8*nt + 2*lc;
            stage[(col  )*SP + rloc] = __float2bfloat16(c[nt][2*half+0]);
            stage[(col+1)*SP + rloc] = __float2bfloat16(c[nt][2*half+1]);
        }
    }
    __syncthreads();
    for (int idx = tid; idx < 32*64; idx += 256) {
        int o = idx >> 6, r2 = (idx & 63) * 2;
        __nv_bfloat162 v = *(const __nv_bfloat162*)&stage[o*SP + r2];
        *(__nv_bfloat162*)&g_bias[(size_t)o * (size_t)L * (size_t)L + row0 + r2] = v;
    }
}

// ---------------- tf32 GEMM, 64x64 tile, cp.async double-buffered ----------------
// 8 warps = 2(M) x 4(N); warp tile 32x16. Optional in-kernel row-LN stats.
#define G_STAGE (64*36)
#define GEMM_SMEM (4*G_STAGE*4)   // 36864

template<bool HAS_BIAS, bool DO_GELU, bool HAS_RES, bool LN_EPI, bool COORD>
__device__ __forceinline__ void gemm_body64(
    const float* __restrict__ A, const float* __restrict__ Bw,
    const float* __restrict__ bias, const float* __restrict__ Rsrc,
    const float* __restrict__ GW, const float* __restrict__ b2v,
    const float* __restrict__ xn, const float* __restrict__ cW,
    const float* __restrict__ cb,
    float* __restrict__ Cout, int M, int N, int K)
{
    extern __shared__ float sm[];
    float* AsB = sm;                    // [2][64][36]
    float* BsB = sm + 2*G_STAGE;        // [2][64][36]
    const int tid = threadIdx.x, lane = tid & 31, warp = tid >> 5;
    const int wm = warp >> 2, wn = warp & 3;
    const int m0 = blockIdx.y * 64, n0 = blockIdx.x * 64;
    const int lr = lane >> 2, lc = lane & 3;
    const int pr = tid >> 3, pq = tid & 7;

    float c[2][2][4];
    #pragma unroll
    for (int mt = 0; mt < 2; mt++)
        #pragma unroll
        for (int nt = 0; nt < 2; nt++)
            #pragma unroll
            for (int r = 0; r < 4; r++) c[mt][nt][r] = 0.f;

    // row-stat accumulators (4 threads per row: row = tid>>2, seg = tid&3)
    float stat_s = 0.f, stat_q = 0.f;
    const int srow = tid >> 2, sseg = tid & 3;

    const int NK = K >> 5;
    {
        #pragma unroll
        for (int it = 0; it < 2; it++) {
            int r = pr + 32*it;
            cp16(&AsB[r*36 + 4*pq], &A [(size_t)(m0 + r)*K + 4*pq]);
            cp16(&BsB[r*36 + 4*pq], &Bw[(size_t)(n0 + r)*K + 4*pq]);
        }
        CP_COMMIT();
    }

    for (int ks = 0; ks < NK; ks++) {
        if (ks + 1 < NK) {
            float* as = AsB + ((ks+1)&1)*G_STAGE;
            float* bs = BsB + ((ks+1)&1)*G_STAGE;
            int k0 = (ks+1) << 5;
            #pragma unroll
            for (int it = 0; it < 2; it++) {
                int r = pr + 32*it;
                cp16(&as[r*36 + 4*pq], &A [(size_t)(m0 + r)*K + k0 + 4*pq]);
                cp16(&bs[r*36 + 4*pq], &Bw[(size_t)(n0 + r)*K + k0 + 4*pq]);
            }
            CP_COMMIT();
            CP_WAIT(1);
        } else {
            CP_WAIT(0);
        }
        __syncthreads();
        const float* as = AsB + (ks&1)*G_STAGE;
        const float* bs = BsB + (ks&1)*G_STAGE;

        if (LN_EPI) {   // accumulate row sums on the idle FMA pipe
            const float* ap = as + srow*36 + sseg*8;
            #pragma unroll
            for (int u = 0; u < 8; u++) { float v = ap[u]; stat_s += v; stat_q += v*v; }
        }

        #pragma unroll
        for (int kk = 0; kk < 32; kk += 8) {
            uint32_t a[2][4], b[2][2];
            #pragma unroll
            for (int mt = 0; mt < 2; mt++) {
                int row = 32*wm + 16*mt + lr;
                a[mt][0] = __float_as_uint(as[(row  )*36 + kk+lc]);
                a[mt][1] = __float_as_uint(as[(row+8)*36 + kk+lc]);
                a[mt][2] = __float_as_uint(as[(row  )*36 + kk+4+lc]);
                a[mt][3] = __float_as_uint(as[(row+8)*36 + kk+4+lc]);
            }
            #pragma unroll
            for (int nt = 0; nt < 2; nt++) {
                int col = 16*wn + 8*nt + lr;
                b[nt][0] = __float_as_uint(bs[col*36 + kk+lc]);
                b[nt][1] = __float_as_uint(bs[col*36 + kk+4+lc]);
            }
            #pragma unroll
            for (int mt = 0; mt < 2; mt++)
                #pragma unroll
                for (int nt = 0; nt < 2; nt++)
                    mma_tf32(c[mt][nt], a[mt][0], a[mt][1], a[mt][2], a[mt][3],
                             b[nt][0], b[nt][1]);
        }
        __syncthreads();
    }

    float* rs_s = sm;        // alias A smem (free after mainloop)
    float* m2_s = sm + 64;
    if (LN_EPI) {
        stat_s += __shfl_xor_sync(0xffffffffu, stat_s, 1);
        stat_s += __shfl_xor_sync(0xffffffffu, stat_s, 2);
        stat_q += __shfl_xor_sync(0xffffffffu, stat_q, 1);
        stat_q += __shfl_xor_sync(0xffffffffu, stat_q, 2);
        if (sseg == 0) {
            float mu = stat_s * (1.0f/256.0f);
            float var = stat_q * (1.0f/256.0f) - mu*mu;
            float rsv = rsqrtf(var + 1e-5f);
            rs_s[srow] = rsv;
            m2_s[srow] = -mu * rsv;
        }
        __syncthreads();
    }

    #pragma unroll
    for (int mt = 0; mt < 2; mt++) {
        #pragma unroll
        for (int half = 0; half < 2; half++) {
            int rloc = 32*wm + 16*mt + lr + 8*half;
            int row = m0 + rloc;
            float rs = 0.f, m2 = 0.f, cx0 = 0.f, cx1 = 0.f, cx2 = 0.f;
            if (LN_EPI) { rs = rs_s[rloc]; m2 = m2_s[rloc]; }
            if (COORD) {
                float cin = g_scal[2];
                cx0 = xn[row*3+0]*cin; cx1 = xn[row*3+1]*cin; cx2 = xn[row*3+2]*cin;
            }
            #pragma unroll
            for (int nt = 0; nt < 2; nt++) {
                int col = n0 + 16*wn + 8*nt + 2*lc;
                float v0 = c[mt][nt][2*half+0];
                float v1 = c[mt][nt][2*half+1];
                if (LN_EPI) {
                    v0 = rs*v0 + m2*GW[col]   + b2v[col];
                    v1 = rs*v1 + m2*GW[col+1] + b2v[col+1];
                }
                if (HAS_BIAS) { v0 += bias[col]; v1 += bias[col+1]; }
                if (COORD) {
                    v0 += cb[col]   + cx0*cW[col*3+0]     + cx1*cW[col*3+1]     + cx2*cW[col*3+2];
                    v1 += cb[col+1] + cx0*cW[(col+1)*3+0] + cx1*cW[(col+1)*3+1] + cx2*cW[(col+1)*3+2];
                }
                if (DO_GELU)  { v0 = gelu_exact(v0); v1 = gelu_exact(v1); }
                if (HAS_RES)  { v0 += Rsrc[(size_t)row*N + col]; v1 += Rsrc[(size_t)row*N + col + 1]; }
                *(float2*)&Cout[(size_t)row*N + col] = make_float2(v0, v1);
            }
        }
    }
}

template<bool HB, bool HG, bool HR>
__global__ void __launch_bounds__(256, 2) k_gemm_tc(
    const float* __restrict__ A, const float* __restrict__ Bw,
    const float* __restrict__ bias, const float* __restrict__ Rsrc,
    float* __restrict__ Cout, int M, int N, int K)
{
    gemm_body64<HB,HG,HR,false,false>(A, Bw, bias, Rsrc,
        nullptr, nullptr, nullptr, nullptr, nullptr, Cout, M, N, K);
}

__global__ void __launch_bounds__(256, 2) k_single_tc(
    const float* __restrict__ A, const float* __restrict__ Bw,
    const float* __restrict__ bias,
    const float* __restrict__ xn, const float* __restrict__ cW,
    const float* __restrict__ cb, float* __restrict__ Cout)
{
    gemm_body64<true,false,false,false,true>(A, Bw, bias, nullptr,
        nullptr, nullptr, xn, cW, cb, Cout, L, C, C);
}

__global__ void __launch_bounds__(256, 2) k_qkv_f(
    int b, float* __restrict__ q, float* __restrict__ k, float* __restrict__ v)
{
    int z = blockIdx.z;
    const float* Bw = g_wqkv + ((size_t)b*768 + z*256)*C;
    const float* GW = &g_gwA[b][z*256];
    const float* b2 = &g_b2A[b][z*256];
    float* Cout = (z == 0) ? q : (z == 1) ? k : v;
    gemm_body64<false,false,false,true,false>(g_h, Bw, nullptr, nullptr,
        GW, b2, nullptr, nullptr, nullptr, Cout, L, C, C);
}

__global__ void __launch_bounds__(256, 2) k_ffn1_f(int b, float* __restrict__ mid)
{
    const float* Bw = g_wf1 + (size_t)b*1024*C;
    const float* GW = &g_gwA[b][768];
    const float* b2 = &g_b2A[b][768];
    gemm_body64<false,true,false,true,false>(g_h, Bw, nullptr, nullptr,
        GW, b2, nullptr, nullptr, nullptr, mid, L, 4*C, C);
}

// ---------------- tensor-core flash attention ----------------
// tf32 QK^T (cp.async double-buffered K), bf16 PV with P fed straight from
// softmax registers, V register-prefetch.
#define KSTG (128*36)
#define VSTG (32*136)
#define ATTN_SMEM (18432 + 2*18432 + 2*8704)   // Qs + Ks[2] + Vt[2] = 72704
__global__ void __launch_bounds__(256) k_attn_tc(int blk)
{
    extern __shared__ char smc[];
    float* Qs = (float*)smc;                                  // [128][36]
    float* KsB = (float*)(smc + 18432);                       // [2][128][36]
    __nv_bfloat16* VtB = (__nv_bfloat16*)(smc + 18432 + 2*18432); // [2][32][136]

    const int h  = blockIdx.y;
    const int i0 = blockIdx.x * 128;
    const int tid = threadIdx.x, lane = tid & 31, warp = tid >> 5;
    const int lr = lane >> 2, lc = lane & 3;
    const float scale = 0.17677669529663687f;

    #pragma unroll
    for (int it = 0; it < 4; it++) {
        int idx = tid + 256*it;
        int r = idx >> 3, q = idx & 7;
        float4 v = *(const float4*)&g_q[(size_t)(i0 + r)*C + h*32 + 4*q];
        float* dst = &Qs[r*36 + 4*q];
        dst[0]=v.x*scale; dst[1]=v.y*scale; dst[2]=v.z*scale; dst[3]=v.w*scale;
    }

    float4 vv[4];
    {
        #pragma unroll
        for (int it = 0; it < 4; it++) {
            int idx = tid + 256*it;
            int r = idx >> 3, q = idx & 7;
            vv[it] = *(const float4*)&g_v[(size_t)(0 + r)*C + h*32 + 4*q];
            cp16(&KsB[r*36 + 4*q], &g_k[(size_t)(0 + r)*C + h*32 + 4*q]);
        }
        CP_COMMIT();
        #pragma unroll
        for (int it = 0; it < 4; it++) {
            int idx = tid + 256*it;
            int r = idx >> 3, q = idx & 7;
            VtB[(4*q+0)*136 + r] = __float2bfloat16(vv[it].x);
            VtB[(4*q+1)*136 + r] = __float2bfloat16(vv[it].y);
            VtB[(4*q+2)*136 + r] = __float2bfloat16(vv[it].z);
            VtB[(4*q+3)*136 + r] = __float2bfloat16(vv[it].w);
        }
        CP_WAIT(0);
        __syncthreads();
    }

    float m_run[2] = {-1e30f, -1e30f};
    float l_run[2] = {0.f, 0.f};
    float o[4][4];
    #pragma unroll
    for (int nt = 0; nt < 4; nt++)
        #pragma unroll
        for (int r = 0; r < 4; r++) o[nt][r] = 0.f;

    const __nv_bfloat16* bias_w = g_bias + ((size_t)blk*H + h)*(size_t)L*L
                                         + (size_t)(i0 + 16*warp)*L;
    const int arow = 16*warp + lr;

    for (int jt = 0; jt < 16; jt++) {
        const int cur = jt & 1, nxt = cur ^ 1;
        const float* Ks = KsB + cur*KSTG;
        const __nv_bfloat16* Vt = VtB + cur*VSTG;
        const bool more = (jt + 1 < 16);

        if (more) {
            int j0n = (jt + 1) * 128;
            float* ks = KsB + nxt*KSTG;
            #pragma unroll
            for (int it = 0; it < 4; it++) {
                int idx = tid + 256*it;
                int r = idx >> 3, q = idx & 7;
                vv[it] = *(const float4*)&g_v[(size_t)(j0n + r)*C + h*32 + 4*q];
                cp16(&ks[r*36 + 4*q], &g_k[(size_t)(j0n + r)*C + h*32 + 4*q]);
            }
            CP_COMMIT();
        }

        float s[16][4];
        #pragma unroll
        for (int nt = 0; nt < 16; nt++)
            #pragma unroll
            for (int r = 0; r < 4; r++) s[nt][r] = 0.f;
        #pragma unroll
        for (int kk = 0; kk < 32; kk += 8) {
            uint32_t a0 = __float_as_uint(Qs[(arow  )*36 + kk+lc]);
            uint32_t a1 = __float_as_uint(Qs[(arow+8)*36 + kk+lc]);
            uint32_t a2 = __float_as_uint(Qs[(arow  )*36 + kk+4+lc]);
            uint32_t a3 = __float_as_uint(Qs[(arow+8)*36 + kk+4+lc]);
            #pragma unroll
            for (int nt = 0; nt < 16; nt++) {
                uint32_t b0 = __float_as_uint(Ks[(8*nt+lr)*36 + kk+lc]);
                uint32_t b1 = __float_as_uint(Ks[(8*nt+lr)*36 + kk+4+lc]);
                mma_tf32(s[nt], a0, a1, a2, a3, b0, b1);
            }
        }
        const int j0 = jt * 128;
        #pragma unroll
        for (int nt = 0; nt < 16; nt++) {
            int j = j0 + 8*nt + 2*lc;
            __nv_bfloat162 blo = *(const __nv_bfloat162*)&bias_w[(size_t)lr*L + j];
            __nv_bfloat162 bhi = *(const __nv_bfloat162*)&bias_w[(size_t)(lr+8)*L + j];
            s[nt][0] += __bfloat162float(blo.x); s[nt][1] += __bfloat162float(blo.y);
            s[nt][2] += __bfloat162float(bhi.x); s[nt][3] += __bfloat162float(bhi.y);
        }

        float mx0 = -1e30f, mx1 = -1e30f;
        #pragma unroll
        for (int nt = 0; nt < 16; nt++) {
            mx0 = fmaxf(mx0, fmaxf(s[nt][0], s[nt][1]));
            mx1 = fmaxf(mx1, fmaxf(s[nt][2], s[nt][3]));
        }
        mx0 = fmaxf(mx0, __shfl_xor_sync(0xffffffffu, mx0, 1));
        mx0 = fmaxf(mx0, __shfl_xor_sync(0xffffffffu, mx0, 2));
        mx1 = fmaxf(mx1, __shfl_xor_sync(0xffffffffu, mx1, 1));
        mx1 = fmaxf(mx1, __shfl_xor_sync(0xffffffffu, mx1, 2));
        float mn0 = fmaxf(m_run[0], mx0), mn1 = fmaxf(m_run[1], mx1);
        float cf0 = __expf(m_run[0] - mn0), cf1 = __expf(m_run[1] - mn1);
        float rs0 = 0.f, rs1 = 0.f;
        #pragma unroll
        for (int nt = 0; nt < 16; nt++) {
            s[nt][0] = __expf(s[nt][0] - mn0);
            s[nt][1] = __expf(s[nt][1] - mn0);
            s[nt][2] = __expf(s[nt][2] - mn1);
            s[nt][3] = __expf(s[nt][3] - mn1);
            rs0 += s[nt][0] + s[nt][1];
            rs1 += s[nt][2] + s[nt][3];
        }
        rs0 += __shfl_xor_sync(0xffffffffu, rs0, 1);
        rs0 += __shfl_xor_sync(0xffffffffu, rs0, 2);
        rs1 += __shfl_xor_sync(0xffffffffu, rs1, 1);
        rs1 += __shfl_xor_sync(0xffffffffu, rs1, 2);
        l_run[0] = l_run[0]*cf0 + rs0;  m_run[0] = mn0;
        l_run[1] = l_run[1]*cf1 + rs1;  m_run[1] = mn1;
        #pragma unroll
        for (int nt = 0; nt < 4; nt++) {
            o[nt][0] *= cf0; o[nt][1] *= cf0;
            o[nt][2] *= cf1; o[nt][3] *= cf1;
        }

        #pragma unroll
        for (int c2 = 0; c2 < 8; c2++) {
            uint32_t a0 = pack_bf16x2(s[2*c2  ][0], s[2*c2  ][1]);
            uint32_t a1 = pack_bf16x2(s[2*c2  ][2], s[2*c2  ][3]);
            uint32_t a2 = pack_bf16x2(s[2*c2+1][0], s[2*c2+1][1]);
            uint32_t a3 = pack_bf16x2(s[2*c2+1][2], s[2*c2+1][3]);
            #pragma unroll
            for (int nt = 0; nt < 4; nt++) {
                uint32_t b0 = *(const uint32_t*)&Vt[(8*nt+lr)*136 + 16*c2 + 2*lc];
                uint32_t b1 = *(const uint32_t*)&Vt[(8*nt+lr)*136 + 16*c2 + 8 + 2*lc];
                mma_bf16(o[nt], a0, a1, a2, a3, b0, b1);
            }
        }

        if (more) {
            __nv_bfloat16* vt = VtB + nxt*VSTG;
            #pragma unroll
            for (int it = 0; it < 4; it++) {
                int idx = tid + 256*it;
                int r = idx >> 3, q = idx & 7;
                vt[(4*q+0)*136 + r] = __float2bfloat16(vv[it].x);
                vt[(4*q+1)*136 + r] = __float2bfloat16(vv[it].y);
                vt[(4*q+2)*136 + r] = __float2bfloat16(vv[it].z);
                vt[(4*q+3)*136 + r] = __float2bfloat16(vv[it].w);
            }
            CP_WAIT(0);
        }
        __syncthreads();
    }

    float inv0 = 1.0f / l_run[0], inv1 = 1.0f / l_run[1];
    #pragma unroll
    for (int nt = 0; nt < 4; nt++) {
        int d = h*32 + 8*nt + 2*lc;
        size_t r0 = (size_t)(i0 + arow) * C + d;
        size_t r1 = (size_t)(i0 + arow + 8) * C + d;
        *(float2*)&g_ao[r0] = make_float2(o[nt][0]*inv0, o[nt][1]*inv0);
        *(float2*)&g_ao[r1] = make_float2(o[nt][2]*inv1, o[nt][3]*inv1);
    }
}

// ---------------- final ----------------
__global__ void __launch_bounds__(256) k_final(const float* __restrict__ xn,
                                               const float* __restrict__ oW,
                                               const float* __restrict__ ob,
                                               float* __restrict__ out)
{
    const int warp = threadIdx.x >> 5, lane = threadIdx.x & 31;
    const int row = blockIdx.x * 8 + warp;
    const float* hr = g_h + (size_t)row * C;
    #pragma unroll
    for (int c = 0; c < 3; c++) {
        float s = 0.f;
        for (int k = lane; k < C; k += 32) s += hr[k] * oW[c*C + k];
        #pragma unroll
        for (int off = 16; off; off >>= 1) s += __shfl_xor_sync(0xffffffffu, s, off);
        if (lane == 0)
            out[row*3 + c] = g_scal[0] * xn[row*3 + c] + g_scal[1] * (s + ob[c]);
    }
}

// ---------------- launcher ----------------
extern "C" void kernel_launch(void* const* d_in, const int* in_sizes, int n_in,
                              void* d_out, int out_size)
{
    const float* x_noisy  = (const float*)d_in[0];
    const float* sigma    = (const float*)d_in[1];
    const float* single   = (const float*)d_in[2];
    const float* pair     = (const float*)d_in[3];
    const float* coord_W  = (const float*)d_in[4];
    const float* coord_b  = (const float*)d_in[5];
    const float* single_W = (const float*)d_in[6];
    const float* single_b = (const float*)d_in[7];
    const float* tmlp_W1  = (const float*)d_in[8];
    const float* tmlp_b1  = (const float*)d_in[9];
    const float* tmlp_W2  = (const float*)d_in[10];
    const float* tmlp_b2  = (const float*)d_in[11];
    const float* ada1_g   = (const float*)d_in[12];
    const float* ada1_b   = (const float*)d_in[13];
    const float* ada1_pW  = (const float*)d_in[14];
    const float* ada1_pb  = (const float*)d_in[15];
    const float* qW       = (const float*)d_in[16];
    const float* kW       = (const float*)d_in[17];
    const float* vW       = (const float*)d_in[18];
    const float* pairW    = (const float*)d_in[19];
    const float* outW     = (const float*)d_in[20];
    const float* outb     = (const float*)d_in[21];
    const float* ada2_g   = (const float*)d_in[22];
    const float* ada2_b   = (const float*)d_in[23];
    const float* ada2_pW  = (const float*)d_in[24];
    const float* ada2_pb  = (const float*)d_in[25];
    const float* ffn_W1   = (const float*)d_in[26];
    const float* ffn_b1   = (const float*)d_in[27];
    const float* ffn_W2   = (const float*)d_in[28];
    const float* ffn_b2   = (const float*)d_in[29];
    const float* out_W    = (const float*)d_in[30];
    const float* out_b    = (const float*)d_in[31];
    float* out = (float*)d_out;

    float *p_h, *p_q, *p_k, *p_v, *p_ao, *p_mid;
    cudaGetSymbolAddress((void**)&p_h,  g_h);
    cudaGetSymbolAddress((void**)&p_q,  g_q);
    cudaGetSymbolAddress((void**)&p_k,  g_k);
    cudaGetSymbolAddress((void**)&p_v,  g_v);
    cudaGetSymbolAddress((void**)&p_ao, g_ao);
    cudaGetSymbolAddress((void**)&p_mid, g_mid);

    static int attr_set = 0;
    if (!attr_set) {
        cudaFuncSetAttribute(k_attn_tc, cudaFuncAttributeMaxDynamicSharedMemorySize, ATTN_SMEM);
        cudaFuncSetAttribute(k_gemm_tc<true,false,true >, cudaFuncAttributeMaxDynamicSharedMemorySize, GEMM_SMEM);
        cudaFuncSetAttribute(k_single_tc, cudaFuncAttributeMaxDynamicSharedMemorySize, GEMM_SMEM);
        cudaFuncSetAttribute(k_qkv_f,  cudaFuncAttributeMaxDynamicSharedMemorySize, GEMM_SMEM);
        cudaFuncSetAttribute(k_ffn1_f, cudaFuncAttributeMaxDynamicSharedMemorySize, GEMM_SMEM);
        attr_set = 1;
    }

    k_bias_tc<<<(L*L)/128, 256>>>(pair, pairW);
    k_prep<<<1, 256>>>(sigma, tmlp_W1, tmlp_b1, tmlp_W2, tmlp_b2,
                       ada1_pW, ada1_pb, ada2_pW, ada2_pb,
                       ada1_g, ada1_b, ada2_g, ada2_b);
    k_foldW<<<NB*1792/8, 256>>>(qW, kW, vW, ffn_W1, ffn_b1);
    k_single_tc<<<dim3(C/64, L/64), 256, GEMM_SMEM>>>(single, single_W, single_b,
                                                      x_noisy, coord_W, coord_b, p_h);

    for (int b = 0; b < NB; b++) {
        k_qkv_f<<<dim3(C/64, L/64, 3), 256, GEMM_SMEM>>>(b, p_q, p_k, p_v);
        k_attn_tc<<<dim3(L/128, H), 256, ATTN_SMEM>>>(b);
        k_gemm_tc<true,false,true><<<dim3(C/64, L/64), 256, GEMM_SMEM>>>(
            p_ao, outW + (size_t)b*C*C, outb + b*C, p_h, p_h, L, C, C);
        k_ffn1_f<<<dim3(4*C/64, L/64), 256, GEMM_SMEM>>>(b, p_mid);
        k_gemm_tc<true,false,true><<<dim3(C/64, L/64), 256, GEMM_SMEM>>>(
            p_mid, ffn_W2 + (size_t)b*4*C*C, ffn_b2 + b*C, p_h, p_h, L, C, 4*C);
    }
    k_final<<<L/8, 256>>>(x_noisy, out_W, out_b, out);
}

// round 14
// speedup vs baseline: 1.3346x; 1.0001x over previous
#include <cuda_runtime.h>
#include <cuda_bf16.h>
#include <math.h>
#include <stdint.h>

#define L 2048
#define C 256
#define NB 4
#define H 8
#define D 32
#define SD 16.0f

// ---------------- scratch (device globals; no allocation allowed) ----------------
__device__ float g_h [L*C];
__device__ float g_q [L*C];
__device__ float g_k [L*C];
__device__ float g_v [L*C];
__device__ float g_ao[L*C];
__device__ float g_mid[L*4*C];
__device__ __nv_bfloat16 g_bias[(size_t)NB*H*L*L];   // 256 MB
__device__ float g_scal[4];   // c_skip, c_out, c_in
// fused-LN precomputes
__device__ float g_G1[NB][C], g_B1[NB][C], g_G2[NB][C], g_B2[NB][C];
__device__ float g_wqkv[(size_t)NB*3*C*C];   // G1-scaled qkv weights
__device__ float g_wf1 [(size_t)NB*4*C*C];   // G2-scaled ffn1 weights
__device__ float g_gwA [NB][3*C + 4*C];      // GW vectors (qkv | ffn1)
__device__ float g_b2A [NB][3*C + 4*C];      // b2 vectors (qkv | ffn1, ffn_b1 folded)

__device__ __forceinline__ float gelu_exact(float x) {
    return 0.5f * x * (1.0f + erff(x * 0.70710678118654752f));
}

__device__ __forceinline__ void mma_tf32(float c[4],
    uint32_t a0, uint32_t a1, uint32_t a2, uint32_t a3,
    uint32_t b0, uint32_t b1)
{
    asm volatile(
        "mma.sync.aligned.m16n8k8.row.col.f32.tf32.tf32.f32 "
        "{%0,%1,%2,%3}, {%4,%5,%6,%7}, {%8,%9}, {%0,%1,%2,%3};"
        : "+f"(c[0]), "+f"(c[1]), "+f"(c[2]), "+f"(c[3])
        : "r"(a0), "r"(a1), "r"(a2), "r"(a3), "r"(b0), "r"(b1));
}

__device__ __forceinline__ void mma_bf16(float c[4],
    uint32_t a0, uint32_t a1, uint32_t a2, uint32_t a3,
    uint32_t b0, uint32_t b1)
{
    asm volatile(
        "mma.sync.aligned.m16n8k16.row.col.f32.bf16.bf16.f32 "
        "{%0,%1,%2,%3}, {%4,%5,%6,%7}, {%8,%9}, {%0,%1,%2,%3};"
        : "+f"(c[0]), "+f"(c[1]), "+f"(c[2]), "+f"(c[3])
        : "r"(a0), "r"(a1), "r"(a2), "r"(a3), "r"(b0), "r"(b1));
}

__device__ __forceinline__ uint32_t pack_bf16x2(float lo, float hi) {
    __nv_bfloat162 t = __floats2bfloat162_rn(lo, hi);
    return *(uint32_t*)&t;
}

__device__ __forceinline__ void cp16(float* smem_dst, const float* gsrc) {
    uint32_t s = (uint32_t)__cvta_generic_to_shared(smem_dst);
    asm volatile("cp.async.cg.shared.global [%0], [%1], 16;" :: "r"(s), "l"(gsrc));
}
#define CP_COMMIT() asm volatile("cp.async.commit_group;")
#define CP_WAIT(n)  asm volatile("cp.async.wait_group %0;" :: "n"(n))

// ---------------- K0: time embedding, time MLP, adaLN cond proj, fold1 ----------------
__global__ void __launch_bounds__(256) k_prep(
    const float* __restrict__ sigma,
    const float* __restrict__ tW1, const float* __restrict__ tb1,
    const float* __restrict__ tW2, const float* __restrict__ tb2,
    const float* __restrict__ a1pW, const float* __restrict__ a1pb,
    const float* __restrict__ a2pW, const float* __restrict__ a2pb,
    const float* __restrict__ a1g, const float* __restrict__ a1b,
    const float* __restrict__ a2g, const float* __restrict__ a2b)
{
    __shared__ float temb[C];
    __shared__ float hid[4*C];
    __shared__ float tcs[C];
    __shared__ float ss1[NB][2*C];
    __shared__ float ss2[NB][2*C];
    const int t = threadIdx.x;
    const float sg = sigma[0];
    if (t == 0) {
        float s2 = sg*sg + SD*SD;
        g_scal[0] = SD*SD / s2;
        g_scal[1] = sg*SD*rsqrtf(s2);
        g_scal[2] = rsqrtf(s2);
    }
    const float c_noise = 0.25f * logf(sg + 1e-8f);
    if (t < 128) {
        float fr = expf(-logf(10000.0f) * (float)t / 128.0f);
        float a = c_noise * fr;
        temb[t]       = cosf(a);
        temb[t + 128] = sinf(a);
    }
    __syncthreads();
    for (int r = t; r < 4*C; r += 256) {
        float acc = tb1[r];
        const float* w = tW1 + (size_t)r * C;
        for (int k2 = 0; k2 < C; k2++) acc += temb[k2] * w[k2];
        hid[r] = gelu_exact(acc);
    }
    __syncthreads();
    for (int r = t; r < C; r += 256) {
        float acc = tb2[r];
        const float* w = tW2 + (size_t)r * 4*C;
        for (int k2 = 0; k2 < 4*C; k2++) acc += hid[k2] * w[k2];
        tcs[r] = acc;
    }
    __syncthreads();
    for (int idx = t; idx < NB*2*C; idx += 256) {
        int b = idx / (2*C), r = idx % (2*C);
        float acc1 = a1pb[b*2*C + r];
        const float* w1 = a1pW + ((size_t)b*2*C + r) * C;
        float acc2 = a2pb[b*2*C + r];
        const float* w2 = a2pW + ((size_t)b*2*C + r) * C;
        for (int k2 = 0; k2 < C; k2++) { acc1 += tcs[k2]*w1[k2]; acc2 += tcs[k2]*w2[k2]; }
        ss1[b][r] = acc1;
        ss2[b][r] = acc2;
    }
    __syncthreads();
    for (int idx = t; idx < NB*C; idx += 256) {
        int b = idx >> 8, c = idx & 255;
        float s1 = 1.0f + ss1[b][c];
        g_G1[b][c] = a1g[b*C + c] * s1;
        g_B1[b][c] = a1b[b*C + c] * s1 + ss1[b][C + c];
        float s2 = 1.0f + ss2[b][c];
        g_G2[b][c] = a2g[b*C + c] * s2;
        g_B2[b][c] = a2b[b*C + c] * s2 + ss2[b][C + c];
    }
}

// ---------------- foldW ----------------
__global__ void __launch_bounds__(256) k_foldW(
    const float* __restrict__ qW, const float* __restrict__ kW,
    const float* __restrict__ vW, const float* __restrict__ f1W,
    const float* __restrict__ f1b)
{
    const int lane = threadIdx.x & 31, warp = threadIdx.x >> 5;
    int gidx = blockIdx.x * 8 + warp;
    int b = gidx / 1792, n = gidx % 1792;
    const float *src, *G, *Bc;
    float* dst;
    float extra = 0.f;
    if (n < 768) {
        int w = n >> 8, nn = n & 255;
        src = (w == 0 ? qW : w == 1 ? kW : vW) + ((size_t)b*C + nn)*C;
        dst = g_wqkv + ((size_t)b*768 + n)*C;
        G = g_G1[b]; Bc = g_B1[b];
    } else {
        int nn = n - 768;
        src = f1W + ((size_t)b*4*C + nn)*C;
        dst = g_wf1 + ((size_t)b*1024 + nn)*C;
        G = g_G2[b]; Bc = g_B2[b];
        extra = f1b[b*4*C + nn];
    }
    float gw = 0.f, b2 = 0.f;
    for (int c = lane; c < C; c += 32) {
        float w = src[c];
        float wg = w * G[c];
        dst[c] = wg;
        gw += wg;
        b2 += w * Bc[c];
    }
    #pragma unroll
    for (int off = 16; off; off >>= 1) {
        gw += __shfl_xor_sync(0xffffffffu, gw, off);
        b2 += __shfl_xor_sync(0xffffffffu, b2, off);
    }
    if (lane == 0) { g_gwA[b][n] = gw; g_b2A[b][n] = b2 + extra; }
}

// ---------------- pair bias via tf32 mma ----------------
__global__ void __launch_bounds__(256) k_bias_tc(const float* __restrict__ pair,
                                                 const float* __restrict__ pW)
{
    __shared__ float As[128][68];
    __shared__ float Ws[32][68];
    const int tid = threadIdx.x, lane = tid & 31, warp = tid >> 5;
    const int lr = lane >> 2, lc = lane & 3;
    const size_t row0 = (size_t)blockIdx.x * 128;

    #pragma unroll
    for (int it = 0; it < 8; it++) {
        int idx = tid + 256*it;
        int r = idx >> 4, q = idx & 15;
        *(float4*)&As[r][4*q] = *(const float4*)&pair[(row0 + r) * 64 + 4*q];
    }
    #pragma unroll
    for (int it = 0; it < 2; it++) {
        int idx = tid + 256*it;
        int r = idx >> 4, q = idx & 15;
        *(float4*)&Ws[r][4*q] = *(const float4*)&pW[r * 64 + 4*q];
    }
    __syncthreads();

    float c[4][4] = {};
    const int arow = 16*warp + lr;
    #pragma unroll
    for (int kk = 0; kk < 64; kk += 8) {
        uint32_t a0 = __float_as_uint(As[arow  ][kk+lc]);
        uint32_t a1 = __float_as_uint(As[arow+8][kk+lc]);
        uint32_t a2 = __float_as_uint(As[arow  ][kk+4+lc]);
        uint32_t a3 = __float_as_uint(As[arow+8][kk+4+lc]);
        #pragma unroll
        for (int nt = 0; nt < 4; nt++) {
            uint32_t b0 = __float_as_uint(Ws[8*nt+lr][kk+lc]);
            uint32_t b1 = __float_as_uint(Ws[8*nt+lr][kk+4+lc]);
            mma_tf32(c[nt], a0, a1, a2, a3, b0, b1);
        }
    }
    __syncthreads();

    __nv_bfloat16* stage = (__nv_bfloat16*)&As[0][0];
    const int SP = 132;
    #pragma unroll
    for (int nt = 0; nt < 4; nt++) {
        #pragma unroll
        for (int half = 0; half < 2; half++) {
            int rloc = 16*warp + lr + 8*half;
            int col = 8*nt + 2*lc;
            stage[(col  )*SP + rloc] = __float2bfloat16(c[nt][2*half+0]);
            stage[(col+1)*SP + rloc] = __float2bfloat16(c[nt][2*half+1]);
        }
    }
    __syncthreads();
    for (int idx = tid; idx < 32*64; idx += 256) {
        int o = idx >> 6, r2 = (idx & 63) * 2;
        __nv_bfloat162 v = *(const __nv_bfloat162*)&stage[o*SP + r2];
        *(__nv_bfloat162*)&g_bias[(size_t)o * (size_t)L * (size_t)L + row0 + r2] = v;
    }
}

// ---------------- tf32 GEMM, 64x64 tile, cp.async double-buffered ----------------
// 8 warps = 2(M) x 4(N); warp tile 32x16. Optional in-kernel row-LN stats.
#define G_STAGE (64*36)
#define GEMM_SMEM (4*G_STAGE*4)   // 36864

template<bool HAS_BIAS, bool DO_GELU, bool HAS_RES, bool LN_EPI, bool COORD>
__device__ __forceinline__ void gemm_body64(
    const float* __restrict__ A, const float* __restrict__ Bw,
    const float* __restrict__ bias, const float* __restrict__ Rsrc,
    const float* __restrict__ GW, const float* __restrict__ b2v,
    const float* __restrict__ xn, const float* __restrict__ cW,
    const float* __restrict__ cb,
    float* __restrict__ Cout, int M, int N, int K)
{
    extern __shared__ float sm[];
    float* AsB = sm;                    // [2][64][36]
    float* BsB = sm + 2*G_STAGE;        // [2][64][36]
    const int tid = threadIdx.x, lane = tid & 31, warp = tid >> 5;
    const int wm = warp >> 2, wn = warp & 3;
    const int m0 = blockIdx.y * 64, n0 = blockIdx.x * 64;
    const int lr = lane >> 2, lc = lane & 3;
    const int pr = tid >> 3, pq = tid & 7;

    float c[2][2][4];
    #pragma unroll
    for (int mt = 0; mt < 2; mt++)
        #pragma unroll
        for (int nt = 0; nt < 2; nt++)
            #pragma unroll
            for (int r = 0; r < 4; r++) c[mt][nt][r] = 0.f;

    // row-stat accumulators (4 threads per row: row = tid>>2, seg = tid&3)
    float stat_s = 0.f, stat_q = 0.f;
    const int srow = tid >> 2, sseg = tid & 3;

    const int NK = K >> 5;
    {
        #pragma unroll
        for (int it = 0; it < 2; it++) {
            int r = pr + 32*it;
            cp16(&AsB[r*36 + 4*pq], &A [(size_t)(m0 + r)*K + 4*pq]);
            cp16(&BsB[r*36 + 4*pq], &Bw[(size_t)(n0 + r)*K + 4*pq]);
        }
        CP_COMMIT();
    }

    for (int ks = 0; ks < NK; ks++) {
        if (ks + 1 < NK) {
            float* as = AsB + ((ks+1)&1)*G_STAGE;
            float* bs = BsB + ((ks+1)&1)*G_STAGE;
            int k0 = (ks+1) << 5;
            #pragma unroll
            for (int it = 0; it < 2; it++) {
                int r = pr + 32*it;
                cp16(&as[r*36 + 4*pq], &A [(size_t)(m0 + r)*K + k0 + 4*pq]);
                cp16(&bs[r*36 + 4*pq], &Bw[(size_t)(n0 + r)*K + k0 + 4*pq]);
            }
            CP_COMMIT();
            CP_WAIT(1);
        } else {
            CP_WAIT(0);
        }
        __syncthreads();
        const float* as = AsB + (ks&1)*G_STAGE;
        const float* bs = BsB + (ks&1)*G_STAGE;

        if (LN_EPI) {   // accumulate row sums on the idle FMA pipe
            const float* ap = as + srow*36 + sseg*8;
            #pragma unroll
            for (int u = 0; u < 8; u++) { float v = ap[u]; stat_s += v; stat_q += v*v; }
        }

        #pragma unroll
        for (int kk = 0; kk < 32; kk += 8) {
            uint32_t a[2][4], b[2][2];
            #pragma unroll
            for (int mt = 0; mt < 2; mt++) {
                int row = 32*wm + 16*mt + lr;
                a[mt][0] = __float_as_uint(as[(row  )*36 + kk+lc]);
                a[mt][1] = __float_as_uint(as[(row+8)*36 + kk+lc]);
                a[mt][2] = __float_as_uint(as[(row  )*36 + kk+4+lc]);
                a[mt][3] = __float_as_uint(as[(row+8)*36 + kk+4+lc]);
            }
            #pragma unroll
            for (int nt = 0; nt < 2; nt++) {
                int col = 16*wn + 8*nt + lr;
                b[nt][0] = __float_as_uint(bs[col*36 + kk+lc]);
                b[nt][1] = __float_as_uint(bs[col*36 + kk+4+lc]);
            }
            #pragma unroll
            for (int mt = 0; mt < 2; mt++)
                #pragma unroll
                for (int nt = 0; nt < 2; nt++)
                    mma_tf32(c[mt][nt], a[mt][0], a[mt][1], a[mt][2], a[mt][3],
                             b[nt][0], b[nt][1]);
        }
        __syncthreads();
    }

    float* rs_s = sm;        // alias A smem (free after mainloop)
    float* m2_s = sm + 64;
    if (LN_EPI) {
        stat_s += __shfl_xor_sync(0xffffffffu, stat_s, 1);
        stat_s += __shfl_xor_sync(0xffffffffu, stat_s, 2);
        stat_q += __shfl_xor_sync(0xffffffffu, stat_q, 1);
        stat_q += __shfl_xor_sync(0xffffffffu, stat_q, 2);
        if (sseg == 0) {
            float mu = stat_s * (1.0f/256.0f);
            float var = stat_q * (1.0f/256.0f) - mu*mu;
            float rsv = rsqrtf(var + 1e-5f);
            rs_s[srow] = rsv;
            m2_s[srow] = -mu * rsv;
        }
        __syncthreads();
    }

    #pragma unroll
    for (int mt = 0; mt < 2; mt++) {
        #pragma unroll
        for (int half = 0; half < 2; half++) {
            int rloc = 32*wm + 16*mt + lr + 8*half;
            int row = m0 + rloc;
            float rs = 0.f, m2 = 0.f, cx0 = 0.f, cx1 = 0.f, cx2 = 0.f;
            if (LN_EPI) { rs = rs_s[rloc]; m2 = m2_s[rloc]; }
            if (COORD) {
                float cin = g_scal[2];
                cx0 = xn[row*3+0]*cin; cx1 = xn[row*3+1]*cin; cx2 = xn[row*3+2]*cin;
            }
            #pragma unroll
            for (int nt = 0; nt < 2; nt++) {
                int col = n0 + 16*wn + 8*nt + 2*lc;
                float v0 = c[mt][nt][2*half+0];
                float v1 = c[mt][nt][2*half+1];
                if (LN_EPI) {
                    v0 = rs*v0 + m2*GW[col]   + b2v[col];
                    v1 = rs*v1 + m2*GW[col+1] + b2v[col+1];
                }
                if (HAS_BIAS) { v0 += bias[col]; v1 += bias[col+1]; }
                if (COORD) {
                    v0 += cb[col]   + cx0*cW[col*3+0]     + cx1*cW[col*3+1]     + cx2*cW[col*3+2];
                    v1 += cb[col+1] + cx0*cW[(col+1)*3+0] + cx1*cW[(col+1)*3+1] + cx2*cW[(col+1)*3+2];
                }
                if (DO_GELU)  { v0 = gelu_exact(v0); v1 = gelu_exact(v1); }
                if (HAS_RES)  { v0 += Rsrc[(size_t)row*N + col]; v1 += Rsrc[(size_t)row*N + col + 1]; }
                *(float2*)&Cout[(size_t)row*N + col] = make_float2(v0, v1);
            }
        }
    }
}

template<bool HB, bool HG, bool HR>
__global__ void __launch_bounds__(256, 2) k_gemm_tc(
    const float* __restrict__ A, const float* __restrict__ Bw,
    const float* __restrict__ bias, const float* __restrict__ Rsrc,
    float* __restrict__ Cout, int M, int N, int K)
{
    gemm_body64<HB,HG,HR,false,false>(A, Bw, bias, Rsrc,
        nullptr, nullptr, nullptr, nullptr, nullptr, Cout, M, N, K);
}

__global__ void __launch_bounds__(256, 2) k_single_tc(
    const float* __restrict__ A, const float* __restrict__ Bw,
    const float* __restrict__ bias,
    const float* __restrict__ xn, const float* __restrict__ cW,
    const float* __restrict__ cb, float* __restrict__ Cout)
{
    gemm_body64<true,false,false,false,true>(A, Bw, bias, nullptr,
        nullptr, nullptr, xn, cW, cb, Cout, L, C, C);
}

__global__ void __launch_bounds__(256, 2) k_qkv_f(
    int b, float* __restrict__ q, float* __restrict__ k, float* __restrict__ v)
{
    int z = blockIdx.z;
    const float* Bw = g_wqkv + ((size_t)b*768 + z*256)*C;
    const float* GW = &g_gwA[b][z*256];
    const float* b2 = &g_b2A[b][z*256];
    float* Cout = (z == 0) ? q : (z == 1) ? k : v;
    gemm_body64<false,false,false,true,false>(g_h, Bw, nullptr, nullptr,
        GW, b2, nullptr, nullptr, nullptr, Cout, L, C, C);
}

__global__ void __launch_bounds__(256, 2) k_ffn1_f(int b, float* __restrict__ mid)
{
    const float* Bw = g_wf1 + (size_t)b*1024*C;
    const float* GW = &g_gwA[b][768];
    const float* b2 = &g_b2A[b][768];
    gemm_body64<false,true,false,true,false>(g_h, Bw, nullptr, nullptr,
        GW, b2, nullptr, nullptr, nullptr, mid, L, 4*C, C);
}

// ---------------- tensor-core flash attention ----------------
// tf32 QK^T (cp.async double-buffered K), bf16 PV with P fed straight from
// softmax registers, V register-prefetch.
#define KSTG (128*36)
#define VSTG (32*136)
#define ATTN_SMEM (18432 + 2*18432 + 2*8704)   // Qs + Ks[2] + Vt[2] = 72704
__global__ void __launch_bounds__(256) k_attn_tc(int blk)
{
    extern __shared__ char smc[];
    float* Qs = (float*)smc;                                  // [128][36]
    float* KsB = (float*)(smc + 18432);                       // [2][128][36]
    __nv_bfloat16* VtB = (__nv_bfloat16*)(smc + 18432 + 2*18432); // [2][32][136]

    const int h  = blockIdx.y;
    const int i0 = blockIdx.x * 128;
    const int tid = threadIdx.x, lane = tid & 31, warp = tid >> 5;
    const int lr = lane >> 2, lc = lane & 3;
    const float scale = 0.17677669529663687f;

    #pragma unroll
    for (int it = 0; it < 4; it++) {
        int idx = tid + 256*it;
        int r = idx >> 3, q = idx & 7;
        float4 v = *(const float4*)&g_q[(size_t)(i0 + r)*C + h*32 + 4*q];
        float* dst = &Qs[r*36 + 4*q];
        dst[0]=v.x*scale; dst[1]=v.y*scale; dst[2]=v.z*scale; dst[3]=v.w*scale;
    }

    float4 vv[4];
    {
        #pragma unroll
        for (int it = 0; it < 4; it++) {
            int idx = tid + 256*it;
            int r = idx >> 3, q = idx & 7;
            vv[it] = *(const float4*)&g_v[(size_t)(0 + r)*C + h*32 + 4*q];
            cp16(&KsB[r*36 + 4*q], &g_k[(size_t)(0 + r)*C + h*32 + 4*q]);
        }
        CP_COMMIT();
        #pragma unroll
        for (int it = 0; it < 4; it++) {
            int idx = tid + 256*it;
            int r = idx >> 3, q = idx & 7;
            VtB[(4*q+0)*136 + r] = __float2bfloat16(vv[it].x);
            VtB[(4*q+1)*136 + r] = __float2bfloat16(vv[it].y);
            VtB[(4*q+2)*136 + r] = __float2bfloat16(vv[it].z);
            VtB[(4*q+3)*136 + r] = __float2bfloat16(vv[it].w);
        }
        CP_WAIT(0);
        __syncthreads();
    }

    float m_run[2] = {-1e30f, -1e30f};
    float l_run[2] = {0.f, 0.f};
    float o[4][4];
    #pragma unroll
    for (int nt = 0; nt < 4; nt++)
        #pragma unroll
        for (int r = 0; r < 4; r++) o[nt][r] = 0.f;

    const __nv_bfloat16* bias_w = g_bias + ((size_t)blk*H + h)*(size_t)L*L
                                         + (size_t)(i0 + 16*warp)*L;
    const int arow = 16*warp + lr;

    for (int jt = 0; jt < 16; jt++) {
        const int cur = jt & 1, nxt = cur ^ 1;
        const float* Ks = KsB + cur*KSTG;
        const __nv_bfloat16* Vt = VtB + cur*VSTG;
        const bool more = (jt + 1 < 16);

        if (more) {
            int j0n = (jt + 1) * 128;
            float* ks = KsB + nxt*KSTG;
            #pragma unroll
            for (int it = 0; it < 4; it++) {
                int idx = tid + 256*it;
                int r = idx >> 3, q = idx & 7;
                vv[it] = *(const float4*)&g_v[(size_t)(j0n + r)*C + h*32 + 4*q];
                cp16(&ks[r*36 + 4*q], &g_k[(size_t)(j0n + r)*C + h*32 + 4*q]);
            }
            CP_COMMIT();
        }

        float s[16][4];
        #pragma unroll
        for (int nt = 0; nt < 16; nt++)
            #pragma unroll
            for (int r = 0; r < 4; r++) s[nt][r] = 0.f;
        #pragma unroll
        for (int kk = 0; kk < 32; kk += 8) {
            uint32_t a0 = __float_as_uint(Qs[(arow  )*36 + kk+lc]);
            uint32_t a1 = __float_as_uint(Qs[(arow+8)*36 + kk+lc]);
            uint32_t a2 = __float_as_uint(Qs[(arow  )*36 + kk+4+lc]);
            uint32_t a3 = __float_as_uint(Qs[(arow+8)*36 + kk+4+lc]);
            #pragma unroll
            for (int nt = 0; nt < 16; nt++) {
                uint32_t b0 = __float_as_uint(Ks[(8*nt+lr)*36 + kk+lc]);
                uint32_t b1 = __float_as_uint(Ks[(8*nt+lr)*36 + kk+4+lc]);
                mma_tf32(s[nt], a0, a1, a2, a3, b0, b1);
            }
        }
        const int j0 = jt * 128;
        #pragma unroll
        for (int nt = 0; nt < 16; nt++) {
            int j = j0 + 8*nt + 2*lc;
            __nv_bfloat162 blo = *(const __nv_bfloat162*)&bias_w[(size_t)lr*L + j];
            __nv_bfloat162 bhi = *(const __nv_bfloat162*)&bias_w[(size_t)(lr+8)*L + j];
            s[nt][0] += __bfloat162float(blo.x); s[nt][1] += __bfloat162float(blo.y);
            s[nt][2] += __bfloat162float(bhi.x); s[nt][3] += __bfloat162float(bhi.y);
        }

        float mx0 = -1e30f, mx1 = -1e30f;
        #pragma unroll
        for (int nt = 0; nt < 16; nt++) {
            mx0 = fmaxf(mx0, fmaxf(s[nt][0], s[nt][1]));
            mx1 = fmaxf(mx1, fmaxf(s[nt][2], s[nt][3]));
        }
        mx0 = fmaxf(mx0, __shfl_xor_sync(0xffffffffu, mx0, 1));
        mx0 = fmaxf(mx0, __shfl_xor_sync(0xffffffffu, mx0, 2));
        mx1 = fmaxf(mx1, __shfl_xor_sync(0xffffffffu, mx1, 1));
        mx1 = fmaxf(mx1, __shfl_xor_sync(0xffffffffu, mx1, 2));
        float mn0 = fmaxf(m_run[0], mx0), mn1 = fmaxf(m_run[1], mx1);
        float cf0 = __expf(m_run[0] - mn0), cf1 = __expf(m_run[1] - mn1);
        float rs0 = 0.f, rs1 = 0.f;
        #pragma unroll
        for (int nt = 0; nt < 16; nt++) {
            s[nt][0] = __expf(s[nt][0] - mn0);
            s[nt][1] = __expf(s[nt][1] - mn0);
            s[nt][2] = __expf(s[nt][2] - mn1);
            s[nt][3] = __expf(s[nt][3] - mn1);
            rs0 += s[nt][0] + s[nt][1];
            rs1 += s[nt][2] + s[nt][3];
        }
        rs0 += __shfl_xor_sync(0xffffffffu, rs0, 1);
        rs0 += __shfl_xor_sync(0xffffffffu, rs0, 2);
        rs1 += __shfl_xor_sync(0xffffffffu, rs1, 1);
        rs1 += __shfl_xor_sync(0xffffffffu, rs1, 2);
        l_run[0] = l_run[0]*cf0 + rs0;  m_run[0] = mn0;
        l_run[1] = l_run[1]*cf1 + rs1;  m_run[1] = mn1;
        #pragma unroll
        for (int nt = 0; nt < 4; nt++) {
            o[nt][0] *= cf0; o[nt][1] *= cf0;
            o[nt][2] *= cf1; o[nt][3] *= cf1;
        }

        #pragma unroll
        for (int c2 = 0; c2 < 8; c2++) {
            uint32_t a0 = pack_bf16x2(s[2*c2  ][0], s[2*c2  ][1]);
            uint32_t a1 = pack_bf16x2(s[2*c2  ][2], s[2*c2  ][3]);
            uint32_t a2 = pack_bf16x2(s[2*c2+1][0], s[2*c2+1][1]);
            uint32_t a3 = pack_bf16x2(s[2*c2+1][2], s[2*c2+1][3]);
            #pragma unroll
            for (int nt = 0; nt < 4; nt++) {
                uint32_t b0 = *(const uint32_t*)&Vt[(8*nt+lr)*136 + 16*c2 + 2*lc];
                uint32_t b1 = *(const uint32_t*)&Vt[(8*nt+lr)*136 + 16*c2 + 8 + 2*lc];
                mma_bf16(o[nt], a0, a1, a2, a3, b0, b1);
            }
        }

        if (more) {
            __nv_bfloat16* vt = VtB + nxt*VSTG;
            #pragma unroll
            for (int it = 0; it < 4; it++) {
                int idx = tid + 256*it;
                int r = idx >> 3, q = idx & 7;
                vt[(4*q+0)*136 + r] = __float2bfloat16(vv[it].x);
                vt[(4*q+1)*136 + r] = __float2bfloat16(vv[it].y);
                vt[(4*q+2)*136 + r] = __float2bfloat16(vv[it].z);
                vt[(4*q+3)*136 + r] = __float2bfloat16(vv[it].w);
            }
            CP_WAIT(0);
        }
        __syncthreads();
    }

    float inv0 = 1.0f / l_run[0], inv1 = 1.0f / l_run[1];
    #pragma unroll
    for (int nt = 0; nt < 4; nt++) {
        int d = h*32 + 8*nt + 2*lc;
        size_t r0 = (size_t)(i0 + arow) * C + d;
        size_t r1 = (size_t)(i0 + arow + 8) * C + d;
        *(float2*)&g_ao[r0] = make_float2(o[nt][0]*inv0, o[nt][1]*inv0);
        *(float2*)&g_ao[r1] = make_float2(o[nt][2]*inv1, o[nt][3]*inv1);
    }
}

// ---------------- final ----------------
__global__ void __launch_bounds__(256) k_final(const float* __restrict__ xn,
                                               const float* __restrict__ oW,
                                               const float* __restrict__ ob,
                                               float* __restrict__ out)
{
    const int warp = threadIdx.x >> 5, lane = threadIdx.x & 31;
    const int row = blockIdx.x * 8 + warp;
    const float* hr = g_h + (size_t)row * C;
    #pragma unroll
    for (int c = 0; c < 3; c++) {
        float s = 0.f;
        for (int k = lane; k < C; k += 32) s += hr[k] * oW[c*C + k];
        #pragma unroll
        for (int off = 16; off; off >>= 1) s += __shfl_xor_sync(0xffffffffu, s, off);
        if (lane == 0)
            out[row*3 + c] = g_scal[0] * xn[row*3 + c] + g_scal[1] * (s + ob[c]);
    }
}

// ---------------- launcher ----------------
extern "C" void kernel_launch(void* const* d_in, const int* in_sizes, int n_in,
                              void* d_out, int out_size)
{
    const float* x_noisy  = (const float*)d_in[0];
    const float* sigma    = (const float*)d_in[1];
    const float* single   = (const float*)d_in[2];
    const float* pair     = (const float*)d_in[3];
    const float* coord_W  = (const float*)d_in[4];
    const float* coord_b  = (const float*)d_in[5];
    const float* single_W = (const float*)d_in[6];
    const float* single_b = (const float*)d_in[7];
    const float* tmlp_W1  = (const float*)d_in[8];
    const float* tmlp_b1  = (const float*)d_in[9];
    const float* tmlp_W2  = (const float*)d_in[10];
    const float* tmlp_b2  = (const float*)d_in[11];
    const float* ada1_g   = (const float*)d_in[12];
    const float* ada1_b   = (const float*)d_in[13];
    const float* ada1_pW  = (const float*)d_in[14];
    const float* ada1_pb  = (const float*)d_in[15];
    const float* qW       = (const float*)d_in[16];
    const float* kW       = (const float*)d_in[17];
    const float* vW       = (const float*)d_in[18];
    const float* pairW    = (const float*)d_in[19];
    const float* outW     = (const float*)d_in[20];
    const float* outb     = (const float*)d_in[21];
    const float* ada2_g   = (const float*)d_in[22];
    const float* ada2_b   = (const float*)d_in[23];
    const float* ada2_pW  = (const float*)d_in[24];
    const float* ada2_pb  = (const float*)d_in[25];
    const float* ffn_W1   = (const float*)d_in[26];
    const float* ffn_b1   = (const float*)d_in[27];
    const float* ffn_W2   = (const float*)d_in[28];
    const float* ffn_b2   = (const float*)d_in[29];
    const float* out_W    = (const float*)d_in[30];
    const float* out_b    = (const float*)d_in[31];
    float* out = (float*)d_out;

    float *p_h, *p_q, *p_k, *p_v, *p_ao, *p_mid;
    cudaGetSymbolAddress((void**)&p_h,  g_h);
    cudaGetSymbolAddress((void**)&p_q,  g_q);
    cudaGetSymbolAddress((void**)&p_k,  g_k);
    cudaGetSymbolAddress((void**)&p_v,  g_v);
    cudaGetSymbolAddress((void**)&p_ao, g_ao);
    cudaGetSymbolAddress((void**)&p_mid, g_mid);

    static int attr_set = 0;
    if (!attr_set) {
        cudaFuncSetAttribute(k_attn_tc, cudaFuncAttributeMaxDynamicSharedMemorySize, ATTN_SMEM);
        cudaFuncSetAttribute(k_gemm_tc<true,false,true >, cudaFuncAttributeMaxDynamicSharedMemorySize, GEMM_SMEM);
        cudaFuncSetAttribute(k_single_tc, cudaFuncAttributeMaxDynamicSharedMemorySize, GEMM_SMEM);
        cudaFuncSetAttribute(k_qkv_f,  cudaFuncAttributeMaxDynamicSharedMemorySize, GEMM_SMEM);
        cudaFuncSetAttribute(k_ffn1_f, cudaFuncAttributeMaxDynamicSharedMemorySize, GEMM_SMEM);
        attr_set = 1;
    }

    k_bias_tc<<<(L*L)/128, 256>>>(pair, pairW);
    k_prep<<<1, 256>>>(sigma, tmlp_W1, tmlp_b1, tmlp_W2, tmlp_b2,
                       ada1_pW, ada1_pb, ada2_pW, ada2_pb,
                       ada1_g, ada1_b, ada2_g, ada2_b);
    k_foldW<<<NB*1792/8, 256>>>(qW, kW, vW, ffn_W1, ffn_b1);
    k_single_tc<<<dim3(C/64, L/64), 256, GEMM_SMEM>>>(single, single_W, single_b,
                                                      x_noisy, coord_W, coord_b, p_h);

    for (int b = 0; b < NB; b++) {
        k_qkv_f<<<dim3(C/64, L/64, 3), 256, GEMM_SMEM>>>(b, p_q, p_k, p_v);
        k_attn_tc<<<dim3(L/128, H), 256, ATTN_SMEM>>>(b);
        k_gemm_tc<true,false,true><<<dim3(C/64, L/64), 256, GEMM_SMEM>>>(
            p_ao, outW + (size_t)b*C*C, outb + b*C, p_h, p_h, L, C, C);
        k_ffn1_f<<<dim3(4*C/64, L/64), 256, GEMM_SMEM>>>(b, p_mid);
        k_gemm_tc<true,false,true><<<dim3(C/64, L/64), 256, GEMM_SMEM>>>(
            p_mid, ffn_W2 + (size_t)b*4*C*C, ffn_b2 + b*C, p_h, p_h, L, C, 4*C);
    }
    k_final<<<L/8, 256>>>(x_noisy, out_W, out_b, out);
}